// round 10
// baseline (speedup 1.0000x reference)
#include <cuda_runtime.h>
#include <cstdint>

#define T_SEQ 256
#define NH 8
#define DHD 64
#define DMODEL 512
#define NPROJ 2560   // 5 * 512

// ---------------- packed fp32x2 helpers (Blackwell FFMA2) ----------------
__device__ __forceinline__ unsigned long long splat2(float x) {
    unsigned long long r;
    asm("mov.b64 %0, {%1, %1};" : "=l"(r) : "f"(x));
    return r;
}
__device__ __forceinline__ unsigned long long fma2(unsigned long long a, unsigned long long b,
                                                   unsigned long long c) {
    unsigned long long d;
    asm("fma.rn.f32x2 %0, %1, %2, %3;" : "=l"(d) : "l"(a), "l"(b), "l"(c));
    return d;
}
__device__ __forceinline__ float2 unpack2(unsigned long long v) {
    float2 f;
    asm("mov.b64 {%0, %1}, %2;" : "=f"(f.x), "=f"(f.y) : "l"(v));
    return f;
}

// ---------------- tf32 helpers ----------------
__device__ __forceinline__ uint32_t f2tf(float x) {
    uint32_t u;
    asm("cvt.rna.tf32.f32 %0, %1;" : "=r"(u) : "f"(x));
    return u;
}
__device__ __forceinline__ float f2tf_f(float x) { return __uint_as_float(f2tf(x)); }

__device__ __forceinline__ void mma8(float d[4], const uint32_t a[4], const uint32_t b[2]) {
    asm("mma.sync.aligned.m16n8k8.row.col.f32.tf32.tf32.f32 "
        "{%0,%1,%2,%3}, {%4,%5,%6,%7}, {%8,%9}, {%0,%1,%2,%3};"
        : "+f"(d[0]), "+f"(d[1]), "+f"(d[2]), "+f"(d[3])
        : "r"(a[0]), "r"(a[1]), "r"(a[2]), "r"(a[3]), "r"(b[0]), "r"(b[1]));
}

// pair-permuted k index within each 8-block: k -> (k&~7) + (k&3)*2 + ((k>>2)&1)
__device__ __forceinline__ int kperm(int k) {
    return (k & ~7) + ((k & 3) * 2) + ((k >> 2) & 1);
}

// ---------------- scratch ----------------
__device__ float g_proj[T_SEQ * NPROJ];            // [t, 2560]
__device__ float g_M[NH * T_SEQ * DHD * DHD];      // [n, q, k, j]
__device__ float g_Ga[NH * T_SEQ * DHD * DHD];     // [n, q, a, c] p-half 0
__device__ float g_Gb[NH * T_SEQ * DHD * DHD];     // [n, q, a, c] p-half 1
__device__ float g_l[2 * NH * T_SEQ];              // softmax denominator partials
__device__ float g_z[T_SEQ * DMODEL];              // [q, n*64+e]

// ---------------- K0: zero z + l ----------------
#define NZERO (T_SEQ * DMODEL + 2 * NH * T_SEQ)
__global__ __launch_bounds__(256) void zero_kernel() {
    int i = blockIdx.x * 256 + threadIdx.x;
    if (i < T_SEQ * DMODEL) g_z[i] = 0.f;
    else g_l[i - T_SEQ * DMODEL] = 0.f;
}

// ---------------- K1: C[M,N] = A[M,K] @ B[K,N] + bias ----------------
__global__ __launch_bounds__(256) void gemm_nn_bias_kernel(
    const float* __restrict__ A, const float* __restrict__ B,
    const float* __restrict__ bias, float* __restrict__ C,
    int M, int N, int K) {
    __shared__ float AsT[32 * 68];
    __shared__ float Bs[32 * 68];
    const int tid = threadIdx.x;
    const int bm = blockIdx.y * 64;
    const int bn = blockIdx.x * 64;
    const int r0 = (tid & 15) * 4;
    const int c0 = (tid >> 4) * 4;
    const int arow = tid >> 3;
    const int acol = (tid & 7) * 4;
    const int brow = tid >> 4;
    const int bcol = (tid & 15) * 4;
    unsigned long long acc2[4][2] = {};
    for (int k0 = 0; k0 < K; k0 += 32) {
#pragma unroll
        for (int rr = 0; rr < 2; rr++) {
            int r = arow + rr * 32;
            float4 v = *reinterpret_cast<const float4*>(&A[(size_t)(bm + r) * K + k0 + acol]);
            AsT[(acol + 0) * 68 + r] = v.x; AsT[(acol + 1) * 68 + r] = v.y;
            AsT[(acol + 2) * 68 + r] = v.z; AsT[(acol + 3) * 68 + r] = v.w;
        }
#pragma unroll
        for (int rr = 0; rr < 2; rr++) {
            float4 v = *reinterpret_cast<const float4*>(&B[(size_t)(k0 + brow + rr * 16) * N + bn + bcol]);
            *reinterpret_cast<float4*>(&Bs[(brow + rr * 16) * 68 + bcol]) = v;
        }
        __syncthreads();
#pragma unroll
        for (int kk = 0; kk < 32; kk++) {
            float4 a = *reinterpret_cast<const float4*>(&AsT[kk * 68 + r0]);
            ulonglong2 b2 = *reinterpret_cast<const ulonglong2*>(&Bs[kk * 68 + c0]);
            unsigned long long as[4] = {splat2(a.x), splat2(a.y), splat2(a.z), splat2(a.w)};
#pragma unroll
            for (int i = 0; i < 4; i++) {
                acc2[i][0] = fma2(as[i], b2.x, acc2[i][0]);
                acc2[i][1] = fma2(as[i], b2.y, acc2[i][1]);
            }
        }
        __syncthreads();
    }
    float4 bb = *reinterpret_cast<const float4*>(&bias[bn + c0]);
#pragma unroll
    for (int i = 0; i < 4; i++) {
        float2 p0 = unpack2(acc2[i][0]);
        float2 p1 = unpack2(acc2[i][1]);
        float4 o = make_float4(p0.x + bb.x, p0.y + bb.y, p1.x + bb.z, p1.y + bb.w);
        *reinterpret_cast<float4*>(&C[(size_t)(bm + r0 + i) * N + bn + c0]) = o;
    }
}

// ---------------- K2: M[n,q,kj] = sum_i qproj[q,i] * Wkq[n,kj,i] ----------------
__global__ __launch_bounds__(256) void compute_M_kernel(const float* __restrict__ Wkq) {
    __shared__ float AsT[64 * 68];
    __shared__ float BsT[64 * 68];
    const int n = blockIdx.z;
    const int bq = blockIdx.y * 64;
    const int bkj = blockIdx.x * 64;
    const int tid = threadIdx.x;
    const int row = tid >> 4;
    const int col = (tid & 15) * 4;
#pragma unroll
    for (int rr = 0; rr < 4; rr++) {
        int r = row + rr * 16;
        float4 va = *reinterpret_cast<const float4*>(&g_proj[(size_t)(bq + r) * NPROJ + 1024 + n * 64 + col]);
        AsT[(col + 0) * 68 + r] = va.x; AsT[(col + 1) * 68 + r] = va.y;
        AsT[(col + 2) * 68 + r] = va.z; AsT[(col + 3) * 68 + r] = va.w;
        float4 vb = *reinterpret_cast<const float4*>(&Wkq[(size_t)n * 262144 + (size_t)(bkj + r) * 64 + col]);
        BsT[(col + 0) * 68 + r] = vb.x; BsT[(col + 1) * 68 + r] = vb.y;
        BsT[(col + 2) * 68 + r] = vb.z; BsT[(col + 3) * 68 + r] = vb.w;
    }
    __syncthreads();
    const int q0 = (tid & 15) * 4;
    const int kj0 = (tid >> 4) * 4;
    unsigned long long acc2[4][2] = {};
#pragma unroll 8
    for (int i = 0; i < 64; i++) {
        float4 a = *reinterpret_cast<const float4*>(&AsT[i * 68 + q0]);
        ulonglong2 b2 = *reinterpret_cast<const ulonglong2*>(&BsT[i * 68 + kj0]);
        unsigned long long as[4] = {splat2(a.x), splat2(a.y), splat2(a.z), splat2(a.w)};
#pragma unroll
        for (int ii = 0; ii < 4; ii++) {
            acc2[ii][0] = fma2(as[ii], b2.x, acc2[ii][0]);
            acc2[ii][1] = fma2(as[ii], b2.y, acc2[ii][1]);
        }
    }
#pragma unroll
    for (int ii = 0; ii < 4; ii++) {
        float2 p0 = unpack2(acc2[ii][0]);
        float2 p1 = unpack2(acc2[ii][1]);
        float4 o = make_float4(p0.x, p0.y, p1.x, p1.y);
        *reinterpret_cast<float4*>(&g_M[(size_t)(n * T_SEQ + bq + q0 + ii) * 4096 + bkj + kj0]) = o;
    }
}

// ---------------- K3: attention, 2 CTAs per (n,q) split by p-half ----------------
// smem regions (floats):
// U  [0, 8704): phase1 k1s [p][k-perm] s68; phase2 k2s [t][j-perm] s68 (4352) + v2T [c][t-perm] s68; phase3 v1s [128][64]
// BP [8704, 17408): B [p][j-perm] s68 (tf32)
// Cg [17408, 26112): phase1 MT [j][k-perm] s68 (4352); phase2 ET [p][t-perm] s68 (tf32); phase3 RT [c][p] s130
// red [26112, 26120)
#define OFF_U   0
#define OFF_V2T 4352
#define OFF_BP  8704
#define OFF_C   17408
#define OFF_RED 26112
#define ATTN_SMEM_FLOATS 26120
#define ATTN_SMEM_BYTES (ATTN_SMEM_FLOATS * 4)

__global__ __launch_bounds__(256, 2) void attn_kernel() {
    extern __shared__ float sm[];
    const int bid = blockIdx.x;
    const int q = 255 - (bid >> 4);
    const int n = (bid >> 1) & 7;
    const int ph = bid & 1;
    const int P = q + 1;
    const int p_base = ph << 7;
    const int p_count_raw = P - p_base;
    if (p_count_raw <= 0) return;
    const int p_count = min(p_count_raw, 128);
    const int tid = threadIdx.x;

    float* U   = sm + OFF_U;
    float* BP  = sm + OFF_BP;
    float* Cg  = sm + OFF_C;
    float* red = sm + OFF_RED;

    const int pl = tid & 31;
    const int wid = tid >> 5;
    const int gid = pl >> 2;          // mma group 0..7
    const int tidg = pl & 3;          // thread-in-group 0..3

    // ---- load MT[j][k-perm] (stride 68) from g_M[k][j] ----
    {
        const float* Mg = g_M + (size_t)(n * T_SEQ + q) * 4096;
        float* MT = Cg;
        const int rr = tid >> 4;            // k = pass*16 + rr
        const int jv = (tid & 15) * 4;
#pragma unroll
        for (int pass = 0; pass < 4; pass++) {
            int k = pass * 16 + rr;
            float4 v = *reinterpret_cast<const float4*>(&Mg[k * 64 + jv]);
            int kp = kperm(k);
            MT[(jv + 0) * 68 + kp] = f2tf_f(v.x);
            MT[(jv + 1) * 68 + kp] = f2tf_f(v.y);
            MT[(jv + 2) * 68 + kp] = f2tf_f(v.z);
            MT[(jv + 3) * 68 + kp] = f2tf_f(v.w);
        }
    }
    // ---- load k1s[p][k-perm] (stride 68, tf32), zero rows >= p_count ----
    {
        float* k1s = U;
        const int rr = tid >> 4;
        const int iv = (tid & 15) * 4;      // iv&7 in {0,4}
        const int basep = (iv & ~7) + ((iv >> 2) & 1);
#pragma unroll
        for (int pass = 0; pass < 8; pass++) {
            int lp = pass * 16 + rr;
            float4 v = make_float4(0.f, 0.f, 0.f, 0.f);
            if (lp < p_count)
                v = *reinterpret_cast<const float4*>(&g_proj[(size_t)(p_base + lp) * NPROJ + n * 64 + iv]);
            float* row = &k1s[lp * 68 + basep];
            row[0] = f2tf_f(v.x);
            row[2] = f2tf_f(v.y);
            row[4] = f2tf_f(v.z);
            row[6] = f2tf_f(v.w);
        }
    }
    __syncthreads();

    // ---- phase 1 (tf32 mma): B[p,j] = sum_k k1[p,k]*M[k,j]; store BP[p][j-perm] ----
    {
        const float* k1s = U;
        const float* MT = Cg;
        const int p0w = (wid & 3) * 32;
        const int j0w = (wid >> 2) * 32;
        float bacc[2][4][4] = {};
#pragma unroll
        for (int k = 0; k < 8; k++) {
            const int k0 = k * 8;
            uint32_t afr[2][4], bfr[4][2];
#pragma unroll
            for (int mt = 0; mt < 2; mt++) {
                int pb = p0w + mt * 16;
                float2 lo = *reinterpret_cast<const float2*>(&k1s[(pb + gid) * 68 + k0 + 2 * tidg]);
                float2 hi = *reinterpret_cast<const float2*>(&k1s[(pb + gid + 8) * 68 + k0 + 2 * tidg]);
                afr[mt][0] = __float_as_uint(lo.x);
                afr[mt][1] = __float_as_uint(hi.x);
                afr[mt][2] = __float_as_uint(lo.y);
                afr[mt][3] = __float_as_uint(hi.y);
            }
#pragma unroll
            for (int nt = 0; nt < 4; nt++) {
                float2 b = *reinterpret_cast<const float2*>(&MT[(j0w + nt * 8 + gid) * 68 + k0 + 2 * tidg]);
                bfr[nt][0] = __float_as_uint(b.x);
                bfr[nt][1] = __float_as_uint(b.y);
            }
#pragma unroll
            for (int mt = 0; mt < 2; mt++)
#pragma unroll
                for (int nt = 0; nt < 4; nt++)
                    mma8(bacc[mt][nt], afr[mt], bfr[nt]);
        }
#pragma unroll
        for (int mt = 0; mt < 2; mt++)
#pragma unroll
            for (int nt = 0; nt < 4; nt++)
#pragma unroll
                for (int r = 0; r < 4; r++) {
                    int p = p0w + mt * 16 + gid + ((r >> 1) << 3);
                    int j = j0w + nt * 8 + 2 * tidg + (r & 1);
                    BP[p * 68 + kperm(j)] = f2tf_f(bacc[mt][nt][r]);
                }
    }
    __syncthreads();

    // ---- phase 2 (tf32 mma): stream t-tiles over [0, P) ----
    float rfr[2][4][4] = {};
    float lsum = 0.f;
    float* k2s = U;                   // [t][j-perm] stride 68
    float* v2T = U + OFF_V2T;         // [c][t-perm] stride 68
    float* ET  = Cg;                  // [p][t-perm] stride 68
    const int s_t0w = (wid & 1) * 32, s_p0w = (wid >> 1) * 32;
    const int r_p0 = (wid & 3) * 32, r_c0 = (wid >> 2) * 32;
    for (int t0 = 0; t0 < P; t0 += 64) {
        // load k2 tile [t][j-perm]
        {
            const int rr = tid >> 4;
            const int iv = (tid & 15) * 4;
            const int basep = (iv & ~7) + ((iv >> 2) & 1);
#pragma unroll
            for (int pass = 0; pass < 4; pass++) {
                int t = pass * 16 + rr;
                int gt = t0 + t;
                float4 a = make_float4(0.f, 0.f, 0.f, 0.f);
                if (gt < P) a = *reinterpret_cast<const float4*>(&g_proj[(size_t)gt * NPROJ + 512 + n * 64 + iv]);
                float* row = &k2s[t * 68 + basep];
                row[0] = f2tf_f(a.x);
                row[2] = f2tf_f(a.y);
                row[4] = f2tf_f(a.z);
                row[6] = f2tf_f(a.w);
            }
        }
        // load v2 tile transposed [c][t-perm]
        {
            const int c = tid & 63;
            const int tg4 = (tid >> 6) * 4;
#pragma unroll
            for (int it = 0; it < 4; it++) {
                int t4 = it * 16 + tg4;
                int basep = (t4 & ~7) + ((t4 >> 2) & 1);
#pragma unroll
                for (int k = 0; k < 4; k++) {
                    int gt = t0 + t4 + k;
                    float v = (gt < P) ? g_proj[(size_t)gt * NPROJ + 2048 + n * 64 + c] : 0.f;
                    v2T[c * 68 + basep + 2 * k] = f2tf_f(v);
                }
            }
        }
        __syncthreads();
        // ---- S^T mma: D[t][p] = sum_j k2[t][j] * B[p][j] ----
        {
            float sfr[2][4][4] = {};
#pragma unroll
            for (int k = 0; k < 8; k++) {
                const int j0 = k * 8;
                uint32_t afr[2][4], bfr[4][2];
#pragma unroll
                for (int mt = 0; mt < 2; mt++) {
                    int tb = s_t0w + mt * 16;
                    float2 lo = *reinterpret_cast<const float2*>(&k2s[(tb + gid) * 68 + j0 + 2 * tidg]);
                    float2 hi = *reinterpret_cast<const float2*>(&k2s[(tb + gid + 8) * 68 + j0 + 2 * tidg]);
                    afr[mt][0] = __float_as_uint(lo.x);
                    afr[mt][1] = __float_as_uint(hi.x);
                    afr[mt][2] = __float_as_uint(lo.y);
                    afr[mt][3] = __float_as_uint(hi.y);
                }
#pragma unroll
                for (int nt = 0; nt < 4; nt++) {
                    float2 b = *reinterpret_cast<const float2*>(&BP[(s_p0w + nt * 8 + gid) * 68 + j0 + 2 * tidg]);
                    bfr[nt][0] = __float_as_uint(b.x);
                    bfr[nt][1] = __float_as_uint(b.y);
                }
#pragma unroll
                for (int mt = 0; mt < 2; mt++)
#pragma unroll
                    for (int nt = 0; nt < 4; nt++)
                        mma8(sfr[mt][nt], afr[mt], bfr[nt]);
            }
            // exp + mask + store ET[p][t-perm]
#pragma unroll
            for (int mt = 0; mt < 2; mt++)
#pragma unroll
                for (int nt = 0; nt < 4; nt++)
#pragma unroll
                    for (int r = 0; r < 4; r++) {
                        int t_loc = s_t0w + mt * 16 + gid + ((r >> 1) << 3);
                        int p_loc = s_p0w + nt * 8 + 2 * tidg + (r & 1);
                        int gt = t0 + t_loc;
                        int gp = p_base + p_loc;
                        float e = (gp < P && gt < P) ? __expf(sfr[mt][nt][r] * 0.015625f) : 0.f;
                        lsum += e;
                        ET[p_loc * 68 + kperm(t_loc)] = f2tf_f(e);
                    }
        }
        __syncthreads();
        // ---- R mma: R[p][c] += sum_t E[p][t] * v2[t][c] ----
        {
#pragma unroll
            for (int k = 0; k < 8; k++) {
                const int t8 = k * 8;
                uint32_t afr[2][4], bfr[4][2];
#pragma unroll
                for (int mt = 0; mt < 2; mt++) {
                    int pb = r_p0 + mt * 16;
                    float2 lo = *reinterpret_cast<const float2*>(&ET[(pb + gid) * 68 + t8 + 2 * tidg]);
                    float2 hi = *reinterpret_cast<const float2*>(&ET[(pb + gid + 8) * 68 + t8 + 2 * tidg]);
                    afr[mt][0] = __float_as_uint(lo.x);
                    afr[mt][1] = __float_as_uint(hi.x);
                    afr[mt][2] = __float_as_uint(lo.y);
                    afr[mt][3] = __float_as_uint(hi.y);
                }
#pragma unroll
                for (int nt = 0; nt < 4; nt++) {
                    float2 b = *reinterpret_cast<const float2*>(&v2T[(r_c0 + nt * 8 + gid) * 68 + t8 + 2 * tidg]);
                    bfr[nt][0] = __float_as_uint(b.x);
                    bfr[nt][1] = __float_as_uint(b.y);
                }
#pragma unroll
                for (int mt = 0; mt < 2; mt++)
#pragma unroll
                    for (int nt = 0; nt < 4; nt++)
                        mma8(rfr[mt][nt], afr[mt], bfr[nt]);
            }
        }
        __syncthreads();
    }

    // ---- stage RT[c][p] (stride 130) into Cg; load v1 rows into U ----
    {
        float* RT = Cg;
#pragma unroll
        for (int mt = 0; mt < 2; mt++)
#pragma unroll
            for (int nt = 0; nt < 4; nt++)
#pragma unroll
                for (int r = 0; r < 4; r++) {
                    int p = r_p0 + mt * 16 + gid + ((r >> 1) << 3);
                    int c = r_c0 + nt * 8 + 2 * tidg + (r & 1);
                    RT[c * 130 + p] = rfr[mt][nt][r];
                }
    }
    {
        float* v1s = U;   // [128][64]
        const int rr = tid >> 4;
        const int iv = (tid & 15) * 4;
#pragma unroll
        for (int pass = 0; pass < 8; pass++) {
            int lp = pass * 16 + rr;
            if (lp < p_count) {
                float4 v = *reinterpret_cast<const float4*>(
                    &g_proj[(size_t)(p_base + lp) * NPROJ + 1536 + n * 64 + iv]);
                *reinterpret_cast<float4*>(&v1s[lp * 64 + iv]) = v;
            }
        }
    }
    // lsum reduce
#pragma unroll
    for (int off = 16; off > 0; off >>= 1)
        lsum += __shfl_xor_sync(0xffffffffu, lsum, off);
    if (pl == 0) red[wid] = lsum;
    __syncthreads();
    if (tid == 0) {
        float total = 0.f;
#pragma unroll
        for (int w = 0; w < 8; w++) total += red[w];
        g_l[ph * (NH * T_SEQ) + n * T_SEQ + q] = total;
    }

    // ---- phase 3 (FFMA2 fp32): G[a,c] = sum_{lp<p_count} v1[lp,a] * RT[c,lp] ----
    {
        const float* v1s = U;
        const float* RT = Cg;
        const int a0 = (tid & 15) * 4;
        const int c0 = (tid >> 4) * 4;
        unsigned long long acc2[2][4] = {};
#pragma unroll 4
        for (int p = 0; p < p_count; p++) {
            ulonglong2 av2 = *reinterpret_cast<const ulonglong2*>(&v1s[p * 64 + a0]);
#pragma unroll
            for (int k = 0; k < 4; k++) {
                unsigned long long r2 = splat2(RT[(c0 + k) * 130 + p]);
                acc2[0][k] = fma2(av2.x, r2, acc2[0][k]);
                acc2[1][k] = fma2(av2.y, r2, acc2[1][k]);
            }
        }
        float* Gout = (ph ? g_Gb : g_Ga) + (size_t)(n * T_SEQ + q) * 4096;
#pragma unroll
        for (int h = 0; h < 2; h++) {
            float2 v0 = unpack2(acc2[h][0]);
            float2 v1 = unpack2(acc2[h][1]);
            float2 v2 = unpack2(acc2[h][2]);
            float2 v3 = unpack2(acc2[h][3]);
            float4 lo = make_float4(v0.x, v1.x, v2.x, v3.x);
            float4 hi = make_float4(v0.y, v1.y, v2.y, v3.y);
            *reinterpret_cast<float4*>(&Gout[(a0 + 2 * h + 0) * 64 + c0]) = lo;
            *reinterpret_cast<float4*>(&Gout[(a0 + 2 * h + 1) * 64 + c0]) = hi;
        }
    }
}

// ---------------- K4: z_raw += (Ga+Gb) @ W_Vq (K-split, atomics) ----------------
__global__ __launch_bounds__(256) void out_v_kernel(const float* __restrict__ Wvq) {
    __shared__ float AsT[32 * 68];
    __shared__ float Bs[32 * 68];
    const int n = blockIdx.y;
    const int bq = blockIdx.x * 64;
    const int ks = blockIdx.z;
    const int tid = threadIdx.x;
    const bool two = (bq >= 128);
    const int arow = tid >> 3, acol = (tid & 7) * 4;
    const int brow = tid >> 4, bcol = (tid & 15) * 4;
    const int q0 = (tid & 15) * 4, e0 = (tid >> 4) * 4;
    unsigned long long acc2[4][2] = {};
    for (int k0 = ks * 1024; k0 < ks * 1024 + 1024; k0 += 32) {
#pragma unroll
        for (int rr = 0; rr < 2; rr++) {
            int r = arow + rr * 32;
            size_t idx = (size_t)(n * T_SEQ + bq + r) * 4096 + k0 + acol;
            float4 v = *reinterpret_cast<const float4*>(&g_Ga[idx]);
            if (two) {
                float4 w = *reinterpret_cast<const float4*>(&g_Gb[idx]);
                v.x += w.x; v.y += w.y; v.z += w.z; v.w += w.w;
            }
            AsT[(acol + 0) * 68 + r] = v.x; AsT[(acol + 1) * 68 + r] = v.y;
            AsT[(acol + 2) * 68 + r] = v.z; AsT[(acol + 3) * 68 + r] = v.w;
        }
#pragma unroll
        for (int rr = 0; rr < 2; rr++) {
            float4 v = *reinterpret_cast<const float4*>(
                &Wvq[(size_t)n * 262144 + (size_t)(k0 + brow + rr * 16) * 64 + bcol]);
            *reinterpret_cast<float4*>(&Bs[(brow + rr * 16) * 68 + bcol]) = v;
        }
        __syncthreads();
#pragma unroll
        for (int kk = 0; kk < 32; kk++) {
            float4 a = *reinterpret_cast<const float4*>(&AsT[kk * 68 + q0]);
            ulonglong2 b2 = *reinterpret_cast<const ulonglong2*>(&Bs[kk * 68 + e0]);
            unsigned long long as[4] = {splat2(a.x), splat2(a.y), splat2(a.z), splat2(a.w)};
#pragma unroll
            for (int i = 0; i < 4; i++) {
                acc2[i][0] = fma2(as[i], b2.x, acc2[i][0]);
                acc2[i][1] = fma2(as[i], b2.y, acc2[i][1]);
            }
        }
        __syncthreads();
    }
#pragma unroll
    for (int i = 0; i < 4; i++) {
        float2 p0 = unpack2(acc2[i][0]);
        float2 p1 = unpack2(acc2[i][1]);
        float* zp = &g_z[(size_t)(bq + q0 + i) * DMODEL + n * 64 + e0];
        atomicAdd(zp + 0, p0.x);
        atomicAdd(zp + 1, p0.y);
        atomicAdd(zp + 2, p1.x);
        atomicAdd(zp + 3, p1.y);
    }
}

// ---------------- K5: out = (z_raw * 1/(la+lb)) @ W_out + b_out ----------------
__global__ __launch_bounds__(256) void gemm_out_kernel(
    const float* __restrict__ Wout, const float* __restrict__ bout, float* __restrict__ C) {
    __shared__ float AsT[32 * 68];
    __shared__ float Bs[32 * 68];
    const int tid = threadIdx.x;
    const int bm = blockIdx.y * 64;
    const int bn = blockIdx.x * 64;
    const int r0 = (tid & 15) * 4;
    const int c0 = (tid >> 4) * 4;
    const int arow = tid >> 3, acol = (tid & 7) * 4;
    const int brow = tid >> 4, bcol = (tid & 15) * 4;
    unsigned long long acc2[4][2] = {};
    for (int k0 = 0; k0 < DMODEL; k0 += 32) {
#pragma unroll
        for (int rr = 0; rr < 2; rr++) {
            int r = bm + arow + rr * 32;
            int gk = k0 + acol;
            int li = (gk >> 6) * T_SEQ + r;
            float invl = 1.f / (g_l[li] + g_l[NH * T_SEQ + li]);
            float4 v = *reinterpret_cast<const float4*>(&g_z[(size_t)r * DMODEL + gk]);
            AsT[(acol + 0) * 68 + arow + rr * 32] = v.x * invl;
            AsT[(acol + 1) * 68 + arow + rr * 32] = v.y * invl;
            AsT[(acol + 2) * 68 + arow + rr * 32] = v.z * invl;
            AsT[(acol + 3) * 68 + arow + rr * 32] = v.w * invl;
        }
#pragma unroll
        for (int rr = 0; rr < 2; rr++) {
            float4 v = *reinterpret_cast<const float4*>(&Wout[(size_t)(k0 + brow + rr * 16) * DMODEL + bn + bcol]);
            *reinterpret_cast<float4*>(&Bs[(brow + rr * 16) * 68 + bcol]) = v;
        }
        __syncthreads();
#pragma unroll
        for (int kk = 0; kk < 32; kk++) {
            float4 a = *reinterpret_cast<const float4*>(&AsT[kk * 68 + r0]);
            ulonglong2 b2 = *reinterpret_cast<const ulonglong2*>(&Bs[kk * 68 + c0]);
            unsigned long long as[4] = {splat2(a.x), splat2(a.y), splat2(a.z), splat2(a.w)};
#pragma unroll
            for (int i = 0; i < 4; i++) {
                acc2[i][0] = fma2(as[i], b2.x, acc2[i][0]);
                acc2[i][1] = fma2(as[i], b2.y, acc2[i][1]);
            }
        }
        __syncthreads();
    }
    float4 bb = *reinterpret_cast<const float4*>(&bout[bn + c0]);
#pragma unroll
    for (int i = 0; i < 4; i++) {
        float2 p0 = unpack2(acc2[i][0]);
        float2 p1 = unpack2(acc2[i][1]);
        float4 o = make_float4(p0.x + bb.x, p0.y + bb.y, p1.x + bb.z, p1.y + bb.w);
        *reinterpret_cast<float4*>(&C[(size_t)(bm + r0 + i) * DMODEL + bn + c0]) = o;
    }
}

// ---------------- launch ----------------
extern "C" void kernel_launch(void* const* d_in, const int* in_sizes, int n_in,
                              void* d_out, int out_size) {
    const float* x       = (const float*)d_in[0];
    const float* Wkkqvv  = (const float*)d_in[1];
    const float* bkkqvv  = (const float*)d_in[2];
    const float* WKq     = (const float*)d_in[3];
    const float* WVq     = (const float*)d_in[4];
    const float* Wout    = (const float*)d_in[5];
    const float* bout    = (const float*)d_in[6];
    float* out = (float*)d_out;

    float* proj_ptr = nullptr;
    cudaGetSymbolAddress((void**)&proj_ptr, g_proj);

    cudaFuncSetAttribute(attn_kernel, cudaFuncAttributeMaxDynamicSharedMemorySize, ATTN_SMEM_BYTES);

    zero_kernel<<<(NZERO + 255) / 256, 256>>>();
    gemm_nn_bias_kernel<<<dim3(NPROJ / 64, T_SEQ / 64), 256>>>(x, Wkkqvv, bkkqvv, proj_ptr,
                                                               T_SEQ, NPROJ, DMODEL);
    compute_M_kernel<<<dim3(64, 4, NH), 256>>>(WKq);
    attn_kernel<<<NH * T_SEQ * 2, 256, ATTN_SMEM_BYTES>>>();
    out_v_kernel<<<dim3(4, NH, 4), 256>>>(WVq);
    gemm_out_kernel<<<dim3(DMODEL / 64, T_SEQ / 64), 256>>>(Wout, bout, out);
}

// round 11
// speedup vs baseline: 1.8255x; 1.8255x over previous
#include <cuda_runtime.h>
#include <cstdint>

#define T_SEQ 256
#define NH 8
#define DHD 64
#define DMODEL 512
#define NPROJ 2560   // 5 * 512

// ---------------- packed fp32x2 helpers (Blackwell FFMA2) ----------------
__device__ __forceinline__ unsigned long long splat2(float x) {
    unsigned long long r;
    asm("mov.b64 %0, {%1, %1};" : "=l"(r) : "f"(x));
    return r;
}
__device__ __forceinline__ unsigned long long fma2(unsigned long long a, unsigned long long b,
                                                   unsigned long long c) {
    unsigned long long d;
    asm("fma.rn.f32x2 %0, %1, %2, %3;" : "=l"(d) : "l"(a), "l"(b), "l"(c));
    return d;
}
__device__ __forceinline__ float2 unpack2(unsigned long long v) {
    float2 f;
    asm("mov.b64 {%0, %1}, %2;" : "=f"(f.x), "=f"(f.y) : "l"(v));
    return f;
}

// ---------------- tf32 / bf16 helpers ----------------
__device__ __forceinline__ uint32_t f2tf(float x) {
    uint32_t u;
    asm("cvt.rna.tf32.f32 %0, %1;" : "=r"(u) : "f"(x));
    return u;
}
__device__ __forceinline__ float f2tf_f(float x) { return __uint_as_float(f2tf(x)); }

// pack two fp32 -> bf16x2 (lo = first arg, hi = second arg)
__device__ __forceinline__ uint32_t bf2(float lo, float hi) {
    uint32_t r;
    asm("cvt.rn.bf16x2.f32 %0, %1, %2;" : "=r"(r) : "f"(hi), "f"(lo));
    return r;
}

__device__ __forceinline__ void mma8(float d[4], const uint32_t a[4], const uint32_t b[2]) {
    asm("mma.sync.aligned.m16n8k8.row.col.f32.tf32.tf32.f32 "
        "{%0,%1,%2,%3}, {%4,%5,%6,%7}, {%8,%9}, {%0,%1,%2,%3};"
        : "+f"(d[0]), "+f"(d[1]), "+f"(d[2]), "+f"(d[3])
        : "r"(a[0]), "r"(a[1]), "r"(a[2]), "r"(a[3]), "r"(b[0]), "r"(b[1]));
}
__device__ __forceinline__ void mma16bf(float d[4], const uint32_t a[4], const uint32_t b[2]) {
    asm("mma.sync.aligned.m16n8k16.row.col.f32.bf16.bf16.f32 "
        "{%0,%1,%2,%3}, {%4,%5,%6,%7}, {%8,%9}, {%0,%1,%2,%3};"
        : "+f"(d[0]), "+f"(d[1]), "+f"(d[2]), "+f"(d[3])
        : "r"(a[0]), "r"(a[1]), "r"(a[2]), "r"(a[3]), "r"(b[0]), "r"(b[1]));
}

// ---------------- scratch ----------------
__device__ float g_proj[T_SEQ * NPROJ];            // [t, 2560]
__device__ float g_M[NH * T_SEQ * DHD * DHD];      // [n, q, k, j]
__device__ float g_Ga[NH * T_SEQ * DHD * DHD];     // [n, q, a, c] p-half 0
__device__ float g_Gb[NH * T_SEQ * DHD * DHD];     // [n, q, a, c] p-half 1
__device__ float g_l[2 * NH * T_SEQ];              // softmax denominator partials
__device__ float g_z[T_SEQ * DMODEL];              // [q, n*64+e]

// ---------------- K0: zero z + l ----------------
#define NZERO (T_SEQ * DMODEL + 2 * NH * T_SEQ)
__global__ __launch_bounds__(256) void zero_kernel() {
    int i = blockIdx.x * 256 + threadIdx.x;
    if (i < T_SEQ * DMODEL) g_z[i] = 0.f;
    else g_l[i - T_SEQ * DMODEL] = 0.f;
}

// ---------------- K1: C[M,N] = A[M,K] @ B[K,N] + bias ----------------
__global__ __launch_bounds__(256) void gemm_nn_bias_kernel(
    const float* __restrict__ A, const float* __restrict__ B,
    const float* __restrict__ bias, float* __restrict__ C,
    int M, int N, int K) {
    __shared__ float AsT[32 * 68];
    __shared__ float Bs[32 * 68];
    const int tid = threadIdx.x;
    const int bm = blockIdx.y * 64;
    const int bn = blockIdx.x * 64;
    const int r0 = (tid & 15) * 4;
    const int c0 = (tid >> 4) * 4;
    const int arow = tid >> 3;
    const int acol = (tid & 7) * 4;
    const int brow = tid >> 4;
    const int bcol = (tid & 15) * 4;
    unsigned long long acc2[4][2] = {};
    for (int k0 = 0; k0 < K; k0 += 32) {
#pragma unroll
        for (int rr = 0; rr < 2; rr++) {
            int r = arow + rr * 32;
            float4 v = *reinterpret_cast<const float4*>(&A[(size_t)(bm + r) * K + k0 + acol]);
            AsT[(acol + 0) * 68 + r] = v.x; AsT[(acol + 1) * 68 + r] = v.y;
            AsT[(acol + 2) * 68 + r] = v.z; AsT[(acol + 3) * 68 + r] = v.w;
        }
#pragma unroll
        for (int rr = 0; rr < 2; rr++) {
            float4 v = *reinterpret_cast<const float4*>(&B[(size_t)(k0 + brow + rr * 16) * N + bn + bcol]);
            *reinterpret_cast<float4*>(&Bs[(brow + rr * 16) * 68 + bcol]) = v;
        }
        __syncthreads();
#pragma unroll
        for (int kk = 0; kk < 32; kk++) {
            float4 a = *reinterpret_cast<const float4*>(&AsT[kk * 68 + r0]);
            ulonglong2 b2 = *reinterpret_cast<const ulonglong2*>(&Bs[kk * 68 + c0]);
            unsigned long long as[4] = {splat2(a.x), splat2(a.y), splat2(a.z), splat2(a.w)};
#pragma unroll
            for (int i = 0; i < 4; i++) {
                acc2[i][0] = fma2(as[i], b2.x, acc2[i][0]);
                acc2[i][1] = fma2(as[i], b2.y, acc2[i][1]);
            }
        }
        __syncthreads();
    }
    float4 bb = *reinterpret_cast<const float4*>(&bias[bn + c0]);
#pragma unroll
    for (int i = 0; i < 4; i++) {
        float2 p0 = unpack2(acc2[i][0]);
        float2 p1 = unpack2(acc2[i][1]);
        float4 o = make_float4(p0.x + bb.x, p0.y + bb.y, p1.x + bb.z, p1.y + bb.w);
        *reinterpret_cast<float4*>(&C[(size_t)(bm + r0 + i) * N + bn + c0]) = o;
    }
}

// ---------------- K2: M[n,q,kj] = sum_i qproj[q,i] * Wkq[n,kj,i] ----------------
__global__ __launch_bounds__(256) void compute_M_kernel(const float* __restrict__ Wkq) {
    __shared__ float AsT[64 * 68];
    __shared__ float BsT[64 * 68];
    const int n = blockIdx.z;
    const int bq = blockIdx.y * 64;
    const int bkj = blockIdx.x * 64;
    const int tid = threadIdx.x;
    const int row = tid >> 4;
    const int col = (tid & 15) * 4;
#pragma unroll
    for (int rr = 0; rr < 4; rr++) {
        int r = row + rr * 16;
        float4 va = *reinterpret_cast<const float4*>(&g_proj[(size_t)(bq + r) * NPROJ + 1024 + n * 64 + col]);
        AsT[(col + 0) * 68 + r] = va.x; AsT[(col + 1) * 68 + r] = va.y;
        AsT[(col + 2) * 68 + r] = va.z; AsT[(col + 3) * 68 + r] = va.w;
        float4 vb = *reinterpret_cast<const float4*>(&Wkq[(size_t)n * 262144 + (size_t)(bkj + r) * 64 + col]);
        BsT[(col + 0) * 68 + r] = vb.x; BsT[(col + 1) * 68 + r] = vb.y;
        BsT[(col + 2) * 68 + r] = vb.z; BsT[(col + 3) * 68 + r] = vb.w;
    }
    __syncthreads();
    const int q0 = (tid & 15) * 4;
    const int kj0 = (tid >> 4) * 4;
    unsigned long long acc2[4][2] = {};
#pragma unroll 8
    for (int i = 0; i < 64; i++) {
        float4 a = *reinterpret_cast<const float4*>(&AsT[i * 68 + q0]);
        ulonglong2 b2 = *reinterpret_cast<const ulonglong2*>(&BsT[i * 68 + kj0]);
        unsigned long long as[4] = {splat2(a.x), splat2(a.y), splat2(a.z), splat2(a.w)};
#pragma unroll
        for (int ii = 0; ii < 4; ii++) {
            acc2[ii][0] = fma2(as[ii], b2.x, acc2[ii][0]);
            acc2[ii][1] = fma2(as[ii], b2.y, acc2[ii][1]);
        }
    }
#pragma unroll
    for (int ii = 0; ii < 4; ii++) {
        float2 p0 = unpack2(acc2[ii][0]);
        float2 p1 = unpack2(acc2[ii][1]);
        float4 o = make_float4(p0.x, p0.y, p1.x, p1.y);
        *reinterpret_cast<float4*>(&g_M[(size_t)(n * T_SEQ + bq + q0 + ii) * 4096 + bkj + kj0]) = o;
    }
}

// ---------------- K3: attention, 2 CTAs per (n,q) split by p-half ----------------
// smem regions (floats):
// U  [0, 8704): phase1 k1T s129; phase2 k2b (uint32 [64][36]) + v2T [c][t] s68 at +4352; phase3 v1s [128][64]
// BP [8704, 17408): phase2 BPb (uint32 [128][36] = 4608)
// Cg [17408, 26112): phase1 M s64; phase2 ET [p][t] s68 (tf32); phase3 RT [c][p] s130
// red [26112, 26120)
#define OFF_U   0
#define OFF_V2T 4352
#define OFF_BP  8704
#define OFF_C   17408
#define OFF_RED 26112
#define ATTN_SMEM_FLOATS 26120
#define ATTN_SMEM_BYTES (ATTN_SMEM_FLOATS * 4)

// NI = ceil(p_count/32) in 1..4 (phases 1/3 only)
template <int NI>
__device__ __forceinline__ void attn_body(float* sm, int n, int q, int ph, int tid) {
    float* U   = sm + OFF_U;
    uint32_t* BPb = reinterpret_cast<uint32_t*>(sm + OFF_BP);   // [p][j/2] stride 36
    float* Cg  = sm + OFF_C;
    float* red = sm + OFF_RED;

    const int P = q + 1;
    const int p_base = ph << 7;
    const int p_count = min(P - p_base, 128);
    const int pl = tid & 31;
    const int wid = tid >> 5;
    const int c8 = wid * 8;
    const int gid = pl >> 2;          // mma group id 0..7
    const int tidg = pl & 3;          // thread-in-group 0..3

    // ---- load M into Cg region (stride 64) ----
    {
        const float* Mg = g_M + (size_t)(n * T_SEQ + q) * 4096;
        float* Ms = Cg;
#pragma unroll
        for (int r = 0; r < 4; r++) {
            int off = (tid + r * 256) * 4;
            *reinterpret_cast<float4*>(&Ms[off]) = *reinterpret_cast<const float4*>(&Mg[off]);
        }
    }
    // ---- load k1 transposed [k][local p] (stride 129) ----
    {
        float* k1T = U;
        const int rr = tid >> 4;
        const int iv = (tid & 15) * 4;
#pragma unroll
        for (int pass = 0; pass < NI * 2; pass++) {
            int lp = pass * 16 + rr;
            int gp = p_base + lp;
            float4 v = make_float4(0.f, 0.f, 0.f, 0.f);
            if (lp < p_count) v = *reinterpret_cast<const float4*>(&g_proj[(size_t)gp * NPROJ + n * 64 + iv]);
            k1T[(iv + 0) * 129 + lp] = v.x;
            k1T[(iv + 1) * 129 + lp] = v.y;
            k1T[(iv + 2) * 129 + lp] = v.z;
            k1T[(iv + 3) * 129 + lp] = v.w;
        }
    }
    __syncthreads();

    // ---- phase 1 (FFMA2): B[p,j] = sum_k k1[p,k]*M[k,j]; store BPb[p][j/2] bf16x2 ----
    {
        const float* k1T = U;
        const float* Ms = Cg;
        unsigned long long acc2[NI][4] = {};
#pragma unroll 4
        for (int k = 0; k < 64; k++) {
            unsigned long long a2[NI];
#pragma unroll
            for (int i = 0; i < NI; i++) a2[i] = splat2(k1T[k * 129 + pl + 32 * i]);
            const ulonglong2* bp = reinterpret_cast<const ulonglong2*>(&Ms[k * 64 + c8]);
            ulonglong2 b01 = bp[0], b23 = bp[1];
#pragma unroll
            for (int i = 0; i < NI; i++) {
                acc2[i][0] = fma2(a2[i], b01.x, acc2[i][0]);
                acc2[i][1] = fma2(a2[i], b01.y, acc2[i][1]);
                acc2[i][2] = fma2(a2[i], b23.x, acc2[i][2]);
                acc2[i][3] = fma2(a2[i], b23.y, acc2[i][3]);
            }
        }
        __syncthreads();   // M (in Cg) consumed before ET reuse; BPb region untouched before
#pragma unroll
        for (int m = 0; m < 4; m++)
#pragma unroll
            for (int i = 0; i < NI; i++) {
                float2 v = unpack2(acc2[i][m]);
                int p = pl + 32 * i;
                BPb[p * 36 + (c8 >> 1) + m] = bf2(v.x, v.y);
            }
        // zero rows >= p_count (q<128 CTAs): ensures S mma sees 0 (also masked later)
        if (NI < 4) {
            for (int p = p_count + tid; p < 128; p += 256) {
#pragma unroll
                for (int m = 0; m < 36; m++) BPb[p * 36 + m] = 0u;
            }
        }
    }
    __syncthreads();

    // ---- phase 2: stream t-tiles over [0, P); S in bf16 mma, R in tf32 mma ----
    float rfr[2][4][4] = {};
    float lsum = 0.f;
    uint32_t* k2b = reinterpret_cast<uint32_t*>(U);   // [t][j/2] stride 36
    float* v2T = U + OFF_V2T;                         // [c][t] stride 68 (tf32)
    float* ET  = Cg;                                  // [p][t] stride 68 (tf32)
    const int s_t0w = (wid & 1) * 32, s_p0w = (wid >> 1) * 32;
    const int r_p0 = (wid & 3) * 32, r_c0 = (wid >> 2) * 32;
    for (int t0 = 0; t0 < P; t0 += 64) {
        // load k2 tile [t][j] -> bf16 pairs
        {
            const int rr = tid >> 4;
            const int iv = (tid & 15) * 4;
#pragma unroll
            for (int pass = 0; pass < 4; pass++) {
                int t = pass * 16 + rr;
                int gt = t0 + t;
                float4 a = make_float4(0.f, 0.f, 0.f, 0.f);
                if (gt < P) a = *reinterpret_cast<const float4*>(&g_proj[(size_t)gt * NPROJ + 512 + n * 64 + iv]);
                k2b[t * 36 + (iv >> 1) + 0] = bf2(a.x, a.y);
                k2b[t * 36 + (iv >> 1) + 1] = bf2(a.z, a.w);
            }
        }
        // load v2 tile transposed [c][t] (tf32)
        {
            const int c = tid & 63;
            const int tg4 = (tid >> 6) * 4;
#pragma unroll
            for (int it = 0; it < 4; it++) {
                int t4 = it * 16 + tg4;
                float4 c4;
                float* cf = &c4.x;
#pragma unroll
                for (int k = 0; k < 4; k++) {
                    int gt = t0 + t4 + k;
                    float v = (gt < P) ? g_proj[(size_t)gt * NPROJ + 2048 + n * 64 + c] : 0.f;
                    cf[k] = f2tf_f(v);
                }
                *reinterpret_cast<float4*>(&v2T[c * 68 + t4]) = c4;
            }
        }
        __syncthreads();
        // ---- S^T mma (bf16 k16): D[t][p] = sum_j k2[t][j] * B[p][j] ----
        {
            float sfr[2][4][4] = {};
#pragma unroll
            for (int k = 0; k < 4; k++) {
                const int j8 = k * 8;   // uint32 offset = 16 bf16 per step
                uint32_t afr[2][4], bfr[4][2];
#pragma unroll
                for (int mt = 0; mt < 2; mt++) {
                    int tb = s_t0w + mt * 16;
                    afr[mt][0] = k2b[(tb + gid) * 36 + j8 + tidg];
                    afr[mt][1] = k2b[(tb + gid + 8) * 36 + j8 + tidg];
                    afr[mt][2] = k2b[(tb + gid) * 36 + j8 + tidg + 4];
                    afr[mt][3] = k2b[(tb + gid + 8) * 36 + j8 + tidg + 4];
                }
#pragma unroll
                for (int nt = 0; nt < 4; nt++) {
                    int pb = s_p0w + nt * 8 + gid;
                    bfr[nt][0] = BPb[pb * 36 + j8 + tidg];
                    bfr[nt][1] = BPb[pb * 36 + j8 + tidg + 4];
                }
#pragma unroll
                for (int mt = 0; mt < 2; mt++)
#pragma unroll
                    for (int nt = 0; nt < 4; nt++)
                        mma16bf(sfr[mt][nt], afr[mt], bfr[nt]);
            }
            // exp + mask + store ET[p][t] (tf32)
#pragma unroll
            for (int mt = 0; mt < 2; mt++)
#pragma unroll
                for (int nt = 0; nt < 4; nt++)
#pragma unroll
                    for (int r = 0; r < 4; r++) {
                        int t_loc = s_t0w + mt * 16 + gid + ((r >> 1) << 3);
                        int p_loc = s_p0w + nt * 8 + 2 * tidg + (r & 1);
                        int gt = t0 + t_loc;
                        int gp = p_base + p_loc;
                        float e = (gp < P && gt < P) ? __expf(sfr[mt][nt][r] * 0.015625f) : 0.f;
                        lsum += e;
                        ET[p_loc * 68 + t_loc] = f2tf_f(e);
                    }
        }
        __syncthreads();
        // ---- R mma (tf32): R[p][c] += sum_t E[p][t] * v2[t][c] ----
        {
#pragma unroll
            for (int k = 0; k < 8; k++) {
                const int t8 = k * 8;
                uint32_t afr[2][4], bfr[4][2];
#pragma unroll
                for (int mt = 0; mt < 2; mt++) {
                    int pb = r_p0 + mt * 16;
                    afr[mt][0] = __float_as_uint(ET[(pb + gid) * 68 + t8 + tidg]);
                    afr[mt][1] = __float_as_uint(ET[(pb + gid + 8) * 68 + t8 + tidg]);
                    afr[mt][2] = __float_as_uint(ET[(pb + gid) * 68 + t8 + tidg + 4]);
                    afr[mt][3] = __float_as_uint(ET[(pb + gid + 8) * 68 + t8 + tidg + 4]);
                }
#pragma unroll
                for (int nt = 0; nt < 4; nt++) {
                    int cb = r_c0 + nt * 8 + gid;
                    bfr[nt][0] = __float_as_uint(v2T[cb * 68 + t8 + tidg]);
                    bfr[nt][1] = __float_as_uint(v2T[cb * 68 + t8 + tidg + 4]);
                }
#pragma unroll
                for (int mt = 0; mt < 2; mt++)
#pragma unroll
                    for (int nt = 0; nt < 4; nt++)
                        mma8(rfr[mt][nt], afr[mt], bfr[nt]);
            }
        }
        __syncthreads();
    }

    // ---- stage RT[c][p] (stride 130) into Cg; load v1 rows into U ----
    {
        float* RT = Cg;
#pragma unroll
        for (int mt = 0; mt < 2; mt++)
#pragma unroll
            for (int nt = 0; nt < 4; nt++)
#pragma unroll
                for (int r = 0; r < 4; r++) {
                    int p = r_p0 + mt * 16 + gid + ((r >> 1) << 3);
                    int c = r_c0 + nt * 8 + 2 * tidg + (r & 1);
                    RT[c * 130 + p] = rfr[mt][nt][r];
                }
    }
    {
        float* v1s = U;   // [128][64]
        const int rr = tid >> 4;
        const int iv = (tid & 15) * 4;
#pragma unroll
        for (int pass = 0; pass < NI * 2; pass++) {
            int lp = pass * 16 + rr;
            if (lp < p_count) {
                float4 v = *reinterpret_cast<const float4*>(
                    &g_proj[(size_t)(p_base + lp) * NPROJ + 1536 + n * 64 + iv]);
                *reinterpret_cast<float4*>(&v1s[lp * 64 + iv]) = v;
            }
        }
    }
    // lsum reduce
#pragma unroll
    for (int off = 16; off > 0; off >>= 1)
        lsum += __shfl_xor_sync(0xffffffffu, lsum, off);
    if (pl == 0) red[wid] = lsum;
    __syncthreads();
    if (tid == 0) {
        float total = 0.f;
#pragma unroll
        for (int w = 0; w < 8; w++) total += red[w];
        g_l[ph * (NH * T_SEQ) + n * T_SEQ + q] = total;
    }

    // ---- phase 3 (FFMA2 fp32): G[a,c] = sum_{lp<p_count} v1[lp,a] * RT[c,lp] ----
    {
        const float* v1s = U;
        const float* RT = Cg;
        const int a0 = (tid & 15) * 4;
        const int c0 = (tid >> 4) * 4;
        unsigned long long acc2[2][4] = {};
#pragma unroll 4
        for (int p = 0; p < p_count; p++) {
            ulonglong2 av2 = *reinterpret_cast<const ulonglong2*>(&v1s[p * 64 + a0]);
#pragma unroll
            for (int k = 0; k < 4; k++) {
                unsigned long long r2 = splat2(RT[(c0 + k) * 130 + p]);
                acc2[0][k] = fma2(av2.x, r2, acc2[0][k]);
                acc2[1][k] = fma2(av2.y, r2, acc2[1][k]);
            }
        }
        float* Gout = (ph ? g_Gb : g_Ga) + (size_t)(n * T_SEQ + q) * 4096;
#pragma unroll
        for (int h = 0; h < 2; h++) {
            float2 v0 = unpack2(acc2[h][0]);
            float2 v1 = unpack2(acc2[h][1]);
            float2 v2 = unpack2(acc2[h][2]);
            float2 v3 = unpack2(acc2[h][3]);
            float4 lo = make_float4(v0.x, v1.x, v2.x, v3.x);
            float4 hi = make_float4(v0.y, v1.y, v2.y, v3.y);
            *reinterpret_cast<float4*>(&Gout[(a0 + 2 * h + 0) * 64 + c0]) = lo;
            *reinterpret_cast<float4*>(&Gout[(a0 + 2 * h + 1) * 64 + c0]) = hi;
        }
    }
}

__global__ __launch_bounds__(256, 2) void attn_kernel() {
    extern __shared__ float sm[];
    const int bid = blockIdx.x;
    const int q = 255 - (bid >> 4);
    const int n = (bid >> 1) & 7;
    const int ph = bid & 1;
    const int P = q + 1;
    const int p_count = P - (ph << 7);
    if (p_count <= 0) return;
    const int ni = (min(p_count, 128) + 31) >> 5;
    switch (ni) {
        case 1: attn_body<1>(sm, n, q, ph, threadIdx.x); break;
        case 2: attn_body<2>(sm, n, q, ph, threadIdx.x); break;
        case 3: attn_body<3>(sm, n, q, ph, threadIdx.x); break;
        default: attn_body<4>(sm, n, q, ph, threadIdx.x); break;
    }
}

// ---------------- K4: z_raw += (Ga+Gb) @ W_Vq (K-split x8, atomics) ----------------
__global__ __launch_bounds__(256) void out_v_kernel(const float* __restrict__ Wvq) {
    __shared__ float AsT[32 * 68];
    __shared__ float Bs[32 * 68];
    const int n = blockIdx.y;
    const int bq = blockIdx.x * 64;
    const int ks = blockIdx.z;
    const int tid = threadIdx.x;
    const bool two = (bq >= 128);
    const int arow = tid >> 3, acol = (tid & 7) * 4;
    const int brow = tid >> 4, bcol = (tid & 15) * 4;
    const int q0 = (tid & 15) * 4, e0 = (tid >> 4) * 4;
    unsigned long long acc2[4][2] = {};
    for (int k0 = ks * 512; k0 < ks * 512 + 512; k0 += 32) {
#pragma unroll
        for (int rr = 0; rr < 2; rr++) {
            int r = arow + rr * 32;
            size_t idx = (size_t)(n * T_SEQ + bq + r) * 4096 + k0 + acol;
            float4 v = *reinterpret_cast<const float4*>(&g_Ga[idx]);
            if (two) {
                float4 w = *reinterpret_cast<const float4*>(&g_Gb[idx]);
                v.x += w.x; v.y += w.y; v.z += w.z; v.w += w.w;
            }
            AsT[(acol + 0) * 68 + r] = v.x; AsT[(acol + 1) * 68 + r] = v.y;
            AsT[(acol + 2) * 68 + r] = v.z; AsT[(acol + 3) * 68 + r] = v.w;
        }
#pragma unroll
        for (int rr = 0; rr < 2; rr++) {
            float4 v = *reinterpret_cast<const float4*>(
                &Wvq[(size_t)n * 262144 + (size_t)(k0 + brow + rr * 16) * 64 + bcol]);
            *reinterpret_cast<float4*>(&Bs[(brow + rr * 16) * 68 + bcol]) = v;
        }
        __syncthreads();
#pragma unroll
        for (int kk = 0; kk < 32; kk++) {
            float4 a = *reinterpret_cast<const float4*>(&AsT[kk * 68 + q0]);
            ulonglong2 b2 = *reinterpret_cast<const ulonglong2*>(&Bs[kk * 68 + e0]);
            unsigned long long as[4] = {splat2(a.x), splat2(a.y), splat2(a.z), splat2(a.w)};
#pragma unroll
            for (int i = 0; i < 4; i++) {
                acc2[i][0] = fma2(as[i], b2.x, acc2[i][0]);
                acc2[i][1] = fma2(as[i], b2.y, acc2[i][1]);
            }
        }
        __syncthreads();
    }
#pragma unroll
    for (int i = 0; i < 4; i++) {
        float2 p0 = unpack2(acc2[i][0]);
        float2 p1 = unpack2(acc2[i][1]);
        float* zp = &g_z[(size_t)(bq + q0 + i) * DMODEL + n * 64 + e0];
        atomicAdd(zp + 0, p0.x);
        atomicAdd(zp + 1, p0.y);
        atomicAdd(zp + 2, p1.x);
        atomicAdd(zp + 3, p1.y);
    }
}

// ---------------- K5: out = (z_raw * 1/(la+lb)) @ W_out + b_out ----------------
__global__ __launch_bounds__(256) void gemm_out_kernel(
    const float* __restrict__ Wout, const float* __restrict__ bout, float* __restrict__ C) {
    __shared__ float AsT[32 * 68];
    __shared__ float Bs[32 * 68];
    const int tid = threadIdx.x;
    const int bm = blockIdx.y * 64;
    const int bn = blockIdx.x * 64;
    const int r0 = (tid & 15) * 4;
    const int c0 = (tid >> 4) * 4;
    const int arow = tid >> 3, acol = (tid & 7) * 4;
    const int brow = tid >> 4, bcol = (tid & 15) * 4;
    unsigned long long acc2[4][2] = {};
    for (int k0 = 0; k0 < DMODEL; k0 += 32) {
#pragma unroll
        for (int rr = 0; rr < 2; rr++) {
            int r = bm + arow + rr * 32;
            int gk = k0 + acol;
            int li = (gk >> 6) * T_SEQ + r;
            float invl = 1.f / (g_l[li] + g_l[NH * T_SEQ + li]);
            float4 v = *reinterpret_cast<const float4*>(&g_z[(size_t)r * DMODEL + gk]);
            AsT[(acol + 0) * 68 + arow + rr * 32] = v.x * invl;
            AsT[(acol + 1) * 68 + arow + rr * 32] = v.y * invl;
            AsT[(acol + 2) * 68 + arow + rr * 32] = v.z * invl;
            AsT[(acol + 3) * 68 + arow + rr * 32] = v.w * invl;
        }
#pragma unroll
        for (int rr = 0; rr < 2; rr++) {
            float4 v = *reinterpret_cast<const float4*>(&Wout[(size_t)(k0 + brow + rr * 16) * DMODEL + bn + bcol]);
            *reinterpret_cast<float4*>(&Bs[(brow + rr * 16) * 68 + bcol]) = v;
        }
        __syncthreads();
#pragma unroll
        for (int kk = 0; kk < 32; kk++) {
            float4 a = *reinterpret_cast<const float4*>(&AsT[kk * 68 + r0]);
            ulonglong2 b2 = *reinterpret_cast<const ulonglong2*>(&Bs[kk * 68 + c0]);
            unsigned long long as[4] = {splat2(a.x), splat2(a.y), splat2(a.z), splat2(a.w)};
#pragma unroll
            for (int i = 0; i < 4; i++) {
                acc2[i][0] = fma2(as[i], b2.x, acc2[i][0]);
                acc2[i][1] = fma2(as[i], b2.y, acc2[i][1]);
            }
        }
        __syncthreads();
    }
    float4 bb = *reinterpret_cast<const float4*>(&bout[bn + c0]);
#pragma unroll
    for (int i = 0; i < 4; i++) {
        float2 p0 = unpack2(acc2[i][0]);
        float2 p1 = unpack2(acc2[i][1]);
        float4 o = make_float4(p0.x + bb.x, p0.y + bb.y, p1.x + bb.z, p1.y + bb.w);
        *reinterpret_cast<float4*>(&C[(size_t)(bm + r0 + i) * DMODEL + bn + c0]) = o;
    }
}

// ---------------- launch ----------------
extern "C" void kernel_launch(void* const* d_in, const int* in_sizes, int n_in,
                              void* d_out, int out_size) {
    const float* x       = (const float*)d_in[0];
    const float* Wkkqvv  = (const float*)d_in[1];
    const float* bkkqvv  = (const float*)d_in[2];
    const float* WKq     = (const float*)d_in[3];
    const float* WVq     = (const float*)d_in[4];
    const float* Wout    = (const float*)d_in[5];
    const float* bout    = (const float*)d_in[6];
    float* out = (float*)d_out;

    float* proj_ptr = nullptr;
    cudaGetSymbolAddress((void**)&proj_ptr, g_proj);

    cudaFuncSetAttribute(attn_kernel, cudaFuncAttributeMaxDynamicSharedMemorySize, ATTN_SMEM_BYTES);

    zero_kernel<<<(NZERO + 255) / 256, 256>>>();
    gemm_nn_bias_kernel<<<dim3(NPROJ / 64, T_SEQ / 64), 256>>>(x, Wkkqvv, bkkqvv, proj_ptr,
                                                               T_SEQ, NPROJ, DMODEL);
    compute_M_kernel<<<dim3(64, 4, NH), 256>>>(WKq);
    attn_kernel<<<NH * T_SEQ * 2, 256, ATTN_SMEM_BYTES>>>();
    out_v_kernel<<<dim3(4, NH, 8), 256>>>(WVq);
    gemm_out_kernel<<<dim3(DMODEL / 64, T_SEQ / 64), 256>>>(Wout, bout, out);
}

// round 12
// speedup vs baseline: 1.9843x; 1.0870x over previous
#include <cuda_runtime.h>
#include <cstdint>

#define T_SEQ 256
#define NH 8
#define DHD 64
#define DMODEL 512
#define NPROJ 2560   // 5 * 512

// ---------------- packed fp32x2 helpers (Blackwell FFMA2) ----------------
__device__ __forceinline__ unsigned long long splat2(float x) {
    unsigned long long r;
    asm("mov.b64 %0, {%1, %1};" : "=l"(r) : "f"(x));
    return r;
}
__device__ __forceinline__ unsigned long long fma2(unsigned long long a, unsigned long long b,
                                                   unsigned long long c) {
    unsigned long long d;
    asm("fma.rn.f32x2 %0, %1, %2, %3;" : "=l"(d) : "l"(a), "l"(b), "l"(c));
    return d;
}
__device__ __forceinline__ float2 unpack2(unsigned long long v) {
    float2 f;
    asm("mov.b64 {%0, %1}, %2;" : "=f"(f.x), "=f"(f.y) : "l"(v));
    return f;
}

// ---------------- bf16 helpers ----------------
// pack two fp32 -> bf16x2 (lo = first arg, hi = second arg)
__device__ __forceinline__ uint32_t bf2(float lo, float hi) {
    uint32_t r;
    asm("cvt.rn.bf16x2.f32 %0, %1, %2;" : "=r"(r) : "f"(hi), "f"(lo));
    return r;
}
__device__ __forceinline__ void mma16bf(float d[4], const uint32_t a[4], const uint32_t b[2]) {
    asm("mma.sync.aligned.m16n8k16.row.col.f32.bf16.bf16.f32 "
        "{%0,%1,%2,%3}, {%4,%5,%6,%7}, {%8,%9}, {%0,%1,%2,%3};"
        : "+f"(d[0]), "+f"(d[1]), "+f"(d[2]), "+f"(d[3])
        : "r"(a[0]), "r"(a[1]), "r"(a[2]), "r"(a[3]), "r"(b[0]), "r"(b[1]));
}

// ---------------- scratch ----------------
__device__ float g_proj[T_SEQ * NPROJ];            // [t, 2560]
__device__ float g_M[NH * T_SEQ * DHD * DHD];      // [n, q, k, j]
__device__ float g_Ga[NH * T_SEQ * DHD * DHD];     // [n, q, a, c] p-half 0
__device__ float g_Gb[NH * T_SEQ * DHD * DHD];     // [n, q, a, c] p-half 1
__device__ float g_l[2 * NH * T_SEQ];              // softmax denominator partials
__device__ float g_z[T_SEQ * DMODEL];              // [q, n*64+e]

// ---------------- K0: zero z + l ----------------
#define NZERO (T_SEQ * DMODEL + 2 * NH * T_SEQ)
__global__ __launch_bounds__(256) void zero_kernel() {
    int i = blockIdx.x * 256 + threadIdx.x;
    if (i < T_SEQ * DMODEL) g_z[i] = 0.f;
    else g_l[i - T_SEQ * DMODEL] = 0.f;
}

// ---------------- K1: C[M,N] = A[M,K] @ B[K,N] + bias ----------------
__global__ __launch_bounds__(256) void gemm_nn_bias_kernel(
    const float* __restrict__ A, const float* __restrict__ B,
    const float* __restrict__ bias, float* __restrict__ C,
    int M, int N, int K) {
    __shared__ float AsT[32 * 68];
    __shared__ float Bs[32 * 68];
    const int tid = threadIdx.x;
    const int bm = blockIdx.y * 64;
    const int bn = blockIdx.x * 64;
    const int r0 = (tid & 15) * 4;
    const int c0 = (tid >> 4) * 4;
    const int arow = tid >> 3;
    const int acol = (tid & 7) * 4;
    const int brow = tid >> 4;
    const int bcol = (tid & 15) * 4;
    unsigned long long acc2[4][2] = {};
    for (int k0 = 0; k0 < K; k0 += 32) {
#pragma unroll
        for (int rr = 0; rr < 2; rr++) {
            int r = arow + rr * 32;
            float4 v = *reinterpret_cast<const float4*>(&A[(size_t)(bm + r) * K + k0 + acol]);
            AsT[(acol + 0) * 68 + r] = v.x; AsT[(acol + 1) * 68 + r] = v.y;
            AsT[(acol + 2) * 68 + r] = v.z; AsT[(acol + 3) * 68 + r] = v.w;
        }
#pragma unroll
        for (int rr = 0; rr < 2; rr++) {
            float4 v = *reinterpret_cast<const float4*>(&B[(size_t)(k0 + brow + rr * 16) * N + bn + bcol]);
            *reinterpret_cast<float4*>(&Bs[(brow + rr * 16) * 68 + bcol]) = v;
        }
        __syncthreads();
#pragma unroll
        for (int kk = 0; kk < 32; kk++) {
            float4 a = *reinterpret_cast<const float4*>(&AsT[kk * 68 + r0]);
            ulonglong2 b2 = *reinterpret_cast<const ulonglong2*>(&Bs[kk * 68 + c0]);
            unsigned long long as[4] = {splat2(a.x), splat2(a.y), splat2(a.z), splat2(a.w)};
#pragma unroll
            for (int i = 0; i < 4; i++) {
                acc2[i][0] = fma2(as[i], b2.x, acc2[i][0]);
                acc2[i][1] = fma2(as[i], b2.y, acc2[i][1]);
            }
        }
        __syncthreads();
    }
    float4 bb = *reinterpret_cast<const float4*>(&bias[bn + c0]);
#pragma unroll
    for (int i = 0; i < 4; i++) {
        float2 p0 = unpack2(acc2[i][0]);
        float2 p1 = unpack2(acc2[i][1]);
        float4 o = make_float4(p0.x + bb.x, p0.y + bb.y, p1.x + bb.z, p1.y + bb.w);
        *reinterpret_cast<float4*>(&C[(size_t)(bm + r0 + i) * N + bn + c0]) = o;
    }
}

// ---------------- K2: M[n,q,kj] = sum_i qproj[q,i] * Wkq[n,kj,i] ----------------
__global__ __launch_bounds__(256) void compute_M_kernel(const float* __restrict__ Wkq) {
    __shared__ float AsT[64 * 68];
    __shared__ float BsT[64 * 68];
    const int n = blockIdx.z;
    const int bq = blockIdx.y * 64;
    const int bkj = blockIdx.x * 64;
    const int tid = threadIdx.x;
    const int row = tid >> 4;
    const int col = (tid & 15) * 4;
#pragma unroll
    for (int rr = 0; rr < 4; rr++) {
        int r = row + rr * 16;
        float4 va = *reinterpret_cast<const float4*>(&g_proj[(size_t)(bq + r) * NPROJ + 1024 + n * 64 + col]);
        AsT[(col + 0) * 68 + r] = va.x; AsT[(col + 1) * 68 + r] = va.y;
        AsT[(col + 2) * 68 + r] = va.z; AsT[(col + 3) * 68 + r] = va.w;
        float4 vb = *reinterpret_cast<const float4*>(&Wkq[(size_t)n * 262144 + (size_t)(bkj + r) * 64 + col]);
        BsT[(col + 0) * 68 + r] = vb.x; BsT[(col + 1) * 68 + r] = vb.y;
        BsT[(col + 2) * 68 + r] = vb.z; BsT[(col + 3) * 68 + r] = vb.w;
    }
    __syncthreads();
    const int q0 = (tid & 15) * 4;
    const int kj0 = (tid >> 4) * 4;
    unsigned long long acc2[4][2] = {};
#pragma unroll 8
    for (int i = 0; i < 64; i++) {
        float4 a = *reinterpret_cast<const float4*>(&AsT[i * 68 + q0]);
        ulonglong2 b2 = *reinterpret_cast<const ulonglong2*>(&BsT[i * 68 + kj0]);
        unsigned long long as[4] = {splat2(a.x), splat2(a.y), splat2(a.z), splat2(a.w)};
#pragma unroll
        for (int ii = 0; ii < 4; ii++) {
            acc2[ii][0] = fma2(as[ii], b2.x, acc2[ii][0]);
            acc2[ii][1] = fma2(as[ii], b2.y, acc2[ii][1]);
        }
    }
#pragma unroll
    for (int ii = 0; ii < 4; ii++) {
        float2 p0 = unpack2(acc2[ii][0]);
        float2 p1 = unpack2(acc2[ii][1]);
        float4 o = make_float4(p0.x, p0.y, p1.x, p1.y);
        *reinterpret_cast<float4*>(&g_M[(size_t)(n * T_SEQ + bq + q0 + ii) * 4096 + bkj + kj0]) = o;
    }
}

// ---------------- K3: attention, 2 CTAs per (n,q) split by p-half ----------------
// smem regions (floats):
// U  [0, 8704): ph1 k1T s129 (8256); ph2 k2b u32[64*36] + v2b u32[64*36] (4608 fl); ph3 v1s [128][64]
// BP [8704, 17408): BPb u32 [128*36] = 4608 fl
// Cg [17408, 26112): ph1 M s64 (4096); ph3 RT [c][p] s130 (8320)
// red [26112, 26440): red[8] + spart[256] + stot[64]
#define OFF_U   0
#define OFF_BP  8704
#define OFF_C   17408
#define OFF_RED 26112
#define ATTN_SMEM_FLOATS 26440
#define ATTN_SMEM_BYTES (ATTN_SMEM_FLOATS * 4)

// NI = ceil(p_count/32) in 1..4 (phases 1/3 only)
template <int NI>
__device__ __forceinline__ void attn_body(float* sm, int n, int q, int ph, int tid) {
    float* U   = sm + OFF_U;
    uint32_t* BPb = reinterpret_cast<uint32_t*>(sm + OFF_BP);   // [p][j/2] stride 36
    float* Cg  = sm + OFF_C;
    float* red = sm + OFF_RED;

    const int P = q + 1;
    const int p_base = ph << 7;
    const int p_count = min(P - p_base, 128);
    const int pl = tid & 31;
    const int wid = tid >> 5;
    const int c8 = wid * 8;
    const int gid = pl >> 2;          // mma group id 0..7
    const int tidg = pl & 3;          // thread-in-group 0..3

    // ---- load M into Cg region (stride 64) ----
    {
        const float* Mg = g_M + (size_t)(n * T_SEQ + q) * 4096;
        float* Ms = Cg;
#pragma unroll
        for (int r = 0; r < 4; r++) {
            int off = (tid + r * 256) * 4;
            *reinterpret_cast<float4*>(&Ms[off]) = *reinterpret_cast<const float4*>(&Mg[off]);
        }
    }
    // ---- load k1 transposed [k][local p] (stride 129) ----
    {
        float* k1T = U;
        const int rr = tid >> 4;
        const int iv = (tid & 15) * 4;
#pragma unroll
        for (int pass = 0; pass < NI * 2; pass++) {
            int lp = pass * 16 + rr;
            int gp = p_base + lp;
            float4 v = make_float4(0.f, 0.f, 0.f, 0.f);
            if (lp < p_count) v = *reinterpret_cast<const float4*>(&g_proj[(size_t)gp * NPROJ + n * 64 + iv]);
            k1T[(iv + 0) * 129 + lp] = v.x;
            k1T[(iv + 1) * 129 + lp] = v.y;
            k1T[(iv + 2) * 129 + lp] = v.z;
            k1T[(iv + 3) * 129 + lp] = v.w;
        }
    }
    __syncthreads();

    // ---- phase 1 (FFMA2): B[p,j] = sum_k k1[p,k]*M[k,j]; store BPb[p][j/2] bf16x2 ----
    {
        const float* k1T = U;
        const float* Ms = Cg;
        unsigned long long acc2[NI][4] = {};
#pragma unroll 4
        for (int k = 0; k < 64; k++) {
            unsigned long long a2[NI];
#pragma unroll
            for (int i = 0; i < NI; i++) a2[i] = splat2(k1T[k * 129 + pl + 32 * i]);
            const ulonglong2* bp = reinterpret_cast<const ulonglong2*>(&Ms[k * 64 + c8]);
            ulonglong2 b01 = bp[0], b23 = bp[1];
#pragma unroll
            for (int i = 0; i < NI; i++) {
                acc2[i][0] = fma2(a2[i], b01.x, acc2[i][0]);
                acc2[i][1] = fma2(a2[i], b01.y, acc2[i][1]);
                acc2[i][2] = fma2(a2[i], b23.x, acc2[i][2]);
                acc2[i][3] = fma2(a2[i], b23.y, acc2[i][3]);
            }
        }
        __syncthreads();   // M (in Cg) consumed
#pragma unroll
        for (int m = 0; m < 4; m++)
#pragma unroll
            for (int i = 0; i < NI; i++) {
                float2 v = unpack2(acc2[i][m]);
                int p = pl + 32 * i;
                BPb[p * 36 + (c8 >> 1) + m] = bf2(v.x, v.y);
            }
        // rows >= 32*NI left as-is: garbage there yields masked (d=-1) rows, never read
    }
    __syncthreads();

    // ---- phase 2: S[p][t] bf16 mma; delta trick; R bf16 mma with register A-frags ----
    float rfr[8][4] = {};             // R correction frags: 16p x 64c per warp
    float lsum = 0.f;
    float stot_loc = 0.f;             // per-thread partial of column sums of v2
    uint32_t* k2b = reinterpret_cast<uint32_t*>(U);          // [t][t-pairs] stride 36
    uint32_t* v2b = reinterpret_cast<uint32_t*>(U) + 2304;   // [c][t-pairs] stride 36
    const int p0w = wid * 16;
    const int cld = tid & 63;         // loader c
    const int tq  = tid >> 6;         // loader t-quarter
    for (int t0 = 0; t0 < P; t0 += 64) {
        // load k2 tile [t][j] -> bf16 pairs
        {
            const int rr = tid >> 4;
            const int iv = (tid & 15) * 4;
#pragma unroll
            for (int pass = 0; pass < 4; pass++) {
                int t = pass * 16 + rr;
                int gt = t0 + t;
                float4 a = make_float4(0.f, 0.f, 0.f, 0.f);
                if (gt < P) a = *reinterpret_cast<const float4*>(&g_proj[(size_t)gt * NPROJ + 512 + n * 64 + iv]);
                k2b[t * 36 + (iv >> 1) + 0] = bf2(a.x, a.y);
                k2b[t * 36 + (iv >> 1) + 1] = bf2(a.z, a.w);
            }
        }
        // load v2 transposed [c][t] bf16 pairs + accumulate fp32 column sums
        {
#pragma unroll
            for (int it = 0; it < 4; it++) {
                int t4 = tq * 16 + it * 4;
                float v[4];
#pragma unroll
                for (int k = 0; k < 4; k++) {
                    int gt = t0 + t4 + k;
                    v[k] = (gt < P) ? g_proj[(size_t)gt * NPROJ + 2048 + n * 64 + cld] : 0.f;
                    stot_loc += v[k];
                }
                v2b[cld * 36 + (t4 >> 1) + 0] = bf2(v[0], v[1]);
                v2b[cld * 36 + (t4 >> 1) + 1] = bf2(v[2], v[3]);
            }
        }
        __syncthreads();
        // ---- S mma: S[p][t], warp tile 16p x 64t ----
        float sfr[8][4] = {};
#pragma unroll
        for (int kk = 0; kk < 4; kk++) {
            const int j8 = kk * 8;
            uint32_t afr[4];
            afr[0] = BPb[(p0w + gid) * 36 + j8 + tidg];
            afr[1] = BPb[(p0w + gid + 8) * 36 + j8 + tidg];
            afr[2] = BPb[(p0w + gid) * 36 + j8 + tidg + 4];
            afr[3] = BPb[(p0w + gid + 8) * 36 + j8 + tidg + 4];
#pragma unroll
            for (int nt = 0; nt < 8; nt++) {
                uint32_t bfr[2];
                bfr[0] = k2b[(nt * 8 + gid) * 36 + j8 + tidg];
                bfr[1] = k2b[(nt * 8 + gid) * 36 + j8 + tidg + 4];
                mma16bf(sfr[nt], afr, bfr);
            }
        }
        // ---- exp + mask; d = e - 1 kept in sfr (registers) ----
#pragma unroll
        for (int nt = 0; nt < 8; nt++)
#pragma unroll
            for (int r = 0; r < 4; r++) {
                int p_loc = p0w + gid + ((r >> 1) << 3);
                int t_loc = nt * 8 + 2 * tidg + (r & 1);
                int gp = p_base + p_loc;
                int gt = t0 + t_loc;
                float e = (gp < P && gt < P) ? __expf(sfr[nt][r] * 0.015625f) : 0.f;
                lsum += e;
                sfr[nt][r] = e - 1.f;
            }
        // ---- R correction mma: Rcorr[p][c] += sum_t d[p][t] * v2[t][c] ----
#pragma unroll
        for (int kk = 0; kk < 4; kk++) {
            uint32_t afr[4];
            afr[0] = bf2(sfr[2 * kk][0], sfr[2 * kk][1]);         // row gid,   k-lo
            afr[1] = bf2(sfr[2 * kk][2], sfr[2 * kk][3]);         // row gid+8, k-lo
            afr[2] = bf2(sfr[2 * kk + 1][0], sfr[2 * kk + 1][1]); // row gid,   k-hi
            afr[3] = bf2(sfr[2 * kk + 1][2], sfr[2 * kk + 1][3]); // row gid+8, k-hi
            const int t8 = kk * 8;
#pragma unroll
            for (int nt = 0; nt < 8; nt++) {
                uint32_t bfr[2];
                bfr[0] = v2b[(nt * 8 + gid) * 36 + t8 + tidg];
                bfr[1] = v2b[(nt * 8 + gid) * 36 + t8 + tidg + 4];
                mma16bf(rfr[nt], afr, bfr);
            }
        }
        __syncthreads();
    }

    // ---- reductions + load v1 ----
    {
        float* spart = red + 8;           // [4][64]
        spart[tq * 64 + cld] = stot_loc;
#pragma unroll
        for (int off = 16; off > 0; off >>= 1)
            lsum += __shfl_xor_sync(0xffffffffu, lsum, off);
        if (pl == 0) red[wid] = lsum;
    }
    {   // v1 into U (k2b/v2b fully consumed before final loop sync)
        float* v1s = U;   // [128][64]
        const int rr = tid >> 4;
        const int iv = (tid & 15) * 4;
#pragma unroll
        for (int pass = 0; pass < NI * 2; pass++) {
            int lp = pass * 16 + rr;
            if (lp < p_count) {
                float4 v = *reinterpret_cast<const float4*>(
                    &g_proj[(size_t)(p_base + lp) * NPROJ + 1536 + n * 64 + iv]);
                *reinterpret_cast<float4*>(&v1s[lp * 64 + iv]) = v;
            }
        }
    }
    __syncthreads();
    {
        float* spart = red + 8;
        float* stotc = red + 8 + 256;     // [64]
        if (tid < 64)
            stotc[tid] = spart[tid] + spart[64 + tid] + spart[128 + tid] + spart[192 + tid];
        if (tid == 0) {
            float total = 0.f;
#pragma unroll
            for (int w = 0; w < 8; w++) total += red[w];
            g_l[ph * (NH * T_SEQ) + n * T_SEQ + q] = total;
        }
    }
    __syncthreads();
    // ---- stage RT[c][p] = Rcorr + Stot[c] (stride 130) into Cg ----
    {
        float* RT = Cg;
        const float* stotc = red + 8 + 256;
#pragma unroll
        for (int nt = 0; nt < 8; nt++)
#pragma unroll
            for (int r = 0; r < 4; r++) {
                int p = p0w + gid + ((r >> 1) << 3);
                int c = nt * 8 + 2 * tidg + (r & 1);
                RT[c * 130 + p] = rfr[nt][r] + stotc[c];
            }
    }
    __syncthreads();

    // ---- phase 3 (FFMA2 fp32): G[a,c] = sum_{lp<p_count} v1[lp,a] * RT[c,lp] ----
    {
        const float* v1s = U;
        const float* RT = Cg;
        const int a0 = (tid & 15) * 4;
        const int c0 = (tid >> 4) * 4;
        unsigned long long acc2[2][4] = {};
#pragma unroll 4
        for (int p = 0; p < p_count; p++) {
            ulonglong2 av2 = *reinterpret_cast<const ulonglong2*>(&v1s[p * 64 + a0]);
#pragma unroll
            for (int k = 0; k < 4; k++) {
                unsigned long long r2 = splat2(RT[(c0 + k) * 130 + p]);
                acc2[0][k] = fma2(av2.x, r2, acc2[0][k]);
                acc2[1][k] = fma2(av2.y, r2, acc2[1][k]);
            }
        }
        float* Gout = (ph ? g_Gb : g_Ga) + (size_t)(n * T_SEQ + q) * 4096;
#pragma unroll
        for (int h = 0; h < 2; h++) {
            float2 v0 = unpack2(acc2[h][0]);
            float2 v1 = unpack2(acc2[h][1]);
            float2 v2 = unpack2(acc2[h][2]);
            float2 v3 = unpack2(acc2[h][3]);
            float4 lo = make_float4(v0.x, v1.x, v2.x, v3.x);
            float4 hi = make_float4(v0.y, v1.y, v2.y, v3.y);
            *reinterpret_cast<float4*>(&Gout[(a0 + 2 * h + 0) * 64 + c0]) = lo;
            *reinterpret_cast<float4*>(&Gout[(a0 + 2 * h + 1) * 64 + c0]) = hi;
        }
    }
}

__global__ __launch_bounds__(256, 2) void attn_kernel() {
    extern __shared__ float sm[];
    const int bid = blockIdx.x;
    const int q = 255 - (bid >> 4);
    const int n = (bid >> 1) & 7;
    const int ph = bid & 1;
    const int P = q + 1;
    const int p_count = P - (ph << 7);
    if (p_count <= 0) return;
    const int ni = (min(p_count, 128) + 31) >> 5;
    switch (ni) {
        case 1: attn_body<1>(sm, n, q, ph, threadIdx.x); break;
        case 2: attn_body<2>(sm, n, q, ph, threadIdx.x); break;
        case 3: attn_body<3>(sm, n, q, ph, threadIdx.x); break;
        default: attn_body<4>(sm, n, q, ph, threadIdx.x); break;
    }
}

// ---------------- K4: z_raw += (Ga+Gb) @ W_Vq (K-split x8, atomics) ----------------
__global__ __launch_bounds__(256) void out_v_kernel(const float* __restrict__ Wvq) {
    __shared__ float AsT[32 * 68];
    __shared__ float Bs[32 * 68];
    const int n = blockIdx.y;
    const int bq = blockIdx.x * 64;
    const int ks = blockIdx.z;
    const int tid = threadIdx.x;
    const bool two = (bq >= 128);
    const int arow = tid >> 3, acol = (tid & 7) * 4;
    const int brow = tid >> 4, bcol = (tid & 15) * 4;
    const int q0 = (tid & 15) * 4, e0 = (tid >> 4) * 4;
    unsigned long long acc2[4][2] = {};
    for (int k0 = ks * 512; k0 < ks * 512 + 512; k0 += 32) {
#pragma unroll
        for (int rr = 0; rr < 2; rr++) {
            int r = arow + rr * 32;
            size_t idx = (size_t)(n * T_SEQ + bq + r) * 4096 + k0 + acol;
            float4 v = *reinterpret_cast<const float4*>(&g_Ga[idx]);
            if (two) {
                float4 w = *reinterpret_cast<const float4*>(&g_Gb[idx]);
                v.x += w.x; v.y += w.y; v.z += w.z; v.w += w.w;
            }
            AsT[(acol + 0) * 68 + r] = v.x; AsT[(acol + 1) * 68 + r] = v.y;
            AsT[(acol + 2) * 68 + r] = v.z; AsT[(acol + 3) * 68 + r] = v.w;
        }
#pragma unroll
        for (int rr = 0; rr < 2; rr++) {
            float4 v = *reinterpret_cast<const float4*>(
                &Wvq[(size_t)n * 262144 + (size_t)(k0 + brow + rr * 16) * 64 + bcol]);
            *reinterpret_cast<float4*>(&Bs[(brow + rr * 16) * 68 + bcol]) = v;
        }
        __syncthreads();
#pragma unroll
        for (int kk = 0; kk < 32; kk++) {
            float4 a = *reinterpret_cast<const float4*>(&AsT[kk * 68 + q0]);
            ulonglong2 b2 = *reinterpret_cast<const ulonglong2*>(&Bs[kk * 68 + e0]);
            unsigned long long as[4] = {splat2(a.x), splat2(a.y), splat2(a.z), splat2(a.w)};
#pragma unroll
            for (int i = 0; i < 4; i++) {
                acc2[i][0] = fma2(as[i], b2.x, acc2[i][0]);
                acc2[i][1] = fma2(as[i], b2.y, acc2[i][1]);
            }
        }
        __syncthreads();
    }
#pragma unroll
    for (int i = 0; i < 4; i++) {
        float2 p0 = unpack2(acc2[i][0]);
        float2 p1 = unpack2(acc2[i][1]);
        float* zp = &g_z[(size_t)(bq + q0 + i) * DMODEL + n * 64 + e0];
        atomicAdd(zp + 0, p0.x);
        atomicAdd(zp + 1, p0.y);
        atomicAdd(zp + 2, p1.x);
        atomicAdd(zp + 3, p1.y);
    }
}

// ---------------- K5: out = (z_raw * 1/(la+lb)) @ W_out + b_out ----------------
__global__ __launch_bounds__(256) void gemm_out_kernel(
    const float* __restrict__ Wout, const float* __restrict__ bout, float* __restrict__ C) {
    __shared__ float AsT[32 * 68];
    __shared__ float Bs[32 * 68];
    const int tid = threadIdx.x;
    const int bm = blockIdx.y * 64;
    const int bn = blockIdx.x * 64;
    const int r0 = (tid & 15) * 4;
    const int c0 = (tid >> 4) * 4;
    const int arow = tid >> 3, acol = (tid & 7) * 4;
    const int brow = tid >> 4, bcol = (tid & 15) * 4;
    unsigned long long acc2[4][2] = {};
    for (int k0 = 0; k0 < DMODEL; k0 += 32) {
#pragma unroll
        for (int rr = 0; rr < 2; rr++) {
            int r = bm + arow + rr * 32;
            int gk = k0 + acol;
            int li = (gk >> 6) * T_SEQ + r;
            float invl = 1.f / (g_l[li] + g_l[NH * T_SEQ + li]);
            float4 v = *reinterpret_cast<const float4*>(&g_z[(size_t)r * DMODEL + gk]);
            AsT[(acol + 0) * 68 + arow + rr * 32] = v.x * invl;
            AsT[(acol + 1) * 68 + arow + rr * 32] = v.y * invl;
            AsT[(acol + 2) * 68 + arow + rr * 32] = v.z * invl;
            AsT[(acol + 3) * 68 + arow + rr * 32] = v.w * invl;
        }
#pragma unroll
        for (int rr = 0; rr < 2; rr++) {
            float4 v = *reinterpret_cast<const float4*>(&Wout[(size_t)(k0 + brow + rr * 16) * DMODEL + bn + bcol]);
            *reinterpret_cast<float4*>(&Bs[(brow + rr * 16) * 68 + bcol]) = v;
        }
        __syncthreads();
#pragma unroll
        for (int kk = 0; kk < 32; kk++) {
            float4 a = *reinterpret_cast<const float4*>(&AsT[kk * 68 + r0]);
            ulonglong2 b2 = *reinterpret_cast<const ulonglong2*>(&Bs[kk * 68 + c0]);
            unsigned long long as[4] = {splat2(a.x), splat2(a.y), splat2(a.z), splat2(a.w)};
#pragma unroll
            for (int i = 0; i < 4; i++) {
                acc2[i][0] = fma2(as[i], b2.x, acc2[i][0]);
                acc2[i][1] = fma2(as[i], b2.y, acc2[i][1]);
            }
        }
        __syncthreads();
    }
    float4 bb = *reinterpret_cast<const float4*>(&bout[bn + c0]);
#pragma unroll
    for (int i = 0; i < 4; i++) {
        float2 p0 = unpack2(acc2[i][0]);
        float2 p1 = unpack2(acc2[i][1]);
        float4 o = make_float4(p0.x + bb.x, p0.y + bb.y, p1.x + bb.z, p1.y + bb.w);
        *reinterpret_cast<float4*>(&C[(size_t)(bm + r0 + i) * DMODEL + bn + c0]) = o;
    }
}

// ---------------- launch ----------------
extern "C" void kernel_launch(void* const* d_in, const int* in_sizes, int n_in,
                              void* d_out, int out_size) {
    const float* x       = (const float*)d_in[0];
    const float* Wkkqvv  = (const float*)d_in[1];
    const float* bkkqvv  = (const float*)d_in[2];
    const float* WKq     = (const float*)d_in[3];
    const float* WVq     = (const float*)d_in[4];
    const float* Wout    = (const float*)d_in[5];
    const float* bout    = (const float*)d_in[6];
    float* out = (float*)d_out;

    float* proj_ptr = nullptr;
    cudaGetSymbolAddress((void**)&proj_ptr, g_proj);

    cudaFuncSetAttribute(attn_kernel, cudaFuncAttributeMaxDynamicSharedMemorySize, ATTN_SMEM_BYTES);

    zero_kernel<<<(NZERO + 255) / 256, 256>>>();
    gemm_nn_bias_kernel<<<dim3(NPROJ / 64, T_SEQ / 64), 256>>>(x, Wkkqvv, bkkqvv, proj_ptr,
                                                               T_SEQ, NPROJ, DMODEL);
    compute_M_kernel<<<dim3(64, 4, NH), 256>>>(WKq);
    attn_kernel<<<NH * T_SEQ * 2, 256, ATTN_SMEM_BYTES>>>();
    out_v_kernel<<<dim3(4, NH, 8), 256>>>(WVq);
    gemm_out_kernel<<<dim3(DMODEL / 64, T_SEQ / 64), 256>>>(Wout, bout, out);
}

// round 14
// speedup vs baseline: 2.5132x; 1.2665x over previous
#include <cuda_runtime.h>
#include <cstdint>

#define T_SEQ 256
#define NH 8
#define DHD 64
#define DMODEL 512
#define NPROJ 2560   // 5 * 512

// ---------------- packed fp32x2 helpers (Blackwell FFMA2) ----------------
__device__ __forceinline__ unsigned long long splat2(float x) {
    unsigned long long r;
    asm("mov.b64 %0, {%1, %1};" : "=l"(r) : "f"(x));
    return r;
}
__device__ __forceinline__ unsigned long long fma2(unsigned long long a, unsigned long long b,
                                                   unsigned long long c) {
    unsigned long long d;
    asm("fma.rn.f32x2 %0, %1, %2, %3;" : "=l"(d) : "l"(a), "l"(b), "l"(c));
    return d;
}
__device__ __forceinline__ float2 unpack2(unsigned long long v) {
    float2 f;
    asm("mov.b64 {%0, %1}, %2;" : "=f"(f.x), "=f"(f.y) : "l"(v));
    return f;
}

// ---------------- bf16 helpers ----------------
// pack two fp32 -> bf16x2 (lo = first arg, hi = second arg)
__device__ __forceinline__ uint32_t bf2(float lo, float hi) {
    uint32_t r;
    asm("cvt.rn.bf16x2.f32 %0, %1, %2;" : "=r"(r) : "f"(hi), "f"(lo));
    return r;
}
__device__ __forceinline__ uint16_t bf16lo(float x) {
    return (uint16_t)(bf2(x, 0.f) & 0xffffu);
}
__device__ __forceinline__ void mma16bf(float d[4], const uint32_t a[4], const uint32_t b[2]) {
    asm("mma.sync.aligned.m16n8k16.row.col.f32.bf16.bf16.f32 "
        "{%0,%1,%2,%3}, {%4,%5,%6,%7}, {%8,%9}, {%0,%1,%2,%3};"
        : "+f"(d[0]), "+f"(d[1]), "+f"(d[2]), "+f"(d[3])
        : "r"(a[0]), "r"(a[1]), "r"(a[2]), "r"(a[3]), "r"(b[0]), "r"(b[1]));
}

// ---------------- scratch ----------------
__device__ float g_proj[T_SEQ * NPROJ];            // [t, 2560]
__device__ float g_M[NH * T_SEQ * DHD * DHD];      // [n, q, k, j]
__device__ float g_Ga[NH * T_SEQ * DHD * DHD];     // [n, q, a, c] p-half 0
__device__ float g_Gb[NH * T_SEQ * DHD * DHD];     // [n, q, a, c] p-half 1
__device__ float g_l[2 * NH * T_SEQ];              // softmax denominator partials
__device__ float g_z[T_SEQ * DMODEL];              // [q, n*64+e]

// ---------------- K0: zero z + l ----------------
#define NZERO (T_SEQ * DMODEL + 2 * NH * T_SEQ)
__global__ __launch_bounds__(256) void zero_kernel() {
    int i = blockIdx.x * 256 + threadIdx.x;
    if (i < T_SEQ * DMODEL) g_z[i] = 0.f;
    else g_l[i - T_SEQ * DMODEL] = 0.f;
}

// ---------------- K1: C[M,N] = A[M,K] @ B[K,N] + bias ----------------
__global__ __launch_bounds__(256) void gemm_nn_bias_kernel(
    const float* __restrict__ A, const float* __restrict__ B,
    const float* __restrict__ bias, float* __restrict__ C,
    int M, int N, int K) {
    __shared__ float AsT[32 * 68];
    __shared__ float Bs[32 * 68];
    const int tid = threadIdx.x;
    const int bm = blockIdx.y * 64;
    const int bn = blockIdx.x * 64;
    const int r0 = (tid & 15) * 4;
    const int c0 = (tid >> 4) * 4;
    const int arow = tid >> 3;
    const int acol = (tid & 7) * 4;
    const int brow = tid >> 4;
    const int bcol = (tid & 15) * 4;
    unsigned long long acc2[4][2] = {};
    for (int k0 = 0; k0 < K; k0 += 32) {
#pragma unroll
        for (int rr = 0; rr < 2; rr++) {
            int r = arow + rr * 32;
            float4 v = *reinterpret_cast<const float4*>(&A[(size_t)(bm + r) * K + k0 + acol]);
            AsT[(acol + 0) * 68 + r] = v.x; AsT[(acol + 1) * 68 + r] = v.y;
            AsT[(acol + 2) * 68 + r] = v.z; AsT[(acol + 3) * 68 + r] = v.w;
        }
#pragma unroll
        for (int rr = 0; rr < 2; rr++) {
            float4 v = *reinterpret_cast<const float4*>(&B[(size_t)(k0 + brow + rr * 16) * N + bn + bcol]);
            *reinterpret_cast<float4*>(&Bs[(brow + rr * 16) * 68 + bcol]) = v;
        }
        __syncthreads();
#pragma unroll
        for (int kk = 0; kk < 32; kk++) {
            float4 a = *reinterpret_cast<const float4*>(&AsT[kk * 68 + r0]);
            ulonglong2 b2 = *reinterpret_cast<const ulonglong2*>(&Bs[kk * 68 + c0]);
            unsigned long long as[4] = {splat2(a.x), splat2(a.y), splat2(a.z), splat2(a.w)};
#pragma unroll
            for (int i = 0; i < 4; i++) {
                acc2[i][0] = fma2(as[i], b2.x, acc2[i][0]);
                acc2[i][1] = fma2(as[i], b2.y, acc2[i][1]);
            }
        }
        __syncthreads();
    }
    float4 bb = *reinterpret_cast<const float4*>(&bias[bn + c0]);
#pragma unroll
    for (int i = 0; i < 4; i++) {
        float2 p0 = unpack2(acc2[i][0]);
        float2 p1 = unpack2(acc2[i][1]);
        float4 o = make_float4(p0.x + bb.x, p0.y + bb.y, p1.x + bb.z, p1.y + bb.w);
        *reinterpret_cast<float4*>(&C[(size_t)(bm + r0 + i) * N + bn + c0]) = o;
    }
}

// ---------------- K2: M[n,q,kj] = sum_i qproj[q,i] * Wkq[n,kj,i] ----------------
__global__ __launch_bounds__(256) void compute_M_kernel(const float* __restrict__ Wkq) {
    __shared__ float AsT[64 * 68];
    __shared__ float BsT[64 * 68];
    const int n = blockIdx.z;
    const int bq = blockIdx.y * 64;
    const int bkj = blockIdx.x * 64;
    const int tid = threadIdx.x;
    const int row = tid >> 4;
    const int col = (tid & 15) * 4;
#pragma unroll
    for (int rr = 0; rr < 4; rr++) {
        int r = row + rr * 16;
        float4 va = *reinterpret_cast<const float4*>(&g_proj[(size_t)(bq + r) * NPROJ + 1024 + n * 64 + col]);
        AsT[(col + 0) * 68 + r] = va.x; AsT[(col + 1) * 68 + r] = va.y;
        AsT[(col + 2) * 68 + r] = va.z; AsT[(col + 3) * 68 + r] = va.w;
        float4 vb = *reinterpret_cast<const float4*>(&Wkq[(size_t)n * 262144 + (size_t)(bkj + r) * 64 + col]);
        BsT[(col + 0) * 68 + r] = vb.x; BsT[(col + 1) * 68 + r] = vb.y;
        BsT[(col + 2) * 68 + r] = vb.z; BsT[(col + 3) * 68 + r] = vb.w;
    }
    __syncthreads();
    const int q0 = (tid & 15) * 4;
    const int kj0 = (tid >> 4) * 4;
    unsigned long long acc2[4][2] = {};
#pragma unroll 8
    for (int i = 0; i < 64; i++) {
        float4 a = *reinterpret_cast<const float4*>(&AsT[i * 68 + q0]);
        ulonglong2 b2 = *reinterpret_cast<const ulonglong2*>(&BsT[i * 68 + kj0]);
        unsigned long long as[4] = {splat2(a.x), splat2(a.y), splat2(a.z), splat2(a.w)};
#pragma unroll
        for (int ii = 0; ii < 4; ii++) {
            acc2[ii][0] = fma2(as[ii], b2.x, acc2[ii][0]);
            acc2[ii][1] = fma2(as[ii], b2.y, acc2[ii][1]);
        }
    }
#pragma unroll
    for (int ii = 0; ii < 4; ii++) {
        float2 p0 = unpack2(acc2[ii][0]);
        float2 p1 = unpack2(acc2[ii][1]);
        float4 o = make_float4(p0.x, p0.y, p1.x, p1.y);
        *reinterpret_cast<float4*>(&g_M[(size_t)(n * T_SEQ + bq + q0 + ii) * 4096 + bkj + kj0]) = o;
    }
}

// ---------------- K3: attention, 2 CTAs per (n,q) split by p-half ----------------
// smem regions (floats):
// U   [0, 4608): ph1 k1b u32[128][36]; ph2 k2b u32[64][36] + v2b u32[64][36]; ph3 v1Tb u32[64][68]=4352
// BP  [4608, 9216): BPb u32[128][36]=4608; ph3 Gs fp32 [64][68]=4352
// Cg  [9216, 13568): ph1 MTb u32[64][36]=2304; ph3 RcorrTb bf16 [64c][136p-halfs]=4352 fl
// red [13568, 14216): red[8] spart[256] stot[64] v1part[256] v1sum[64]
#define OFF_U   0
#define OFF_BP  4608
#define OFF_C   9216
#define OFF_RED 13568
#define ATTN_SMEM_FLOATS 14216
#define ATTN_SMEM_BYTES (ATTN_SMEM_FLOATS * 4)

__global__ __launch_bounds__(256, 2) void attn_kernel() {
    extern __shared__ float sm[];
    const int bid = blockIdx.x;
    const int q = 255 - (bid >> 4);
    const int n = (bid >> 1) & 7;
    const int ph = bid & 1;
    const int P = q + 1;
    const int p_base = ph << 7;
    if (P - p_base <= 0) return;
    const int p_count = min(P - p_base, 128);
    const int tid = threadIdx.x;

    float* U = sm + OFF_U;
    uint32_t* BPb = reinterpret_cast<uint32_t*>(sm + OFF_BP);   // [p][j/2] stride 36
    float* Cg = sm + OFF_C;
    float* red = sm + OFF_RED;
    float* spart  = red + 8;
    float* stotc  = red + 8 + 256;
    float* v1part = red + 8 + 256 + 64;
    float* v1sum  = red + 8 + 256 + 64 + 256;

    const int pl = tid & 31;
    const int wid = tid >> 5;
    const int gid = pl >> 2;          // mma group id 0..7
    const int tidg = pl & 3;          // thread-in-group 0..3
    const int p0w = wid * 16;
    const int cld = tid & 63;
    const int tq  = tid >> 6;

    // ---- load k1b [p][k-pairs] bf16 (stride 36), zero rows >= p_count ----
    {
        uint32_t* k1b = reinterpret_cast<uint32_t*>(U);
        const int rr = tid >> 4;
        const int iv = (tid & 15) * 4;
#pragma unroll
        for (int pass = 0; pass < 8; pass++) {
            int lp = pass * 16 + rr;
            float4 v = make_float4(0.f, 0.f, 0.f, 0.f);
            if (lp < p_count)
                v = *reinterpret_cast<const float4*>(&g_proj[(size_t)(p_base + lp) * NPROJ + n * 64 + iv]);
            k1b[lp * 36 + (iv >> 1) + 0] = bf2(v.x, v.y);
            k1b[lp * 36 + (iv >> 1) + 1] = bf2(v.z, v.w);
        }
    }
    // ---- load MTb [j][k-pairs] bf16 (transposed from g_M[k][j], stride 36) ----
    {
        uint32_t* MTb = reinterpret_cast<uint32_t*>(Cg);
        const float* Mg = g_M + (size_t)(n * T_SEQ + q) * 4096;
#pragma unroll
        for (int i = 0; i < 8; i++) {
            int kp = tq * 8 + i;
            float a = Mg[(2 * kp) * 64 + cld];
            float b = Mg[(2 * kp + 1) * 64 + cld];
            MTb[cld * 36 + kp] = bf2(a, b);
        }
    }
    __syncthreads();

    // ---- phase 1 (bf16 mma): B[p][j] = sum_k k1[p,k] M[k,j]; pack BPb from D-frags ----
    {
        const uint32_t* k1b = reinterpret_cast<const uint32_t*>(U);
        const uint32_t* MTb = reinterpret_cast<const uint32_t*>(Cg);
        float bacc[8][4] = {};
#pragma unroll
        for (int kk = 0; kk < 4; kk++) {
            const int k8 = kk * 8;
            uint32_t afr[4];
            afr[0] = k1b[(p0w + gid) * 36 + k8 + tidg];
            afr[1] = k1b[(p0w + gid + 8) * 36 + k8 + tidg];
            afr[2] = k1b[(p0w + gid) * 36 + k8 + tidg + 4];
            afr[3] = k1b[(p0w + gid + 8) * 36 + k8 + tidg + 4];
#pragma unroll
            for (int nt = 0; nt < 8; nt++) {
                uint32_t bfr[2];
                bfr[0] = MTb[(nt * 8 + gid) * 36 + k8 + tidg];
                bfr[1] = MTb[(nt * 8 + gid) * 36 + k8 + tidg + 4];
                mma16bf(bacc[nt], afr, bfr);
            }
        }
#pragma unroll
        for (int nt = 0; nt < 8; nt++) {
            BPb[(p0w + gid) * 36 + nt * 4 + tidg]     = bf2(bacc[nt][0], bacc[nt][1]);
            BPb[(p0w + gid + 8) * 36 + nt * 4 + tidg] = bf2(bacc[nt][2], bacc[nt][3]);
        }
    }
    __syncthreads();

    // ---- phase 2: S[p][t] bf16 mma; delta trick; Rcorr bf16 mma with register A-frags ----
    float rfr[8][4] = {};             // Rcorr frags: 16p x 64c per warp
    float lsum = 0.f;
    float stot_loc = 0.f;
    uint32_t* k2b = reinterpret_cast<uint32_t*>(U);          // [t][j-pairs] stride 36
    uint32_t* v2b = reinterpret_cast<uint32_t*>(U) + 2304;   // [c][t-pairs] stride 36
    for (int t0 = 0; t0 < P; t0 += 64) {
        {   // load k2 tile [t][j] -> bf16 pairs
            const int rr = tid >> 4;
            const int iv = (tid & 15) * 4;
#pragma unroll
            for (int pass = 0; pass < 4; pass++) {
                int t = pass * 16 + rr;
                int gt = t0 + t;
                float4 a = make_float4(0.f, 0.f, 0.f, 0.f);
                if (gt < P) a = *reinterpret_cast<const float4*>(&g_proj[(size_t)gt * NPROJ + 512 + n * 64 + iv]);
                k2b[t * 36 + (iv >> 1) + 0] = bf2(a.x, a.y);
                k2b[t * 36 + (iv >> 1) + 1] = bf2(a.z, a.w);
            }
        }
        {   // load v2 transposed [c][t] bf16 pairs + fp32 column-sum partials
#pragma unroll
            for (int it = 0; it < 4; it++) {
                int t4 = tq * 16 + it * 4;
                float v[4];
#pragma unroll
                for (int k = 0; k < 4; k++) {
                    int gt = t0 + t4 + k;
                    v[k] = (gt < P) ? g_proj[(size_t)gt * NPROJ + 2048 + n * 64 + cld] : 0.f;
                    stot_loc += v[k];
                }
                v2b[cld * 36 + (t4 >> 1) + 0] = bf2(v[0], v[1]);
                v2b[cld * 36 + (t4 >> 1) + 1] = bf2(v[2], v[3]);
            }
        }
        __syncthreads();
        // S mma: warp tile 16p x 64t
        float sfr[8][4] = {};
#pragma unroll
        for (int kk = 0; kk < 4; kk++) {
            const int j8 = kk * 8;
            uint32_t afr[4];
            afr[0] = BPb[(p0w + gid) * 36 + j8 + tidg];
            afr[1] = BPb[(p0w + gid + 8) * 36 + j8 + tidg];
            afr[2] = BPb[(p0w + gid) * 36 + j8 + tidg + 4];
            afr[3] = BPb[(p0w + gid + 8) * 36 + j8 + tidg + 4];
#pragma unroll
            for (int nt = 0; nt < 8; nt++) {
                uint32_t bfr[2];
                bfr[0] = k2b[(nt * 8 + gid) * 36 + j8 + tidg];
                bfr[1] = k2b[(nt * 8 + gid) * 36 + j8 + tidg + 4];
                mma16bf(sfr[nt], afr, bfr);
            }
        }
        // exp + mask; d = e - 1 kept in registers
#pragma unroll
        for (int nt = 0; nt < 8; nt++)
#pragma unroll
            for (int r = 0; r < 4; r++) {
                int p_loc = p0w + gid + ((r >> 1) << 3);
                int t_loc = nt * 8 + 2 * tidg + (r & 1);
                int gp = p_base + p_loc;
                int gt = t0 + t_loc;
                float e = (gp < P && gt < P) ? __expf(sfr[nt][r] * 0.015625f) : 0.f;
                lsum += e;
                sfr[nt][r] = e - 1.f;
            }
        // Rcorr mma: register repack of d as A-frags
#pragma unroll
        for (int kk = 0; kk < 4; kk++) {
            uint32_t afr[4];
            afr[0] = bf2(sfr[2 * kk][0], sfr[2 * kk][1]);
            afr[1] = bf2(sfr[2 * kk][2], sfr[2 * kk][3]);
            afr[2] = bf2(sfr[2 * kk + 1][0], sfr[2 * kk + 1][1]);
            afr[3] = bf2(sfr[2 * kk + 1][2], sfr[2 * kk + 1][3]);
            const int t8 = kk * 8;
#pragma unroll
            for (int nt = 0; nt < 8; nt++) {
                uint32_t bfr[2];
                bfr[0] = v2b[(nt * 8 + gid) * 36 + t8 + tidg];
                bfr[1] = v2b[(nt * 8 + gid) * 36 + t8 + tidg + 4];
                mma16bf(rfr[nt], afr, bfr);
            }
        }
        __syncthreads();
    }

    // ---- stage RcorrTb [c][p] bf16 scalars into Cg (row stride 136 halfwords = 68 u32) ----
    {
        uint16_t* RTh = reinterpret_cast<uint16_t*>(Cg);
#pragma unroll
        for (int nt = 0; nt < 8; nt++)
#pragma unroll
            for (int r = 0; r < 4; r++) {
                int p = p0w + gid + ((r >> 1) << 3);
                int c = nt * 8 + 2 * tidg + (r & 1);
                RTh[c * 136 + p] = bf16lo(rfr[nt][r]);
            }
    }
    // ---- v1 transposed load -> v1Tb [a][p-pairs] bf16 (stride 68) + fp32 column partials ----
    {
        uint32_t* v1Tb = reinterpret_cast<uint32_t*>(U);
        float vsum = 0.f;
#pragma unroll
        for (int i = 0; i < 16; i++) {
            int pp = tq * 16 + i;
            int pA = 2 * pp, pB = 2 * pp + 1;
            float va = (pA < p_count)
                ? g_proj[(size_t)(p_base + pA) * NPROJ + 1536 + n * 64 + cld] : 0.f;
            float vb = (pB < p_count)
                ? g_proj[(size_t)(p_base + pB) * NPROJ + 1536 + n * 64 + cld] : 0.f;
            v1Tb[cld * 68 + pp] = bf2(va, vb);
            vsum += va + vb;
        }
        v1part[tq * 64 + cld] = vsum;
    }
    // reductions
    spart[tq * 64 + cld] = stot_loc;
#pragma unroll
    for (int off = 16; off > 0; off >>= 1)
        lsum += __shfl_xor_sync(0xffffffffu, lsum, off);
    if (pl == 0) red[wid] = lsum;
    __syncthreads();
    if (tid < 64) {
        stotc[tid] = spart[tid] + spart[64 + tid] + spart[128 + tid] + spart[192 + tid];
        v1sum[tid] = v1part[tid] + v1part[64 + tid] + v1part[128 + tid] + v1part[192 + tid];
    }
    if (tid == 0) {
        float total = 0.f;
#pragma unroll
        for (int w = 0; w < 8; w++) total += red[w];
        g_l[ph * (NH * T_SEQ) + n * T_SEQ + q] = total;
    }
    __syncthreads();

    // ---- phase 3 (bf16 mma + fp32 rank-1): G[a,c] = v1sum[a]*Stot[c] + sum_p v1[p,a]*Rcorr[p,c] ----
    {
        const uint32_t* v1Tb = reinterpret_cast<const uint32_t*>(U);         // [a][p-pairs] stride 68
        const uint32_t* RTb = reinterpret_cast<const uint32_t*>(Cg);          // [c][p-pairs] stride 68
        float* Gs = sm + OFF_BP;     // fp32 [a][c] stride 68
        const int a0w = (wid & 3) * 16;
        const int c0w = (wid >> 2) * 32;
        float gacc[4][4] = {};
#pragma unroll
        for (int kk = 0; kk < 8; kk++) {
            const int k8 = kk * 8;
            uint32_t afr[4];
            afr[0] = v1Tb[(a0w + gid) * 68 + k8 + tidg];
            afr[1] = v1Tb[(a0w + gid + 8) * 68 + k8 + tidg];
            afr[2] = v1Tb[(a0w + gid) * 68 + k8 + tidg + 4];
            afr[3] = v1Tb[(a0w + gid + 8) * 68 + k8 + tidg + 4];
#pragma unroll
            for (int nt = 0; nt < 4; nt++) {
                uint32_t bfr[2];
                bfr[0] = RTb[(c0w + nt * 8 + gid) * 68 + k8 + tidg];
                bfr[1] = RTb[(c0w + nt * 8 + gid) * 68 + k8 + tidg + 4];
                mma16bf(gacc[nt], afr, bfr);
            }
        }
        __syncthreads();   // BPb (aliased by Gs) no longer read by any warp; order before Gs writes
#pragma unroll
        for (int nt = 0; nt < 4; nt++)
#pragma unroll
            for (int r = 0; r < 4; r++) {
                int a = a0w + gid + ((r >> 1) << 3);
                int c = c0w + nt * 8 + 2 * tidg + (r & 1);
                Gs[a * 68 + c] = gacc[nt][r] + v1sum[a] * stotc[c];
            }
    }
    __syncthreads();
    // ---- coalesced copy Gs -> Gout ----
    {
        const float* Gs = sm + OFF_BP;
        float* Gout = (ph ? g_Gb : g_Ga) + (size_t)(n * T_SEQ + q) * 4096;
#pragma unroll
        for (int kq = 0; kq < 4; kq++) {
            int f = tid + kq * 256;
            int row = f >> 4, c4 = (f & 15) * 4;
            float4 v = *reinterpret_cast<const float4*>(&Gs[row * 68 + c4]);
            *reinterpret_cast<float4*>(&Gout[row * 64 + c4]) = v;
        }
    }
}

// ---------------- K4: z_raw += (Ga+Gb) @ W_Vq (K-split x8, atomics) ----------------
__global__ __launch_bounds__(256) void out_v_kernel(const float* __restrict__ Wvq) {
    __shared__ float AsT[32 * 68];
    __shared__ float Bs[32 * 68];
    const int n = blockIdx.y;
    const int bq = blockIdx.x * 64;
    const int ks = blockIdx.z;
    const int tid = threadIdx.x;
    const bool two = (bq >= 128);
    const int arow = tid >> 3, acol = (tid & 7) * 4;
    const int brow = tid >> 4, bcol = (tid & 15) * 4;
    const int q0 = (tid & 15) * 4, e0 = (tid >> 4) * 4;
    unsigned long long acc2[4][2] = {};
    for (int k0 = ks * 512; k0 < ks * 512 + 512; k0 += 32) {
#pragma unroll
        for (int rr = 0; rr < 2; rr++) {
            int r = arow + rr * 32;
            size_t idx = (size_t)(n * T_SEQ + bq + r) * 4096 + k0 + acol;
            float4 v = *reinterpret_cast<const float4*>(&g_Ga[idx]);
            if (two) {
                float4 w = *reinterpret_cast<const float4*>(&g_Gb[idx]);
                v.x += w.x; v.y += w.y; v.z += w.z; v.w += w.w;
            }
            AsT[(acol + 0) * 68 + r] = v.x; AsT[(acol + 1) * 68 + r] = v.y;
            AsT[(acol + 2) * 68 + r] = v.z; AsT[(acol + 3) * 68 + r] = v.w;
        }
#pragma unroll
        for (int rr = 0; rr < 2; rr++) {
            float4 v = *reinterpret_cast<const float4*>(
                &Wvq[(size_t)n * 262144 + (size_t)(k0 + brow + rr * 16) * 64 + bcol]);
            *reinterpret_cast<float4*>(&Bs[(brow + rr * 16) * 68 + bcol]) = v;
        }
        __syncthreads();
#pragma unroll
        for (int kk = 0; kk < 32; kk++) {
            float4 a = *reinterpret_cast<const float4*>(&AsT[kk * 68 + q0]);
            ulonglong2 b2 = *reinterpret_cast<const ulonglong2*>(&Bs[kk * 68 + e0]);
            unsigned long long as[4] = {splat2(a.x), splat2(a.y), splat2(a.z), splat2(a.w)};
#pragma unroll
            for (int i = 0; i < 4; i++) {
                acc2[i][0] = fma2(as[i], b2.x, acc2[i][0]);
                acc2[i][1] = fma2(as[i], b2.y, acc2[i][1]);
            }
        }
        __syncthreads();
    }
#pragma unroll
    for (int i = 0; i < 4; i++) {
        float2 p0 = unpack2(acc2[i][0]);
        float2 p1 = unpack2(acc2[i][1]);
        float* zp = &g_z[(size_t)(bq + q0 + i) * DMODEL + n * 64 + e0];
        atomicAdd(zp + 0, p0.x);
        atomicAdd(zp + 1, p0.y);
        atomicAdd(zp + 2, p1.x);
        atomicAdd(zp + 3, p1.y);
    }
}

// ---------------- K5: out = (z_raw * 1/(la+lb)) @ W_out + b_out ----------------
__global__ __launch_bounds__(256) void gemm_out_kernel(
    const float* __restrict__ Wout, const float* __restrict__ bout, float* __restrict__ C) {
    __shared__ float AsT[32 * 68];
    __shared__ float Bs[32 * 68];
    const int tid = threadIdx.x;
    const int bm = blockIdx.y * 64;
    const int bn = blockIdx.x * 64;
    const int r0 = (tid & 15) * 4;
    const int c0 = (tid >> 4) * 4;
    const int arow = tid >> 3, acol = (tid & 7) * 4;
    const int brow = tid >> 4, bcol = (tid & 15) * 4;
    unsigned long long acc2[4][2] = {};
    for (int k0 = 0; k0 < DMODEL; k0 += 32) {
#pragma unroll
        for (int rr = 0; rr < 2; rr++) {
            int r = bm + arow + rr * 32;
            int gk = k0 + acol;
            int li = (gk >> 6) * T_SEQ + r;
            float invl = 1.f / (g_l[li] + g_l[NH * T_SEQ + li]);
            float4 v = *reinterpret_cast<const float4*>(&g_z[(size_t)r * DMODEL + gk]);
            AsT[(acol + 0) * 68 + arow + rr * 32] = v.x * invl;
            AsT[(acol + 1) * 68 + arow + rr * 32] = v.y * invl;
            AsT[(acol + 2) * 68 + arow + rr * 32] = v.z * invl;
            AsT[(acol + 3) * 68 + arow + rr * 32] = v.w * invl;
        }
#pragma unroll
        for (int rr = 0; rr < 2; rr++) {
            float4 v = *reinterpret_cast<const float4*>(&Wout[(size_t)(k0 + brow + rr * 16) * DMODEL + bn + bcol]);
            *reinterpret_cast<float4*>(&Bs[(brow + rr * 16) * 68 + bcol]) = v;
        }
        __syncthreads();
#pragma unroll
        for (int kk = 0; kk < 32; kk++) {
            float4 a = *reinterpret_cast<const float4*>(&AsT[kk * 68 + r0]);
            ulonglong2 b2 = *reinterpret_cast<const ulonglong2*>(&Bs[kk * 68 + c0]);
            unsigned long long as[4] = {splat2(a.x), splat2(a.y), splat2(a.z), splat2(a.w)};
#pragma unroll
            for (int i = 0; i < 4; i++) {
                acc2[i][0] = fma2(as[i], b2.x, acc2[i][0]);
                acc2[i][1] = fma2(as[i], b2.y, acc2[i][1]);
            }
        }
        __syncthreads();
    }
    float4 bb = *reinterpret_cast<const float4*>(&bout[bn + c0]);
#pragma unroll
    for (int i = 0; i < 4; i++) {
        float2 p0 = unpack2(acc2[i][0]);
        float2 p1 = unpack2(acc2[i][1]);
        float4 o = make_float4(p0.x + bb.x, p0.y + bb.y, p1.x + bb.z, p1.y + bb.w);
        *reinterpret_cast<float4*>(&C[(size_t)(bm + r0 + i) * DMODEL + bn + c0]) = o;
    }
}

// ---------------- launch ----------------
extern "C" void kernel_launch(void* const* d_in, const int* in_sizes, int n_in,
                              void* d_out, int out_size) {
    const float* x       = (const float*)d_in[0];
    const float* Wkkqvv  = (const float*)d_in[1];
    const float* bkkqvv  = (const float*)d_in[2];
    const float* WKq     = (const float*)d_in[3];
    const float* WVq     = (const float*)d_in[4];
    const float* Wout    = (const float*)d_in[5];
    const float* bout    = (const float*)d_in[6];
    float* out = (float*)d_out;

    float* proj_ptr = nullptr;
    cudaGetSymbolAddress((void**)&proj_ptr, g_proj);

    cudaFuncSetAttribute(attn_kernel, cudaFuncAttributeMaxDynamicSharedMemorySize, ATTN_SMEM_BYTES);

    zero_kernel<<<(NZERO + 255) / 256, 256>>>();
    gemm_nn_bias_kernel<<<dim3(NPROJ / 64, T_SEQ / 64), 256>>>(x, Wkkqvv, bkkqvv, proj_ptr,
                                                               T_SEQ, NPROJ, DMODEL);
    compute_M_kernel<<<dim3(64, 4, NH), 256>>>(WKq);
    attn_kernel<<<NH * T_SEQ * 2, 256, ATTN_SMEM_BYTES>>>();
    out_v_kernel<<<dim3(4, NH, 8), 256>>>(WVq);
    gemm_out_kernel<<<dim3(DMODEL / 64, T_SEQ / 64), 256>>>(Wout, bout, out);
}

// round 15
// speedup vs baseline: 2.8512x; 1.1345x over previous
#include <cuda_runtime.h>
#include <cstdint>

#define T_SEQ 256
#define NH 8
#define DHD 64
#define DMODEL 512
#define NPROJ 2560   // 5 * 512

// ---------------- packed fp32x2 helpers (Blackwell FFMA2) ----------------
__device__ __forceinline__ unsigned long long splat2(float x) {
    unsigned long long r;
    asm("mov.b64 %0, {%1, %1};" : "=l"(r) : "f"(x));
    return r;
}
__device__ __forceinline__ unsigned long long fma2(unsigned long long a, unsigned long long b,
                                                   unsigned long long c) {
    unsigned long long d;
    asm("fma.rn.f32x2 %0, %1, %2, %3;" : "=l"(d) : "l"(a), "l"(b), "l"(c));
    return d;
}
__device__ __forceinline__ float2 unpack2(unsigned long long v) {
    float2 f;
    asm("mov.b64 {%0, %1}, %2;" : "=f"(f.x), "=f"(f.y) : "l"(v));
    return f;
}

// ---------------- bf16 helpers ----------------
__device__ __forceinline__ uint32_t bf2(float lo, float hi) {
    uint32_t r;
    asm("cvt.rn.bf16x2.f32 %0, %1, %2;" : "=r"(r) : "f"(hi), "f"(lo));
    return r;
}
__device__ __forceinline__ uint16_t bf16lo(float x) {
    return (uint16_t)(bf2(x, 0.f) & 0xffffu);
}
__device__ __forceinline__ void mma16bf(float d[4], const uint32_t a[4], const uint32_t b[2]) {
    asm("mma.sync.aligned.m16n8k16.row.col.f32.bf16.bf16.f32 "
        "{%0,%1,%2,%3}, {%4,%5,%6,%7}, {%8,%9}, {%0,%1,%2,%3};"
        : "+f"(d[0]), "+f"(d[1]), "+f"(d[2]), "+f"(d[3])
        : "r"(a[0]), "r"(a[1]), "r"(a[2]), "r"(a[3]), "r"(b[0]), "r"(b[1]));
}

// ---------------- scratch ----------------
__device__ float g_proj[T_SEQ * NPROJ];            // [t, 2560]
__device__ float g_M[NH * T_SEQ * DHD * DHD];      // [n, q, k, j]
__device__ float g_Ga[NH * T_SEQ * DHD * DHD];     // [n, q, a, c] p-half 0
__device__ float g_Gb[NH * T_SEQ * DHD * DHD];     // [n, q, a, c] p-half 1
__device__ float g_l[2 * NH * T_SEQ];              // softmax denominator partials
__device__ float g_z[T_SEQ * DMODEL];              // [q, n*64+e]

// ---------------- K0: zero z + l ----------------
#define NZERO (T_SEQ * DMODEL + 2 * NH * T_SEQ)
__global__ __launch_bounds__(256) void zero_kernel() {
    int i = blockIdx.x * 256 + threadIdx.x;
    if (i < T_SEQ * DMODEL) g_z[i] = 0.f;
    else g_l[i - T_SEQ * DMODEL] = 0.f;
}

// ---------------- K1: C[M,N] = A[M,K] @ B[K,N] + bias ----------------
__global__ __launch_bounds__(256) void gemm_nn_bias_kernel(
    const float* __restrict__ A, const float* __restrict__ B,
    const float* __restrict__ bias, float* __restrict__ C,
    int M, int N, int K) {
    __shared__ float AsT[32 * 68];
    __shared__ float Bs[32 * 68];
    const int tid = threadIdx.x;
    const int bm = blockIdx.y * 64;
    const int bn = blockIdx.x * 64;
    const int r0 = (tid & 15) * 4;
    const int c0 = (tid >> 4) * 4;
    const int arow = tid >> 3;
    const int acol = (tid & 7) * 4;
    const int brow = tid >> 4;
    const int bcol = (tid & 15) * 4;
    unsigned long long acc2[4][2] = {};
    for (int k0 = 0; k0 < K; k0 += 32) {
#pragma unroll
        for (int rr = 0; rr < 2; rr++) {
            int r = arow + rr * 32;
            float4 v = *reinterpret_cast<const float4*>(&A[(size_t)(bm + r) * K + k0 + acol]);
            AsT[(acol + 0) * 68 + r] = v.x; AsT[(acol + 1) * 68 + r] = v.y;
            AsT[(acol + 2) * 68 + r] = v.z; AsT[(acol + 3) * 68 + r] = v.w;
        }
#pragma unroll
        for (int rr = 0; rr < 2; rr++) {
            float4 v = *reinterpret_cast<const float4*>(&B[(size_t)(k0 + brow + rr * 16) * N + bn + bcol]);
            *reinterpret_cast<float4*>(&Bs[(brow + rr * 16) * 68 + bcol]) = v;
        }
        __syncthreads();
#pragma unroll
        for (int kk = 0; kk < 32; kk++) {
            float4 a = *reinterpret_cast<const float4*>(&AsT[kk * 68 + r0]);
            ulonglong2 b2 = *reinterpret_cast<const ulonglong2*>(&Bs[kk * 68 + c0]);
            unsigned long long as[4] = {splat2(a.x), splat2(a.y), splat2(a.z), splat2(a.w)};
#pragma unroll
            for (int i = 0; i < 4; i++) {
                acc2[i][0] = fma2(as[i], b2.x, acc2[i][0]);
                acc2[i][1] = fma2(as[i], b2.y, acc2[i][1]);
            }
        }
        __syncthreads();
    }
    float4 bb = *reinterpret_cast<const float4*>(&bias[bn + c0]);
#pragma unroll
    for (int i = 0; i < 4; i++) {
        float2 p0 = unpack2(acc2[i][0]);
        float2 p1 = unpack2(acc2[i][1]);
        float4 o = make_float4(p0.x + bb.x, p0.y + bb.y, p1.x + bb.z, p1.y + bb.w);
        *reinterpret_cast<float4*>(&C[(size_t)(bm + r0 + i) * N + bn + c0]) = o;
    }
}

// ---------------- K2 (bf16 mma): M[n,q,kj] = sum_i qproj[q,i] * Wkq[n,kj,i] ----------------
// CTA covers all 256 q x 64 kj per head -> Wkq read exactly once from DRAM.
__global__ __launch_bounds__(256) void compute_M_kernel(const float* __restrict__ Wkq) {
    __shared__ uint32_t qb[256 * 36];   // [q][i-pairs] bf16
    __shared__ uint32_t Wb[64 * 36];    // [kj][i-pairs] bf16
    const int n = blockIdx.y;
    const int bkj = blockIdx.x * 64;
    const int tid = threadIdx.x;
    const int pl = tid & 31, wid = tid >> 5;
    const int gid = pl >> 2, tidg = pl & 3;
    const int rr = tid >> 4;
    const int iv = (tid & 15) * 4;
    // load qproj [256 q][64 i]
#pragma unroll
    for (int pass = 0; pass < 16; pass++) {
        int qq = pass * 16 + rr;
        float4 v = *reinterpret_cast<const float4*>(&g_proj[(size_t)qq * NPROJ + 1024 + n * 64 + iv]);
        qb[qq * 36 + (iv >> 1) + 0] = bf2(v.x, v.y);
        qb[qq * 36 + (iv >> 1) + 1] = bf2(v.z, v.w);
    }
    // load Wkq [64 kj][64 i]
#pragma unroll
    for (int pass = 0; pass < 4; pass++) {
        int row = pass * 16 + rr;
        float4 v = *reinterpret_cast<const float4*>(
            &Wkq[(size_t)n * 262144 + (size_t)(bkj + row) * 64 + iv]);
        Wb[row * 36 + (iv >> 1) + 0] = bf2(v.x, v.y);
        Wb[row * 36 + (iv >> 1) + 1] = bf2(v.z, v.w);
    }
    __syncthreads();
    const int q0w = wid * 32;
    float acc[2][8][4] = {};
#pragma unroll
    for (int kk = 0; kk < 4; kk++) {
        const int k8 = kk * 8;
        uint32_t afr[2][4];
#pragma unroll
        for (int mt = 0; mt < 2; mt++) {
            int qb0 = q0w + mt * 16;
            afr[mt][0] = qb[(qb0 + gid) * 36 + k8 + tidg];
            afr[mt][1] = qb[(qb0 + gid + 8) * 36 + k8 + tidg];
            afr[mt][2] = qb[(qb0 + gid) * 36 + k8 + tidg + 4];
            afr[mt][3] = qb[(qb0 + gid + 8) * 36 + k8 + tidg + 4];
        }
#pragma unroll
        for (int nt = 0; nt < 8; nt++) {
            uint32_t bfr[2];
            bfr[0] = Wb[(nt * 8 + gid) * 36 + k8 + tidg];
            bfr[1] = Wb[(nt * 8 + gid) * 36 + k8 + tidg + 4];
#pragma unroll
            for (int mt = 0; mt < 2; mt++)
                mma16bf(acc[mt][nt], afr[mt], bfr);
        }
    }
#pragma unroll
    for (int mt = 0; mt < 2; mt++)
#pragma unroll
        for (int nt = 0; nt < 8; nt++) {
            int qrow = q0w + mt * 16 + gid;
            int col = bkj + nt * 8 + 2 * tidg;
            *reinterpret_cast<float2*>(&g_M[(size_t)(n * T_SEQ + qrow) * 4096 + col]) =
                make_float2(acc[mt][nt][0], acc[mt][nt][1]);
            *reinterpret_cast<float2*>(&g_M[(size_t)(n * T_SEQ + qrow + 8) * 4096 + col]) =
                make_float2(acc[mt][nt][2], acc[mt][nt][3]);
        }
}

// ---------------- K3: attention, 2 CTAs per (n,q) split by p-half ----------------
// smem regions (floats):
// U   [0, 4608): ph1 k1b u32[128][36]; ph2 k2b u32[64][36] + v2b u32[64][36]; ph3 v1Tb u32[64][68]=4352
// BP  [4608, 9216): BPb u32[128][36]=4608; ph3 Gs fp32 [64][68]=4352
// Cg  [9216, 13568): ph1 MTb u32[64][36]=2304; ph3 RcorrTb bf16 [64c][136p-halfs]=4352 fl
// red [13568, 14216): red[8] spart[256] stot[64] v1part[256] v1sum[64]
#define OFF_U   0
#define OFF_BP  4608
#define OFF_C   9216
#define OFF_RED 13568
#define ATTN_SMEM_FLOATS 14216
#define ATTN_SMEM_BYTES (ATTN_SMEM_FLOATS * 4)

__global__ __launch_bounds__(256, 2) void attn_kernel() {
    extern __shared__ float sm[];
    const int bid = blockIdx.x;
    const int q = 255 - (bid >> 4);
    const int n = (bid >> 1) & 7;
    const int ph = bid & 1;
    const int P = q + 1;
    const int p_base = ph << 7;
    if (P - p_base <= 0) return;
    const int p_count = min(P - p_base, 128);
    const int tid = threadIdx.x;

    float* U = sm + OFF_U;
    uint32_t* BPb = reinterpret_cast<uint32_t*>(sm + OFF_BP);   // [p][j/2] stride 36
    float* Cg = sm + OFF_C;
    float* red = sm + OFF_RED;
    float* spart  = red + 8;
    float* stotc  = red + 8 + 256;
    float* v1part = red + 8 + 256 + 64;
    float* v1sum  = red + 8 + 256 + 64 + 256;

    const int pl = tid & 31;
    const int wid = tid >> 5;
    const int gid = pl >> 2;          // mma group id 0..7
    const int tidg = pl & 3;          // thread-in-group 0..3
    const int p0w = wid * 16;
    const int cld = tid & 63;
    const int tq  = tid >> 6;

    // ---- load k1b [p][k-pairs] bf16 (stride 36), zero rows >= p_count ----
    {
        uint32_t* k1b = reinterpret_cast<uint32_t*>(U);
        const int rr = tid >> 4;
        const int iv = (tid & 15) * 4;
#pragma unroll
        for (int pass = 0; pass < 8; pass++) {
            int lp = pass * 16 + rr;
            float4 v = make_float4(0.f, 0.f, 0.f, 0.f);
            if (lp < p_count)
                v = *reinterpret_cast<const float4*>(&g_proj[(size_t)(p_base + lp) * NPROJ + n * 64 + iv]);
            k1b[lp * 36 + (iv >> 1) + 0] = bf2(v.x, v.y);
            k1b[lp * 36 + (iv >> 1) + 1] = bf2(v.z, v.w);
        }
    }
    // ---- load MTb [j][k-pairs] bf16 (transposed from g_M[k][j], stride 36) ----
    {
        uint32_t* MTb = reinterpret_cast<uint32_t*>(Cg);
        const float* Mg = g_M + (size_t)(n * T_SEQ + q) * 4096;
#pragma unroll
        for (int i = 0; i < 8; i++) {
            int kp = tq * 8 + i;
            float a = Mg[(2 * kp) * 64 + cld];
            float b = Mg[(2 * kp + 1) * 64 + cld];
            MTb[cld * 36 + kp] = bf2(a, b);
        }
    }
    __syncthreads();

    // ---- phase 1 (bf16 mma): B[p][j] = sum_k k1[p,k] M[k,j]; pack BPb from D-frags ----
    {
        const uint32_t* k1b = reinterpret_cast<const uint32_t*>(U);
        const uint32_t* MTb = reinterpret_cast<const uint32_t*>(Cg);
        float bacc[8][4] = {};
#pragma unroll
        for (int kk = 0; kk < 4; kk++) {
            const int k8 = kk * 8;
            uint32_t afr[4];
            afr[0] = k1b[(p0w + gid) * 36 + k8 + tidg];
            afr[1] = k1b[(p0w + gid + 8) * 36 + k8 + tidg];
            afr[2] = k1b[(p0w + gid) * 36 + k8 + tidg + 4];
            afr[3] = k1b[(p0w + gid + 8) * 36 + k8 + tidg + 4];
#pragma unroll
            for (int nt = 0; nt < 8; nt++) {
                uint32_t bfr[2];
                bfr[0] = MTb[(nt * 8 + gid) * 36 + k8 + tidg];
                bfr[1] = MTb[(nt * 8 + gid) * 36 + k8 + tidg + 4];
                mma16bf(bacc[nt], afr, bfr);
            }
        }
#pragma unroll
        for (int nt = 0; nt < 8; nt++) {
            BPb[(p0w + gid) * 36 + nt * 4 + tidg]     = bf2(bacc[nt][0], bacc[nt][1]);
            BPb[(p0w + gid + 8) * 36 + nt * 4 + tidg] = bf2(bacc[nt][2], bacc[nt][3]);
        }
    }
    __syncthreads();

    // ---- phase 2: S[p][t] bf16 mma; delta trick; Rcorr bf16 mma with register A-frags ----
    float rfr[8][4] = {};             // Rcorr frags: 16p x 64c per warp
    float lsum = 0.f;
    float stot_loc = 0.f;
    uint32_t* k2b = reinterpret_cast<uint32_t*>(U);          // [t][j-pairs] stride 36
    uint32_t* v2b = reinterpret_cast<uint32_t*>(U) + 2304;   // [c][t-pairs] stride 36
    for (int t0 = 0; t0 < P; t0 += 64) {
        {   // load k2 tile [t][j] -> bf16 pairs
            const int rr = tid >> 4;
            const int iv = (tid & 15) * 4;
#pragma unroll
            for (int pass = 0; pass < 4; pass++) {
                int t = pass * 16 + rr;
                int gt = t0 + t;
                float4 a = make_float4(0.f, 0.f, 0.f, 0.f);
                if (gt < P) a = *reinterpret_cast<const float4*>(&g_proj[(size_t)gt * NPROJ + 512 + n * 64 + iv]);
                k2b[t * 36 + (iv >> 1) + 0] = bf2(a.x, a.y);
                k2b[t * 36 + (iv >> 1) + 1] = bf2(a.z, a.w);
            }
        }
        {   // load v2 transposed [c][t] bf16 pairs + fp32 column-sum partials
#pragma unroll
            for (int it = 0; it < 4; it++) {
                int t4 = tq * 16 + it * 4;
                float v[4];
#pragma unroll
                for (int k = 0; k < 4; k++) {
                    int gt = t0 + t4 + k;
                    v[k] = (gt < P) ? g_proj[(size_t)gt * NPROJ + 2048 + n * 64 + cld] : 0.f;
                    stot_loc += v[k];
                }
                v2b[cld * 36 + (t4 >> 1) + 0] = bf2(v[0], v[1]);
                v2b[cld * 36 + (t4 >> 1) + 1] = bf2(v[2], v[3]);
            }
        }
        __syncthreads();
        // S mma: warp tile 16p x 64t
        float sfr[8][4] = {};
#pragma unroll
        for (int kk = 0; kk < 4; kk++) {
            const int j8 = kk * 8;
            uint32_t afr[4];
            afr[0] = BPb[(p0w + gid) * 36 + j8 + tidg];
            afr[1] = BPb[(p0w + gid + 8) * 36 + j8 + tidg];
            afr[2] = BPb[(p0w + gid) * 36 + j8 + tidg + 4];
            afr[3] = BPb[(p0w + gid + 8) * 36 + j8 + tidg + 4];
#pragma unroll
            for (int nt = 0; nt < 8; nt++) {
                uint32_t bfr[2];
                bfr[0] = k2b[(nt * 8 + gid) * 36 + j8 + tidg];
                bfr[1] = k2b[(nt * 8 + gid) * 36 + j8 + tidg + 4];
                mma16bf(sfr[nt], afr, bfr);
            }
        }
        // exp + mask; d = e - 1 kept in registers (fast path for full tiles)
        if (t0 + 64 <= P && p_count == 128) {
#pragma unroll
            for (int nt = 0; nt < 8; nt++)
#pragma unroll
                for (int r = 0; r < 4; r++) {
                    float e = __expf(sfr[nt][r] * 0.015625f);
                    lsum += e;
                    sfr[nt][r] = e - 1.f;
                }
        } else {
#pragma unroll
            for (int nt = 0; nt < 8; nt++)
#pragma unroll
                for (int r = 0; r < 4; r++) {
                    int p_loc = p0w + gid + ((r >> 1) << 3);
                    int t_loc = nt * 8 + 2 * tidg + (r & 1);
                    int gp = p_base + p_loc;
                    int gt = t0 + t_loc;
                    float e = (gp < P && gt < P) ? __expf(sfr[nt][r] * 0.015625f) : 0.f;
                    lsum += e;
                    sfr[nt][r] = e - 1.f;
                }
        }
        // Rcorr mma: register repack of d as A-frags
#pragma unroll
        for (int kk = 0; kk < 4; kk++) {
            uint32_t afr[4];
            afr[0] = bf2(sfr[2 * kk][0], sfr[2 * kk][1]);
            afr[1] = bf2(sfr[2 * kk][2], sfr[2 * kk][3]);
            afr[2] = bf2(sfr[2 * kk + 1][0], sfr[2 * kk + 1][1]);
            afr[3] = bf2(sfr[2 * kk + 1][2], sfr[2 * kk + 1][3]);
            const int t8 = kk * 8;
#pragma unroll
            for (int nt = 0; nt < 8; nt++) {
                uint32_t bfr[2];
                bfr[0] = v2b[(nt * 8 + gid) * 36 + t8 + tidg];
                bfr[1] = v2b[(nt * 8 + gid) * 36 + t8 + tidg + 4];
                mma16bf(rfr[nt], afr, bfr);
            }
        }
        __syncthreads();
    }

    // ---- stage RcorrTb [c][p] bf16 scalars into Cg (row stride 136 halfwords = 68 u32) ----
    {
        uint16_t* RTh = reinterpret_cast<uint16_t*>(Cg);
#pragma unroll
        for (int nt = 0; nt < 8; nt++)
#pragma unroll
            for (int r = 0; r < 4; r++) {
                int p = p0w + gid + ((r >> 1) << 3);
                int c = nt * 8 + 2 * tidg + (r & 1);
                RTh[c * 136 + p] = bf16lo(rfr[nt][r]);
            }
    }
    // ---- v1 transposed load -> v1Tb [a][p-pairs] bf16 (stride 68) + fp32 column partials ----
    {
        uint32_t* v1Tb = reinterpret_cast<uint32_t*>(U);
        float vsum = 0.f;
#pragma unroll
        for (int i = 0; i < 16; i++) {
            int pp = tq * 16 + i;
            int pA = 2 * pp, pB = 2 * pp + 1;
            float va = (pA < p_count)
                ? g_proj[(size_t)(p_base + pA) * NPROJ + 1536 + n * 64 + cld] : 0.f;
            float vb = (pB < p_count)
                ? g_proj[(size_t)(p_base + pB) * NPROJ + 1536 + n * 64 + cld] : 0.f;
            v1Tb[cld * 68 + pp] = bf2(va, vb);
            vsum += va + vb;
        }
        v1part[tq * 64 + cld] = vsum;
    }
    // reductions
    spart[tq * 64 + cld] = stot_loc;
#pragma unroll
    for (int off = 16; off > 0; off >>= 1)
        lsum += __shfl_xor_sync(0xffffffffu, lsum, off);
    if (pl == 0) red[wid] = lsum;
    __syncthreads();
    if (tid < 64) {
        stotc[tid] = spart[tid] + spart[64 + tid] + spart[128 + tid] + spart[192 + tid];
        v1sum[tid] = v1part[tid] + v1part[64 + tid] + v1part[128 + tid] + v1part[192 + tid];
    }
    if (tid == 0) {
        float total = 0.f;
#pragma unroll
        for (int w = 0; w < 8; w++) total += red[w];
        g_l[ph * (NH * T_SEQ) + n * T_SEQ + q] = total;
    }
    __syncthreads();

    // ---- phase 3 (bf16 mma + fp32 rank-1): G[a,c] = v1sum[a]*Stot[c] + sum_p v1[p,a]*Rcorr[p,c] ----
    {
        const uint32_t* v1Tb = reinterpret_cast<const uint32_t*>(U);         // [a][p-pairs] stride 68
        const uint32_t* RTb = reinterpret_cast<const uint32_t*>(Cg);          // [c][p-pairs] stride 68
        float* Gs = sm + OFF_BP;     // fp32 [a][c] stride 68
        const int a0w = (wid & 3) * 16;
        const int c0w = (wid >> 2) * 32;
        float gacc[4][4] = {};
#pragma unroll
        for (int kk = 0; kk < 8; kk++) {
            const int k8 = kk * 8;
            uint32_t afr[4];
            afr[0] = v1Tb[(a0w + gid) * 68 + k8 + tidg];
            afr[1] = v1Tb[(a0w + gid + 8) * 68 + k8 + tidg];
            afr[2] = v1Tb[(a0w + gid) * 68 + k8 + tidg + 4];
            afr[3] = v1Tb[(a0w + gid + 8) * 68 + k8 + tidg + 4];
#pragma unroll
            for (int nt = 0; nt < 4; nt++) {
                uint32_t bfr[2];
                bfr[0] = RTb[(c0w + nt * 8 + gid) * 68 + k8 + tidg];
                bfr[1] = RTb[(c0w + nt * 8 + gid) * 68 + k8 + tidg + 4];
                mma16bf(gacc[nt], afr, bfr);
            }
        }
        __syncthreads();   // BPb (aliased by Gs) no longer read; order before Gs writes
#pragma unroll
        for (int nt = 0; nt < 4; nt++)
#pragma unroll
            for (int r = 0; r < 4; r++) {
                int a = a0w + gid + ((r >> 1) << 3);
                int c = c0w + nt * 8 + 2 * tidg + (r & 1);
                Gs[a * 68 + c] = gacc[nt][r] + v1sum[a] * stotc[c];
            }
    }
    __syncthreads();
    // ---- coalesced copy Gs -> Gout ----
    {
        const float* Gs = sm + OFF_BP;
        float* Gout = (ph ? g_Gb : g_Ga) + (size_t)(n * T_SEQ + q) * 4096;
#pragma unroll
        for (int kq = 0; kq < 4; kq++) {
            int f = tid + kq * 256;
            int row = f >> 4, c4 = (f & 15) * 4;
            float4 v = *reinterpret_cast<const float4*>(&Gs[row * 68 + c4]);
            *reinterpret_cast<float4*>(&Gout[row * 64 + c4]) = v;
        }
    }
}

// ---------------- K4: z_raw += (Ga+Gb) @ W_Vq (K-split x8, atomics) ----------------
__global__ __launch_bounds__(256) void out_v_kernel(const float* __restrict__ Wvq) {
    __shared__ float AsT[32 * 68];
    __shared__ float Bs[32 * 68];
    const int n = blockIdx.y;
    const int bq = blockIdx.x * 64;
    const int ks = blockIdx.z;
    const int tid = threadIdx.x;
    const bool two = (bq >= 128);
    const int arow = tid >> 3, acol = (tid & 7) * 4;
    const int brow = tid >> 4, bcol = (tid & 15) * 4;
    const int q0 = (tid & 15) * 4, e0 = (tid >> 4) * 4;
    unsigned long long acc2[4][2] = {};
    for (int k0 = ks * 512; k0 < ks * 512 + 512; k0 += 32) {
#pragma unroll
        for (int rr = 0; rr < 2; rr++) {
            int r = arow + rr * 32;
            size_t idx = (size_t)(n * T_SEQ + bq + r) * 4096 + k0 + acol;
            float4 v = *reinterpret_cast<const float4*>(&g_Ga[idx]);
            if (two) {
                float4 w = *reinterpret_cast<const float4*>(&g_Gb[idx]);
                v.x += w.x; v.y += w.y; v.z += w.z; v.w += w.w;
            }
            AsT[(acol + 0) * 68 + r] = v.x; AsT[(acol + 1) * 68 + r] = v.y;
            AsT[(acol + 2) * 68 + r] = v.z; AsT[(acol + 3) * 68 + r] = v.w;
        }
#pragma unroll
        for (int rr = 0; rr < 2; rr++) {
            float4 v = *reinterpret_cast<const float4*>(
                &Wvq[(size_t)n * 262144 + (size_t)(k0 + brow + rr * 16) * 64 + bcol]);
            *reinterpret_cast<float4*>(&Bs[(brow + rr * 16) * 68 + bcol]) = v;
        }
        __syncthreads();
#pragma unroll
        for (int kk = 0; kk < 32; kk++) {
            float4 a = *reinterpret_cast<const float4*>(&AsT[kk * 68 + q0]);
            ulonglong2 b2 = *reinterpret_cast<const ulonglong2*>(&Bs[kk * 68 + e0]);
            unsigned long long as[4] = {splat2(a.x), splat2(a.y), splat2(a.z), splat2(a.w)};
#pragma unroll
            for (int i = 0; i < 4; i++) {
                acc2[i][0] = fma2(as[i], b2.x, acc2[i][0]);
                acc2[i][1] = fma2(as[i], b2.y, acc2[i][1]);
            }
        }
        __syncthreads();
    }
#pragma unroll
    for (int i = 0; i < 4; i++) {
        float2 p0 = unpack2(acc2[i][0]);
        float2 p1 = unpack2(acc2[i][1]);
        float* zp = &g_z[(size_t)(bq + q0 + i) * DMODEL + n * 64 + e0];
        atomicAdd(zp + 0, p0.x);
        atomicAdd(zp + 1, p0.y);
        atomicAdd(zp + 2, p1.x);
        atomicAdd(zp + 3, p1.y);
    }
}

// ---------------- K5: out = (z_raw * 1/(la+lb)) @ W_out + b_out ----------------
__global__ __launch_bounds__(256) void gemm_out_kernel(
    const float* __restrict__ Wout, const float* __restrict__ bout, float* __restrict__ C) {
    __shared__ float AsT[32 * 68];
    __shared__ float Bs[32 * 68];
    const int tid = threadIdx.x;
    const int bm = blockIdx.y * 64;
    const int bn = blockIdx.x * 64;
    const int r0 = (tid & 15) * 4;
    const int c0 = (tid >> 4) * 4;
    const int arow = tid >> 3, acol = (tid & 7) * 4;
    const int brow = tid >> 4, bcol = (tid & 15) * 4;
    unsigned long long acc2[4][2] = {};
    for (int k0 = 0; k0 < DMODEL; k0 += 32) {
#pragma unroll
        for (int rr = 0; rr < 2; rr++) {
            int r = bm + arow + rr * 32;
            int gk = k0 + acol;
            int li = (gk >> 6) * T_SEQ + r;
            float invl = 1.f / (g_l[li] + g_l[NH * T_SEQ + li]);
            float4 v = *reinterpret_cast<const float4*>(&g_z[(size_t)r * DMODEL + gk]);
            AsT[(acol + 0) * 68 + arow + rr * 32] = v.x * invl;
            AsT[(acol + 1) * 68 + arow + rr * 32] = v.y * invl;
            AsT[(acol + 2) * 68 + arow + rr * 32] = v.z * invl;
            AsT[(acol + 3) * 68 + arow + rr * 32] = v.w * invl;
        }
#pragma unroll
        for (int rr = 0; rr < 2; rr++) {
            float4 v = *reinterpret_cast<const float4*>(&Wout[(size_t)(k0 + brow + rr * 16) * DMODEL + bn + bcol]);
            *reinterpret_cast<float4*>(&Bs[(brow + rr * 16) * 68 + bcol]) = v;
        }
        __syncthreads();
#pragma unroll
        for (int kk = 0; kk < 32; kk++) {
            float4 a = *reinterpret_cast<const float4*>(&AsT[kk * 68 + r0]);
            ulonglong2 b2 = *reinterpret_cast<const ulonglong2*>(&Bs[kk * 68 + c0]);
            unsigned long long as[4] = {splat2(a.x), splat2(a.y), splat2(a.z), splat2(a.w)};
#pragma unroll
            for (int i = 0; i < 4; i++) {
                acc2[i][0] = fma2(as[i], b2.x, acc2[i][0]);
                acc2[i][1] = fma2(as[i], b2.y, acc2[i][1]);
            }
        }
        __syncthreads();
    }
    float4 bb = *reinterpret_cast<const float4*>(&bout[bn + c0]);
#pragma unroll
    for (int i = 0; i < 4; i++) {
        float2 p0 = unpack2(acc2[i][0]);
        float2 p1 = unpack2(acc2[i][1]);
        float4 o = make_float4(p0.x + bb.x, p0.y + bb.y, p1.x + bb.z, p1.y + bb.w);
        *reinterpret_cast<float4*>(&C[(size_t)(bm + r0 + i) * DMODEL + bn + c0]) = o;
    }
}

// ---------------- launch ----------------
extern "C" void kernel_launch(void* const* d_in, const int* in_sizes, int n_in,
                              void* d_out, int out_size) {
    const float* x       = (const float*)d_in[0];
    const float* Wkkqvv  = (const float*)d_in[1];
    const float* bkkqvv  = (const float*)d_in[2];
    const float* WKq     = (const float*)d_in[3];
    const float* WVq     = (const float*)d_in[4];
    const float* Wout    = (const float*)d_in[5];
    const float* bout    = (const float*)d_in[6];
    float* out = (float*)d_out;

    float* proj_ptr = nullptr;
    cudaGetSymbolAddress((void**)&proj_ptr, g_proj);

    cudaFuncSetAttribute(attn_kernel, cudaFuncAttributeMaxDynamicSharedMemorySize, ATTN_SMEM_BYTES);

    zero_kernel<<<(NZERO + 255) / 256, 256>>>();
    gemm_nn_bias_kernel<<<dim3(NPROJ / 64, T_SEQ / 64), 256>>>(x, Wkkqvv, bkkqvv, proj_ptr,
                                                               T_SEQ, NPROJ, DMODEL);
    compute_M_kernel<<<dim3(64, NH), 256>>>(WKq);
    attn_kernel<<<NH * T_SEQ * 2, 256, ATTN_SMEM_BYTES>>>();
    out_v_kernel<<<dim3(4, NH, 8), 256>>>(WVq);
    gemm_out_kernel<<<dim3(DMODEL / 64, T_SEQ / 64), 256>>>(Wout, bout, out);
}

// round 16
// speedup vs baseline: 3.0195x; 1.0590x over previous
#include <cuda_runtime.h>
#include <cstdint>

#define T_SEQ 256
#define NH 8
#define DHD 64
#define DMODEL 512
#define NPROJ 2560   // 5 * 512

// ---------------- packed fp32x2 helpers (Blackwell FFMA2) ----------------
__device__ __forceinline__ unsigned long long splat2(float x) {
    unsigned long long r;
    asm("mov.b64 %0, {%1, %1};" : "=l"(r) : "f"(x));
    return r;
}
__device__ __forceinline__ unsigned long long fma2(unsigned long long a, unsigned long long b,
                                                   unsigned long long c) {
    unsigned long long d;
    asm("fma.rn.f32x2 %0, %1, %2, %3;" : "=l"(d) : "l"(a), "l"(b), "l"(c));
    return d;
}
__device__ __forceinline__ float2 unpack2(unsigned long long v) {
    float2 f;
    asm("mov.b64 {%0, %1}, %2;" : "=f"(f.x), "=f"(f.y) : "l"(v));
    return f;
}

// ---------------- tf32 / bf16 helpers ----------------
__device__ __forceinline__ uint32_t f2tf(float x) {
    uint32_t u;
    asm("cvt.rna.tf32.f32 %0, %1;" : "=r"(u) : "f"(x));
    return u;
}
__device__ __forceinline__ float f2tf_f(float x) { return __uint_as_float(f2tf(x)); }
__device__ __forceinline__ void mma8(float d[4], const uint32_t a[4], const uint32_t b[2]) {
    asm("mma.sync.aligned.m16n8k8.row.col.f32.tf32.tf32.f32 "
        "{%0,%1,%2,%3}, {%4,%5,%6,%7}, {%8,%9}, {%0,%1,%2,%3};"
        : "+f"(d[0]), "+f"(d[1]), "+f"(d[2]), "+f"(d[3])
        : "r"(a[0]), "r"(a[1]), "r"(a[2]), "r"(a[3]), "r"(b[0]), "r"(b[1]));
}
__device__ __forceinline__ uint32_t bf2(float lo, float hi) {
    uint32_t r;
    asm("cvt.rn.bf16x2.f32 %0, %1, %2;" : "=r"(r) : "f"(hi), "f"(lo));
    return r;
}
__device__ __forceinline__ uint16_t bf16lo(float x) {
    return (uint16_t)(bf2(x, 0.f) & 0xffffu);
}
__device__ __forceinline__ void mma16bf(float d[4], const uint32_t a[4], const uint32_t b[2]) {
    asm("mma.sync.aligned.m16n8k16.row.col.f32.bf16.bf16.f32 "
        "{%0,%1,%2,%3}, {%4,%5,%6,%7}, {%8,%9}, {%0,%1,%2,%3};"
        : "+f"(d[0]), "+f"(d[1]), "+f"(d[2]), "+f"(d[3])
        : "r"(a[0]), "r"(a[1]), "r"(a[2]), "r"(a[3]), "r"(b[0]), "r"(b[1]));
}

// ---------------- scratch ----------------
__device__ float g_proj[T_SEQ * NPROJ];            // [t, 2560]
__device__ float g_M[NH * T_SEQ * DHD * DHD];      // [n, q, k, j]
__device__ float g_Ga[NH * T_SEQ * DHD * DHD];     // [n, q, a, c] p-half 0
__device__ float g_Gb[NH * T_SEQ * DHD * DHD];     // [n, q, a, c] p-half 1
__device__ float g_l[2 * NH * T_SEQ];              // softmax denominator partials
__device__ float g_z[T_SEQ * DMODEL];              // [q, n*64+e]
__device__ float g_WkT[NPROJ * DMODEL];            // Wkkqvv^T [n][k]
__device__ float g_WvqT[NH * DHD * 4096];          // Wvq^T [n][e][k]

// ---------------- K0: zero z + l ----------------
#define NZERO (T_SEQ * DMODEL + 2 * NH * T_SEQ)
__global__ __launch_bounds__(256) void zero_kernel() {
    int i = blockIdx.x * 256 + threadIdx.x;
    if (i < T_SEQ * DMODEL) g_z[i] = 0.f;
    else g_l[i - T_SEQ * DMODEL] = 0.f;
}

// ---------------- Ktr: dst[c][r] = src[r][c], batched over z ----------------
__global__ __launch_bounds__(256) void transpose_kernel(
    const float* __restrict__ src, float* __restrict__ dst, int R, int C) {
    __shared__ float t[32][33];
    const int rb = blockIdx.y * 32, cb = blockIdx.x * 32;
    const float* s = src + (size_t)blockIdx.z * R * C;
    float* d = dst + (size_t)blockIdx.z * R * C;
    const int x = threadIdx.x & 31, y = threadIdx.x >> 5;
#pragma unroll
    for (int i = 0; i < 32; i += 8)
        t[y + i][x] = s[(size_t)(rb + y + i) * C + cb + x];
    __syncthreads();
#pragma unroll
    for (int i = 0; i < 32; i += 8)
        d[(size_t)(cb + y + i) * R + rb + x] = t[x][y + i];
}

// ---------------- K1 (tf32 mma): proj = x @ Wkkqvv + bias ----------------
__global__ __launch_bounds__(256) void gemm_proj_kernel(
    const float* __restrict__ x, const float* __restrict__ bias, float* __restrict__ C) {
    __shared__ float As[64 * 36];   // [m][k] tf32
    __shared__ float Bs[64 * 36];   // [n][k] tf32
    const int tid = threadIdx.x;
    const int bm = blockIdx.y * 64;
    const int bn = blockIdx.x * 64;
    const int pl = tid & 31, wid = tid >> 5;
    const int gid = pl >> 2, tidg = pl & 3;
    const int m0 = (wid & 3) * 16;
    const int n0 = (wid >> 2) * 32;
    const int lrow = tid >> 3;
    const int liv = (tid & 7) * 4;
    float acc[4][4] = {};
    for (int k0 = 0; k0 < DMODEL; k0 += 32) {
#pragma unroll
        for (int ps = 0; ps < 2; ps++) {
            int row = lrow + ps * 32;
            float4 v = *reinterpret_cast<const float4*>(&x[(size_t)(bm + row) * DMODEL + k0 + liv]);
            *reinterpret_cast<float4*>(&As[row * 36 + liv]) =
                make_float4(f2tf_f(v.x), f2tf_f(v.y), f2tf_f(v.z), f2tf_f(v.w));
            float4 w = *reinterpret_cast<const float4*>(&g_WkT[(size_t)(bn + row) * DMODEL + k0 + liv]);
            *reinterpret_cast<float4*>(&Bs[row * 36 + liv]) =
                make_float4(f2tf_f(w.x), f2tf_f(w.y), f2tf_f(w.z), f2tf_f(w.w));
        }
        __syncthreads();
#pragma unroll
        for (int kk = 0; kk < 4; kk++) {
            const int k8 = kk * 8;
            uint32_t afr[4];
            afr[0] = __float_as_uint(As[(m0 + gid) * 36 + k8 + tidg]);
            afr[1] = __float_as_uint(As[(m0 + gid + 8) * 36 + k8 + tidg]);
            afr[2] = __float_as_uint(As[(m0 + gid) * 36 + k8 + tidg + 4]);
            afr[3] = __float_as_uint(As[(m0 + gid + 8) * 36 + k8 + tidg + 4]);
#pragma unroll
            for (int nt = 0; nt < 4; nt++) {
                uint32_t bfr[2];
                bfr[0] = __float_as_uint(Bs[(n0 + nt * 8 + gid) * 36 + k8 + tidg]);
                bfr[1] = __float_as_uint(Bs[(n0 + nt * 8 + gid) * 36 + k8 + tidg + 4]);
                mma8(acc[nt], afr, bfr);
            }
        }
        __syncthreads();
    }
#pragma unroll
    for (int nt = 0; nt < 4; nt++)
#pragma unroll
        for (int half = 0; half < 2; half++) {
            int m = bm + m0 + gid + half * 8;
            int c = bn + n0 + nt * 8 + 2 * tidg;
            float2 bb = *reinterpret_cast<const float2*>(&bias[c]);
            float2 o = make_float2(acc[nt][2 * half] + bb.x, acc[nt][2 * half + 1] + bb.y);
            *reinterpret_cast<float2*>(&C[(size_t)m * NPROJ + c]) = o;
        }
}

// ---------------- K2 (bf16 mma): M[n,q,kj] = sum_i qproj[q,i] * Wkq[n,kj,i] ----------------
__global__ __launch_bounds__(256) void compute_M_kernel(const float* __restrict__ Wkq) {
    __shared__ uint32_t qb[256 * 36];
    __shared__ uint32_t Wb[64 * 36];
    const int n = blockIdx.y;
    const int bkj = blockIdx.x * 64;
    const int tid = threadIdx.x;
    const int pl = tid & 31, wid = tid >> 5;
    const int gid = pl >> 2, tidg = pl & 3;
    const int rr = tid >> 4;
    const int iv = (tid & 15) * 4;
#pragma unroll
    for (int pass = 0; pass < 16; pass++) {
        int qq = pass * 16 + rr;
        float4 v = *reinterpret_cast<const float4*>(&g_proj[(size_t)qq * NPROJ + 1024 + n * 64 + iv]);
        qb[qq * 36 + (iv >> 1) + 0] = bf2(v.x, v.y);
        qb[qq * 36 + (iv >> 1) + 1] = bf2(v.z, v.w);
    }
#pragma unroll
    for (int pass = 0; pass < 4; pass++) {
        int row = pass * 16 + rr;
        float4 v = *reinterpret_cast<const float4*>(
            &Wkq[(size_t)n * 262144 + (size_t)(bkj + row) * 64 + iv]);
        Wb[row * 36 + (iv >> 1) + 0] = bf2(v.x, v.y);
        Wb[row * 36 + (iv >> 1) + 1] = bf2(v.z, v.w);
    }
    __syncthreads();
    const int q0w = wid * 32;
    float acc[2][8][4] = {};
#pragma unroll
    for (int kk = 0; kk < 4; kk++) {
        const int k8 = kk * 8;
        uint32_t afr[2][4];
#pragma unroll
        for (int mt = 0; mt < 2; mt++) {
            int qb0 = q0w + mt * 16;
            afr[mt][0] = qb[(qb0 + gid) * 36 + k8 + tidg];
            afr[mt][1] = qb[(qb0 + gid + 8) * 36 + k8 + tidg];
            afr[mt][2] = qb[(qb0 + gid) * 36 + k8 + tidg + 4];
            afr[mt][3] = qb[(qb0 + gid + 8) * 36 + k8 + tidg + 4];
        }
#pragma unroll
        for (int nt = 0; nt < 8; nt++) {
            uint32_t bfr[2];
            bfr[0] = Wb[(nt * 8 + gid) * 36 + k8 + tidg];
            bfr[1] = Wb[(nt * 8 + gid) * 36 + k8 + tidg + 4];
#pragma unroll
            for (int mt = 0; mt < 2; mt++)
                mma16bf(acc[mt][nt], afr[mt], bfr);
        }
    }
#pragma unroll
    for (int mt = 0; mt < 2; mt++)
#pragma unroll
        for (int nt = 0; nt < 8; nt++) {
            int qrow = q0w + mt * 16 + gid;
            int col = bkj + nt * 8 + 2 * tidg;
            *reinterpret_cast<float2*>(&g_M[(size_t)(n * T_SEQ + qrow) * 4096 + col]) =
                make_float2(acc[mt][nt][0], acc[mt][nt][1]);
            *reinterpret_cast<float2*>(&g_M[(size_t)(n * T_SEQ + qrow + 8) * 4096 + col]) =
                make_float2(acc[mt][nt][2], acc[mt][nt][3]);
        }
}

// ---------------- K3: attention, 2 CTAs per (n,q) split by p-half ----------------
#define OFF_U   0
#define OFF_BP  4608
#define OFF_C   9216
#define OFF_RED 13568
#define ATTN_SMEM_FLOATS 14216
#define ATTN_SMEM_BYTES (ATTN_SMEM_FLOATS * 4)

__global__ __launch_bounds__(256, 2) void attn_kernel() {
    extern __shared__ float sm[];
    const int bid = blockIdx.x;
    const int q = 255 - (bid >> 4);
    const int n = (bid >> 1) & 7;
    const int ph = bid & 1;
    const int P = q + 1;
    const int p_base = ph << 7;
    if (P - p_base <= 0) return;
    const int p_count = min(P - p_base, 128);
    const int tid = threadIdx.x;

    float* U = sm + OFF_U;
    uint32_t* BPb = reinterpret_cast<uint32_t*>(sm + OFF_BP);
    float* Cg = sm + OFF_C;
    float* red = sm + OFF_RED;
    float* spart  = red + 8;
    float* stotc  = red + 8 + 256;
    float* v1part = red + 8 + 256 + 64;
    float* v1sum  = red + 8 + 256 + 64 + 256;

    const int pl = tid & 31;
    const int wid = tid >> 5;
    const int gid = pl >> 2;
    const int tidg = pl & 3;
    const int p0w = wid * 16;
    const int cld = tid & 63;
    const int tq  = tid >> 6;

    {
        uint32_t* k1b = reinterpret_cast<uint32_t*>(U);
        const int rr = tid >> 4;
        const int iv = (tid & 15) * 4;
#pragma unroll
        for (int pass = 0; pass < 8; pass++) {
            int lp = pass * 16 + rr;
            float4 v = make_float4(0.f, 0.f, 0.f, 0.f);
            if (lp < p_count)
                v = *reinterpret_cast<const float4*>(&g_proj[(size_t)(p_base + lp) * NPROJ + n * 64 + iv]);
            k1b[lp * 36 + (iv >> 1) + 0] = bf2(v.x, v.y);
            k1b[lp * 36 + (iv >> 1) + 1] = bf2(v.z, v.w);
        }
    }
    {
        uint32_t* MTb = reinterpret_cast<uint32_t*>(Cg);
        const float* Mg = g_M + (size_t)(n * T_SEQ + q) * 4096;
#pragma unroll
        for (int i = 0; i < 8; i++) {
            int kp = tq * 8 + i;
            float a = Mg[(2 * kp) * 64 + cld];
            float b = Mg[(2 * kp + 1) * 64 + cld];
            MTb[cld * 36 + kp] = bf2(a, b);
        }
    }
    __syncthreads();

    {
        const uint32_t* k1b = reinterpret_cast<const uint32_t*>(U);
        const uint32_t* MTb = reinterpret_cast<const uint32_t*>(Cg);
        float bacc[8][4] = {};
#pragma unroll
        for (int kk = 0; kk < 4; kk++) {
            const int k8 = kk * 8;
            uint32_t afr[4];
            afr[0] = k1b[(p0w + gid) * 36 + k8 + tidg];
            afr[1] = k1b[(p0w + gid + 8) * 36 + k8 + tidg];
            afr[2] = k1b[(p0w + gid) * 36 + k8 + tidg + 4];
            afr[3] = k1b[(p0w + gid + 8) * 36 + k8 + tidg + 4];
#pragma unroll
            for (int nt = 0; nt < 8; nt++) {
                uint32_t bfr[2];
                bfr[0] = MTb[(nt * 8 + gid) * 36 + k8 + tidg];
                bfr[1] = MTb[(nt * 8 + gid) * 36 + k8 + tidg + 4];
                mma16bf(bacc[nt], afr, bfr);
            }
        }
#pragma unroll
        for (int nt = 0; nt < 8; nt++) {
            BPb[(p0w + gid) * 36 + nt * 4 + tidg]     = bf2(bacc[nt][0], bacc[nt][1]);
            BPb[(p0w + gid + 8) * 36 + nt * 4 + tidg] = bf2(bacc[nt][2], bacc[nt][3]);
        }
    }
    __syncthreads();

    float rfr[8][4] = {};
    float lsum = 0.f;
    float stot_loc = 0.f;
    uint32_t* k2b = reinterpret_cast<uint32_t*>(U);
    uint32_t* v2b = reinterpret_cast<uint32_t*>(U) + 2304;
    for (int t0 = 0; t0 < P; t0 += 64) {
        {
            const int rr = tid >> 4;
            const int iv = (tid & 15) * 4;
#pragma unroll
            for (int pass = 0; pass < 4; pass++) {
                int t = pass * 16 + rr;
                int gt = t0 + t;
                float4 a = make_float4(0.f, 0.f, 0.f, 0.f);
                if (gt < P) a = *reinterpret_cast<const float4*>(&g_proj[(size_t)gt * NPROJ + 512 + n * 64 + iv]);
                k2b[t * 36 + (iv >> 1) + 0] = bf2(a.x, a.y);
                k2b[t * 36 + (iv >> 1) + 1] = bf2(a.z, a.w);
            }
        }
        {
#pragma unroll
            for (int it = 0; it < 4; it++) {
                int t4 = tq * 16 + it * 4;
                float v[4];
#pragma unroll
                for (int k = 0; k < 4; k++) {
                    int gt = t0 + t4 + k;
                    v[k] = (gt < P) ? g_proj[(size_t)gt * NPROJ + 2048 + n * 64 + cld] : 0.f;
                    stot_loc += v[k];
                }
                v2b[cld * 36 + (t4 >> 1) + 0] = bf2(v[0], v[1]);
                v2b[cld * 36 + (t4 >> 1) + 1] = bf2(v[2], v[3]);
            }
        }
        __syncthreads();
        float sfr[8][4] = {};
#pragma unroll
        for (int kk = 0; kk < 4; kk++) {
            const int j8 = kk * 8;
            uint32_t afr[4];
            afr[0] = BPb[(p0w + gid) * 36 + j8 + tidg];
            afr[1] = BPb[(p0w + gid + 8) * 36 + j8 + tidg];
            afr[2] = BPb[(p0w + gid) * 36 + j8 + tidg + 4];
            afr[3] = BPb[(p0w + gid + 8) * 36 + j8 + tidg + 4];
#pragma unroll
            for (int nt = 0; nt < 8; nt++) {
                uint32_t bfr[2];
                bfr[0] = k2b[(nt * 8 + gid) * 36 + j8 + tidg];
                bfr[1] = k2b[(nt * 8 + gid) * 36 + j8 + tidg + 4];
                mma16bf(sfr[nt], afr, bfr);
            }
        }
        if (t0 + 64 <= P && p_count == 128) {
#pragma unroll
            for (int nt = 0; nt < 8; nt++)
#pragma unroll
                for (int r = 0; r < 4; r++) {
                    float e = __expf(sfr[nt][r] * 0.015625f);
                    lsum += e;
                    sfr[nt][r] = e - 1.f;
                }
        } else {
#pragma unroll
            for (int nt = 0; nt < 8; nt++)
#pragma unroll
                for (int r = 0; r < 4; r++) {
                    int p_loc = p0w + gid + ((r >> 1) << 3);
                    int t_loc = nt * 8 + 2 * tidg + (r & 1);
                    int gp = p_base + p_loc;
                    int gt = t0 + t_loc;
                    float e = (gp < P && gt < P) ? __expf(sfr[nt][r] * 0.015625f) : 0.f;
                    lsum += e;
                    sfr[nt][r] = e - 1.f;
                }
        }
#pragma unroll
        for (int kk = 0; kk < 4; kk++) {
            uint32_t afr[4];
            afr[0] = bf2(sfr[2 * kk][0], sfr[2 * kk][1]);
            afr[1] = bf2(sfr[2 * kk][2], sfr[2 * kk][3]);
            afr[2] = bf2(sfr[2 * kk + 1][0], sfr[2 * kk + 1][1]);
            afr[3] = bf2(sfr[2 * kk + 1][2], sfr[2 * kk + 1][3]);
            const int t8 = kk * 8;
#pragma unroll
            for (int nt = 0; nt < 8; nt++) {
                uint32_t bfr[2];
                bfr[0] = v2b[(nt * 8 + gid) * 36 + t8 + tidg];
                bfr[1] = v2b[(nt * 8 + gid) * 36 + t8 + tidg + 4];
                mma16bf(rfr[nt], afr, bfr);
            }
        }
        __syncthreads();
    }

    {
        uint16_t* RTh = reinterpret_cast<uint16_t*>(Cg);
#pragma unroll
        for (int nt = 0; nt < 8; nt++)
#pragma unroll
            for (int r = 0; r < 4; r++) {
                int p = p0w + gid + ((r >> 1) << 3);
                int c = nt * 8 + 2 * tidg + (r & 1);
                RTh[c * 136 + p] = bf16lo(rfr[nt][r]);
            }
    }
    {
        uint32_t* v1Tb = reinterpret_cast<uint32_t*>(U);
        float vsum = 0.f;
#pragma unroll
        for (int i = 0; i < 16; i++) {
            int pp = tq * 16 + i;
            int pA = 2 * pp, pB = 2 * pp + 1;
            float va = (pA < p_count)
                ? g_proj[(size_t)(p_base + pA) * NPROJ + 1536 + n * 64 + cld] : 0.f;
            float vb = (pB < p_count)
                ? g_proj[(size_t)(p_base + pB) * NPROJ + 1536 + n * 64 + cld] : 0.f;
            v1Tb[cld * 68 + pp] = bf2(va, vb);
            vsum += va + vb;
        }
        v1part[tq * 64 + cld] = vsum;
    }
    spart[tq * 64 + cld] = stot_loc;
#pragma unroll
    for (int off = 16; off > 0; off >>= 1)
        lsum += __shfl_xor_sync(0xffffffffu, lsum, off);
    if (pl == 0) red[wid] = lsum;
    __syncthreads();
    if (tid < 64) {
        stotc[tid] = spart[tid] + spart[64 + tid] + spart[128 + tid] + spart[192 + tid];
        v1sum[tid] = v1part[tid] + v1part[64 + tid] + v1part[128 + tid] + v1part[192 + tid];
    }
    if (tid == 0) {
        float total = 0.f;
#pragma unroll
        for (int w = 0; w < 8; w++) total += red[w];
        g_l[ph * (NH * T_SEQ) + n * T_SEQ + q] = total;
    }
    __syncthreads();

    {
        const uint32_t* v1Tb = reinterpret_cast<const uint32_t*>(U);
        const uint32_t* RTb = reinterpret_cast<const uint32_t*>(Cg);
        float* Gs = sm + OFF_BP;
        const int a0w = (wid & 3) * 16;
        const int c0w = (wid >> 2) * 32;
        float gacc[4][4] = {};
#pragma unroll
        for (int kk = 0; kk < 8; kk++) {
            const int k8 = kk * 8;
            uint32_t afr[4];
            afr[0] = v1Tb[(a0w + gid) * 68 + k8 + tidg];
            afr[1] = v1Tb[(a0w + gid + 8) * 68 + k8 + tidg];
            afr[2] = v1Tb[(a0w + gid) * 68 + k8 + tidg + 4];
            afr[3] = v1Tb[(a0w + gid + 8) * 68 + k8 + tidg + 4];
#pragma unroll
            for (int nt = 0; nt < 4; nt++) {
                uint32_t bfr[2];
                bfr[0] = RTb[(c0w + nt * 8 + gid) * 68 + k8 + tidg];
                bfr[1] = RTb[(c0w + nt * 8 + gid) * 68 + k8 + tidg + 4];
                mma16bf(gacc[nt], afr, bfr);
            }
        }
        __syncthreads();
#pragma unroll
        for (int nt = 0; nt < 4; nt++)
#pragma unroll
            for (int r = 0; r < 4; r++) {
                int a = a0w + gid + ((r >> 1) << 3);
                int c = c0w + nt * 8 + 2 * tidg + (r & 1);
                Gs[a * 68 + c] = gacc[nt][r] + v1sum[a] * stotc[c];
            }
    }
    __syncthreads();
    {
        const float* Gs = sm + OFF_BP;
        float* Gout = (ph ? g_Gb : g_Ga) + (size_t)(n * T_SEQ + q) * 4096;
#pragma unroll
        for (int kq = 0; kq < 4; kq++) {
            int f = tid + kq * 256;
            int row = f >> 4, c4 = (f & 15) * 4;
            float4 v = *reinterpret_cast<const float4*>(&Gs[row * 68 + c4]);
            *reinterpret_cast<float4*>(&Gout[row * 64 + c4]) = v;
        }
    }
}

// ---------------- K4 (tf32 mma): z_raw += (Ga+Gb) @ W_Vq (K-split x8, atomics) ----------------
__global__ __launch_bounds__(256) void out_v_kernel() {
    __shared__ float As[64 * 36];   // [q][k] tf32
    __shared__ float Bs[64 * 36];   // [e][k] tf32
    const int n = blockIdx.y;
    const int bq = blockIdx.x * 64;
    const int ks = blockIdx.z;
    const int tid = threadIdx.x;
    const bool two = (bq >= 128);
    const int pl = tid & 31, wid = tid >> 5;
    const int gid = pl >> 2, tidg = pl & 3;
    const int m0 = (wid & 3) * 16;
    const int n0 = (wid >> 2) * 32;
    const int lrow = tid >> 3;
    const int liv = (tid & 7) * 4;
    float acc[4][4] = {};
    for (int k0 = ks * 512; k0 < ks * 512 + 512; k0 += 32) {
#pragma unroll
        for (int ps = 0; ps < 2; ps++) {
            int row = lrow + ps * 32;
            size_t idx = (size_t)(n * T_SEQ + bq + row) * 4096 + k0 + liv;
            float4 v = *reinterpret_cast<const float4*>(&g_Ga[idx]);
            if (two) {
                float4 w = *reinterpret_cast<const float4*>(&g_Gb[idx]);
                v.x += w.x; v.y += w.y; v.z += w.z; v.w += w.w;
            }
            *reinterpret_cast<float4*>(&As[row * 36 + liv]) =
                make_float4(f2tf_f(v.x), f2tf_f(v.y), f2tf_f(v.z), f2tf_f(v.w));
            float4 w = *reinterpret_cast<const float4*>(
                &g_WvqT[(size_t)n * 262144 + (size_t)row * 4096 + k0 + liv]);
            *reinterpret_cast<float4*>(&Bs[row * 36 + liv]) =
                make_float4(f2tf_f(w.x), f2tf_f(w.y), f2tf_f(w.z), f2tf_f(w.w));
        }
        __syncthreads();
#pragma unroll
        for (int kk = 0; kk < 4; kk++) {
            const int k8 = kk * 8;
            uint32_t afr[4];
            afr[0] = __float_as_uint(As[(m0 + gid) * 36 + k8 + tidg]);
            afr[1] = __float_as_uint(As[(m0 + gid + 8) * 36 + k8 + tidg]);
            afr[2] = __float_as_uint(As[(m0 + gid) * 36 + k8 + tidg + 4]);
            afr[3] = __float_as_uint(As[(m0 + gid + 8) * 36 + k8 + tidg + 4]);
#pragma unroll
            for (int nt = 0; nt < 4; nt++) {
                uint32_t bfr[2];
                bfr[0] = __float_as_uint(Bs[(n0 + nt * 8 + gid) * 36 + k8 + tidg]);
                bfr[1] = __float_as_uint(Bs[(n0 + nt * 8 + gid) * 36 + k8 + tidg + 4]);
                mma8(acc[nt], afr, bfr);
            }
        }
        __syncthreads();
    }
#pragma unroll
    for (int nt = 0; nt < 4; nt++)
#pragma unroll
        for (int r = 0; r < 4; r++) {
            int m = bq + m0 + gid + ((r >> 1) << 3);
            int e = n0 + nt * 8 + 2 * tidg + (r & 1);
            atomicAdd(&g_z[(size_t)m * DMODEL + n * 64 + e], acc[nt][r]);
        }
}

// ---------------- K5: out = (z_raw * 1/(la+lb)) @ W_out + b_out (FFMA2) ----------------
__global__ __launch_bounds__(256) void gemm_out_kernel(
    const float* __restrict__ Wout, const float* __restrict__ bout, float* __restrict__ C) {
    __shared__ float AsT[32 * 68];
    __shared__ float Bs[32 * 68];
    const int tid = threadIdx.x;
    const int bm = blockIdx.y * 64;
    const int bn = blockIdx.x * 64;
    const int r0 = (tid & 15) * 4;
    const int c0 = (tid >> 4) * 4;
    const int arow = tid >> 3, acol = (tid & 7) * 4;
    const int brow = tid >> 4, bcol = (tid & 15) * 4;
    unsigned long long acc2[4][2] = {};
    for (int k0 = 0; k0 < DMODEL; k0 += 32) {
#pragma unroll
        for (int rr = 0; rr < 2; rr++) {
            int r = bm + arow + rr * 32;
            int gk = k0 + acol;
            int li = (gk >> 6) * T_SEQ + r;
            float invl = 1.f / (g_l[li] + g_l[NH * T_SEQ + li]);
            float4 v = *reinterpret_cast<const float4*>(&g_z[(size_t)r * DMODEL + gk]);
            AsT[(acol + 0) * 68 + arow + rr * 32] = v.x * invl;
            AsT[(acol + 1) * 68 + arow + rr * 32] = v.y * invl;
            AsT[(acol + 2) * 68 + arow + rr * 32] = v.z * invl;
            AsT[(acol + 3) * 68 + arow + rr * 32] = v.w * invl;
        }
#pragma unroll
        for (int rr = 0; rr < 2; rr++) {
            float4 v = *reinterpret_cast<const float4*>(&Wout[(size_t)(k0 + brow + rr * 16) * DMODEL + bn + bcol]);
            *reinterpret_cast<float4*>(&Bs[(brow + rr * 16) * 68 + bcol]) = v;
        }
        __syncthreads();
#pragma unroll
        for (int kk = 0; kk < 32; kk++) {
            float4 a = *reinterpret_cast<const float4*>(&AsT[kk * 68 + r0]);
            ulonglong2 b2 = *reinterpret_cast<const ulonglong2*>(&Bs[kk * 68 + c0]);
            unsigned long long as[4] = {splat2(a.x), splat2(a.y), splat2(a.z), splat2(a.w)};
#pragma unroll
            for (int i = 0; i < 4; i++) {
                acc2[i][0] = fma2(as[i], b2.x, acc2[i][0]);
                acc2[i][1] = fma2(as[i], b2.y, acc2[i][1]);
            }
        }
        __syncthreads();
    }
    float4 bb = *reinterpret_cast<const float4*>(&bout[bn + c0]);
#pragma unroll
    for (int i = 0; i < 4; i++) {
        float2 p0 = unpack2(acc2[i][0]);
        float2 p1 = unpack2(acc2[i][1]);
        float4 o = make_float4(p0.x + bb.x, p0.y + bb.y, p1.x + bb.z, p1.y + bb.w);
        *reinterpret_cast<float4*>(&C[(size_t)(bm + r0 + i) * DMODEL + bn + c0]) = o;
    }
}

// ---------------- launch ----------------
extern "C" void kernel_launch(void* const* d_in, const int* in_sizes, int n_in,
                              void* d_out, int out_size) {
    const float* x       = (const float*)d_in[0];
    const float* Wkkqvv  = (const float*)d_in[1];
    const float* bkkqvv  = (const float*)d_in[2];
    const float* WKq     = (const float*)d_in[3];
    const float* WVq     = (const float*)d_in[4];
    const float* Wout    = (const float*)d_in[5];
    const float* bout    = (const float*)d_in[6];
    float* out = (float*)d_out;

    float* proj_ptr = nullptr;
    cudaGetSymbolAddress((void**)&proj_ptr, g_proj);
    float* wkt_ptr = nullptr;
    cudaGetSymbolAddress((void**)&wkt_ptr, g_WkT);
    float* wvqt_ptr = nullptr;
    cudaGetSymbolAddress((void**)&wvqt_ptr, g_WvqT);

    cudaFuncSetAttribute(attn_kernel, cudaFuncAttributeMaxDynamicSharedMemorySize, ATTN_SMEM_BYTES);

    zero_kernel<<<(NZERO + 255) / 256, 256>>>();
    transpose_kernel<<<dim3(NPROJ / 32, DMODEL / 32, 1), 256>>>(Wkkqvv, wkt_ptr, DMODEL, NPROJ);
    transpose_kernel<<<dim3(DHD / 32, 4096 / 32, NH), 256>>>(WVq, wvqt_ptr, 4096, DHD);
    gemm_proj_kernel<<<dim3(NPROJ / 64, T_SEQ / 64), 256>>>(x, bkkqvv, proj_ptr);
    compute_M_kernel<<<dim3(64, NH), 256>>>(WKq);
    attn_kernel<<<NH * T_SEQ * 2, 256, ATTN_SMEM_BYTES>>>();
    out_v_kernel<<<dim3(4, NH, 8), 256>>>();
    gemm_out_kernel<<<dim3(DMODEL / 64, T_SEQ / 64), 256>>>(Wout, bout, out);
}

// round 17
// speedup vs baseline: 3.6435x; 1.2066x over previous
#include <cuda_runtime.h>
#include <cstdint>

#define T_SEQ 256
#define NH 8
#define DHD 64
#define DMODEL 512
#define NPROJ 2560   // 5 * 512

// ---------------- packed fp32x2 helpers (Blackwell FFMA2) ----------------
__device__ __forceinline__ unsigned long long splat2(float x) {
    unsigned long long r;
    asm("mov.b64 %0, {%1, %1};" : "=l"(r) : "f"(x));
    return r;
}
__device__ __forceinline__ unsigned long long fma2(unsigned long long a, unsigned long long b,
                                                   unsigned long long c) {
    unsigned long long d;
    asm("fma.rn.f32x2 %0, %1, %2, %3;" : "=l"(d) : "l"(a), "l"(b), "l"(c));
    return d;
}
__device__ __forceinline__ float2 unpack2(unsigned long long v) {
    float2 f;
    asm("mov.b64 {%0, %1}, %2;" : "=f"(f.x), "=f"(f.y) : "l"(v));
    return f;
}

// ---------------- tf32 / bf16 helpers ----------------
__device__ __forceinline__ uint32_t f2tf(float x) {
    uint32_t u;
    asm("cvt.rna.tf32.f32 %0, %1;" : "=r"(u) : "f"(x));
    return u;
}
__device__ __forceinline__ float f2tf_f(float x) { return __uint_as_float(f2tf(x)); }
__device__ __forceinline__ void mma8(float d[4], const uint32_t a[4], const uint32_t b[2]) {
    asm("mma.sync.aligned.m16n8k8.row.col.f32.tf32.tf32.f32 "
        "{%0,%1,%2,%3}, {%4,%5,%6,%7}, {%8,%9}, {%0,%1,%2,%3};"
        : "+f"(d[0]), "+f"(d[1]), "+f"(d[2]), "+f"(d[3])
        : "r"(a[0]), "r"(a[1]), "r"(a[2]), "r"(a[3]), "r"(b[0]), "r"(b[1]));
}
__device__ __forceinline__ uint32_t bf2(float lo, float hi) {
    uint32_t r;
    asm("cvt.rn.bf16x2.f32 %0, %1, %2;" : "=r"(r) : "f"(hi), "f"(lo));
    return r;
}
__device__ __forceinline__ uint16_t bf16lo(float x) {
    return (uint16_t)(bf2(x, 0.f) & 0xffffu);
}
__device__ __forceinline__ void mma16bf(float d[4], const uint32_t a[4], const uint32_t b[2]) {
    asm("mma.sync.aligned.m16n8k16.row.col.f32.bf16.bf16.f32 "
        "{%0,%1,%2,%3}, {%4,%5,%6,%7}, {%8,%9}, {%0,%1,%2,%3};"
        : "+f"(d[0]), "+f"(d[1]), "+f"(d[2]), "+f"(d[3])
        : "r"(a[0]), "r"(a[1]), "r"(a[2]), "r"(a[3]), "r"(b[0]), "r"(b[1]));
}

// ---------------- scratch ----------------
__device__ float g_proj[T_SEQ * NPROJ];            // [t, 2560]
__device__ float g_M[NH * T_SEQ * DHD * DHD];      // [n, q, k, j]
__device__ float g_Ga[NH * T_SEQ * DHD * DHD];     // [n, q, a, c] p-half 0
__device__ float g_Gb[NH * T_SEQ * DHD * DHD];     // [n, q, a, c] p-half 1
__device__ float g_l[2 * NH * T_SEQ];              // softmax denominator partials
__device__ float g_z[T_SEQ * DMODEL];              // [q, n*64+e]
__device__ float g_WkT[NPROJ * DMODEL];            // Wkkqvv^T [n][k]
__device__ float g_WvqT[NH * DHD * 4096];          // Wvq^T [n][e][k]

// ---------------- K0: zero z + l, seed out with bias ----------------
#define NZERO (T_SEQ * DMODEL + 2 * NH * T_SEQ)
__global__ __launch_bounds__(256) void zero_kernel(float* __restrict__ out,
                                                   const float* __restrict__ bout) {
    int i = blockIdx.x * 256 + threadIdx.x;
    if (i < T_SEQ * DMODEL) {
        g_z[i] = 0.f;
        out[i] = bout[i & (DMODEL - 1)];
    } else {
        g_l[i - T_SEQ * DMODEL] = 0.f;
    }
}

// ---------------- Ktr: dst[c][r] = src[r][c], batched over z ----------------
__global__ __launch_bounds__(256) void transpose_kernel(
    const float* __restrict__ src, float* __restrict__ dst, int R, int C) {
    __shared__ float t[32][33];
    const int rb = blockIdx.y * 32, cb = blockIdx.x * 32;
    const float* s = src + (size_t)blockIdx.z * R * C;
    float* d = dst + (size_t)blockIdx.z * R * C;
    const int x = threadIdx.x & 31, y = threadIdx.x >> 5;
#pragma unroll
    for (int i = 0; i < 32; i += 8)
        t[y + i][x] = s[(size_t)(rb + y + i) * C + cb + x];
    __syncthreads();
#pragma unroll
    for (int i = 0; i < 32; i += 8)
        d[(size_t)(cb + y + i) * R + rb + x] = t[x][y + i];
}

// ---------------- K1 (tf32 mma, pipelined): proj = x @ Wkkqvv + bias ----------------
__global__ __launch_bounds__(256) void gemm_proj_kernel(
    const float* __restrict__ x, const float* __restrict__ bias, float* __restrict__ C) {
    __shared__ float As[64 * 36];   // [m][k] tf32
    __shared__ float Bs[64 * 36];   // [n][k] tf32
    const int tid = threadIdx.x;
    const int bm = blockIdx.y * 64;
    const int bn = blockIdx.x * 64;
    const int pl = tid & 31, wid = tid >> 5;
    const int gid = pl >> 2, tidg = pl & 3;
    const int m0 = (wid & 3) * 16;
    const int n0 = (wid >> 2) * 32;
    const int lrow = tid >> 3;
    const int liv = (tid & 7) * 4;
    float acc[4][4] = {};
    float4 rx[2], rw[2];
#pragma unroll
    for (int ps = 0; ps < 2; ps++) {
        int row = lrow + ps * 32;
        rx[ps] = *reinterpret_cast<const float4*>(&x[(size_t)(bm + row) * DMODEL + liv]);
        rw[ps] = *reinterpret_cast<const float4*>(&g_WkT[(size_t)(bn + row) * DMODEL + liv]);
    }
    for (int it = 0; it < 16; it++) {
#pragma unroll
        for (int ps = 0; ps < 2; ps++) {
            int row = lrow + ps * 32;
            *reinterpret_cast<float4*>(&As[row * 36 + liv]) =
                make_float4(f2tf_f(rx[ps].x), f2tf_f(rx[ps].y), f2tf_f(rx[ps].z), f2tf_f(rx[ps].w));
            *reinterpret_cast<float4*>(&Bs[row * 36 + liv]) =
                make_float4(f2tf_f(rw[ps].x), f2tf_f(rw[ps].y), f2tf_f(rw[ps].z), f2tf_f(rw[ps].w));
        }
        __syncthreads();
        if (it < 15) {
            int kn = (it + 1) * 32;
#pragma unroll
            for (int ps = 0; ps < 2; ps++) {
                int row = lrow + ps * 32;
                rx[ps] = *reinterpret_cast<const float4*>(&x[(size_t)(bm + row) * DMODEL + kn + liv]);
                rw[ps] = *reinterpret_cast<const float4*>(&g_WkT[(size_t)(bn + row) * DMODEL + kn + liv]);
            }
        }
#pragma unroll
        for (int kk = 0; kk < 4; kk++) {
            const int k8 = kk * 8;
            uint32_t afr[4];
            afr[0] = __float_as_uint(As[(m0 + gid) * 36 + k8 + tidg]);
            afr[1] = __float_as_uint(As[(m0 + gid + 8) * 36 + k8 + tidg]);
            afr[2] = __float_as_uint(As[(m0 + gid) * 36 + k8 + tidg + 4]);
            afr[3] = __float_as_uint(As[(m0 + gid + 8) * 36 + k8 + tidg + 4]);
#pragma unroll
            for (int nt = 0; nt < 4; nt++) {
                uint32_t bfr[2];
                bfr[0] = __float_as_uint(Bs[(n0 + nt * 8 + gid) * 36 + k8 + tidg]);
                bfr[1] = __float_as_uint(Bs[(n0 + nt * 8 + gid) * 36 + k8 + tidg + 4]);
                mma8(acc[nt], afr, bfr);
            }
        }
        __syncthreads();
    }
#pragma unroll
    for (int nt = 0; nt < 4; nt++)
#pragma unroll
        for (int half = 0; half < 2; half++) {
            int m = bm + m0 + gid + half * 8;
            int c = bn + n0 + nt * 8 + 2 * tidg;
            float2 bb = *reinterpret_cast<const float2*>(&bias[c]);
            float2 o = make_float2(acc[nt][2 * half] + bb.x, acc[nt][2 * half + 1] + bb.y);
            *reinterpret_cast<float2*>(&C[(size_t)m * NPROJ + c]) = o;
        }
}

// ---------------- K2 (bf16 mma): M[n,q,kj] = sum_i qproj[q,i] * Wkq[n,kj,i] ----------------
__global__ __launch_bounds__(256) void compute_M_kernel(const float* __restrict__ Wkq) {
    __shared__ uint32_t qb[256 * 36];
    __shared__ uint32_t Wb[64 * 36];
    const int n = blockIdx.y;
    const int bkj = blockIdx.x * 64;
    const int tid = threadIdx.x;
    const int pl = tid & 31, wid = tid >> 5;
    const int gid = pl >> 2, tidg = pl & 3;
    const int rr = tid >> 4;
    const int iv = (tid & 15) * 4;
#pragma unroll
    for (int pass = 0; pass < 16; pass++) {
        int qq = pass * 16 + rr;
        float4 v = *reinterpret_cast<const float4*>(&g_proj[(size_t)qq * NPROJ + 1024 + n * 64 + iv]);
        qb[qq * 36 + (iv >> 1) + 0] = bf2(v.x, v.y);
        qb[qq * 36 + (iv >> 1) + 1] = bf2(v.z, v.w);
    }
#pragma unroll
    for (int pass = 0; pass < 4; pass++) {
        int row = pass * 16 + rr;
        float4 v = *reinterpret_cast<const float4*>(
            &Wkq[(size_t)n * 262144 + (size_t)(bkj + row) * 64 + iv]);
        Wb[row * 36 + (iv >> 1) + 0] = bf2(v.x, v.y);
        Wb[row * 36 + (iv >> 1) + 1] = bf2(v.z, v.w);
    }
    __syncthreads();
    const int q0w = wid * 32;
    float acc[2][8][4] = {};
#pragma unroll
    for (int kk = 0; kk < 4; kk++) {
        const int k8 = kk * 8;
        uint32_t afr[2][4];
#pragma unroll
        for (int mt = 0; mt < 2; mt++) {
            int qb0 = q0w + mt * 16;
            afr[mt][0] = qb[(qb0 + gid) * 36 + k8 + tidg];
            afr[mt][1] = qb[(qb0 + gid + 8) * 36 + k8 + tidg];
            afr[mt][2] = qb[(qb0 + gid) * 36 + k8 + tidg + 4];
            afr[mt][3] = qb[(qb0 + gid + 8) * 36 + k8 + tidg + 4];
        }
#pragma unroll
        for (int nt = 0; nt < 8; nt++) {
            uint32_t bfr[2];
            bfr[0] = Wb[(nt * 8 + gid) * 36 + k8 + tidg];
            bfr[1] = Wb[(nt * 8 + gid) * 36 + k8 + tidg + 4];
#pragma unroll
            for (int mt = 0; mt < 2; mt++)
                mma16bf(acc[mt][nt], afr[mt], bfr);
        }
    }
#pragma unroll
    for (int mt = 0; mt < 2; mt++)
#pragma unroll
        for (int nt = 0; nt < 8; nt++) {
            int qrow = q0w + mt * 16 + gid;
            int col = bkj + nt * 8 + 2 * tidg;
            *reinterpret_cast<float2*>(&g_M[(size_t)(n * T_SEQ + qrow) * 4096 + col]) =
                make_float2(acc[mt][nt][0], acc[mt][nt][1]);
            *reinterpret_cast<float2*>(&g_M[(size_t)(n * T_SEQ + qrow + 8) * 4096 + col]) =
                make_float2(acc[mt][nt][2], acc[mt][nt][3]);
        }
}

// ---------------- K3: attention, 2 CTAs per (n,q) split by p-half ----------------
#define OFF_U   0
#define OFF_BP  4608
#define OFF_C   9216
#define OFF_RED 13568
#define ATTN_SMEM_FLOATS 14216
#define ATTN_SMEM_BYTES (ATTN_SMEM_FLOATS * 4)

__global__ __launch_bounds__(256, 2) void attn_kernel() {
    extern __shared__ float sm[];
    const int bid = blockIdx.x;
    const int q = 255 - (bid >> 4);
    const int n = (bid >> 1) & 7;
    const int ph = bid & 1;
    const int P = q + 1;
    const int p_base = ph << 7;
    if (P - p_base <= 0) return;
    const int p_count = min(P - p_base, 128);
    const int tid = threadIdx.x;

    float* U = sm + OFF_U;
    uint32_t* BPb = reinterpret_cast<uint32_t*>(sm + OFF_BP);
    float* Cg = sm + OFF_C;
    float* red = sm + OFF_RED;
    float* spart  = red + 8;
    float* stotc  = red + 8 + 256;
    float* v1part = red + 8 + 256 + 64;
    float* v1sum  = red + 8 + 256 + 64 + 256;

    const int pl = tid & 31;
    const int wid = tid >> 5;
    const int gid = pl >> 2;
    const int tidg = pl & 3;
    const int p0w = wid * 16;
    const int cld = tid & 63;
    const int tq  = tid >> 6;

    {
        uint32_t* k1b = reinterpret_cast<uint32_t*>(U);
        const int rr = tid >> 4;
        const int iv = (tid & 15) * 4;
#pragma unroll
        for (int pass = 0; pass < 8; pass++) {
            int lp = pass * 16 + rr;
            float4 v = make_float4(0.f, 0.f, 0.f, 0.f);
            if (lp < p_count)
                v = *reinterpret_cast<const float4*>(&g_proj[(size_t)(p_base + lp) * NPROJ + n * 64 + iv]);
            k1b[lp * 36 + (iv >> 1) + 0] = bf2(v.x, v.y);
            k1b[lp * 36 + (iv >> 1) + 1] = bf2(v.z, v.w);
        }
    }
    {
        uint32_t* MTb = reinterpret_cast<uint32_t*>(Cg);
        const float* Mg = g_M + (size_t)(n * T_SEQ + q) * 4096;
#pragma unroll
        for (int i = 0; i < 8; i++) {
            int kp = tq * 8 + i;
            float a = Mg[(2 * kp) * 64 + cld];
            float b = Mg[(2 * kp + 1) * 64 + cld];
            MTb[cld * 36 + kp] = bf2(a, b);
        }
    }
    __syncthreads();

    {
        const uint32_t* k1b = reinterpret_cast<const uint32_t*>(U);
        const uint32_t* MTb = reinterpret_cast<const uint32_t*>(Cg);
        float bacc[8][4] = {};
#pragma unroll
        for (int kk = 0; kk < 4; kk++) {
            const int k8 = kk * 8;
            uint32_t afr[4];
            afr[0] = k1b[(p0w + gid) * 36 + k8 + tidg];
            afr[1] = k1b[(p0w + gid + 8) * 36 + k8 + tidg];
            afr[2] = k1b[(p0w + gid) * 36 + k8 + tidg + 4];
            afr[3] = k1b[(p0w + gid + 8) * 36 + k8 + tidg + 4];
#pragma unroll
            for (int nt = 0; nt < 8; nt++) {
                uint32_t bfr[2];
                bfr[0] = MTb[(nt * 8 + gid) * 36 + k8 + tidg];
                bfr[1] = MTb[(nt * 8 + gid) * 36 + k8 + tidg + 4];
                mma16bf(bacc[nt], afr, bfr);
            }
        }
#pragma unroll
        for (int nt = 0; nt < 8; nt++) {
            BPb[(p0w + gid) * 36 + nt * 4 + tidg]     = bf2(bacc[nt][0], bacc[nt][1]);
            BPb[(p0w + gid + 8) * 36 + nt * 4 + tidg] = bf2(bacc[nt][2], bacc[nt][3]);
        }
    }
    __syncthreads();

    float rfr[8][4] = {};
    float lsum = 0.f;
    float stot_loc = 0.f;
    uint32_t* k2b = reinterpret_cast<uint32_t*>(U);
    uint32_t* v2b = reinterpret_cast<uint32_t*>(U) + 2304;
    for (int t0 = 0; t0 < P; t0 += 64) {
        {
            const int rr = tid >> 4;
            const int iv = (tid & 15) * 4;
#pragma unroll
            for (int pass = 0; pass < 4; pass++) {
                int t = pass * 16 + rr;
                int gt = t0 + t;
                float4 a = make_float4(0.f, 0.f, 0.f, 0.f);
                if (gt < P) a = *reinterpret_cast<const float4*>(&g_proj[(size_t)gt * NPROJ + 512 + n * 64 + iv]);
                k2b[t * 36 + (iv >> 1) + 0] = bf2(a.x, a.y);
                k2b[t * 36 + (iv >> 1) + 1] = bf2(a.z, a.w);
            }
        }
        {
#pragma unroll
            for (int it = 0; it < 4; it++) {
                int t4 = tq * 16 + it * 4;
                float v[4];
#pragma unroll
                for (int k = 0; k < 4; k++) {
                    int gt = t0 + t4 + k;
                    v[k] = (gt < P) ? g_proj[(size_t)gt * NPROJ + 2048 + n * 64 + cld] : 0.f;
                    stot_loc += v[k];
                }
                v2b[cld * 36 + (t4 >> 1) + 0] = bf2(v[0], v[1]);
                v2b[cld * 36 + (t4 >> 1) + 1] = bf2(v[2], v[3]);
            }
        }
        __syncthreads();
        float sfr[8][4] = {};
#pragma unroll
        for (int kk = 0; kk < 4; kk++) {
            const int j8 = kk * 8;
            uint32_t afr[4];
            afr[0] = BPb[(p0w + gid) * 36 + j8 + tidg];
            afr[1] = BPb[(p0w + gid + 8) * 36 + j8 + tidg];
            afr[2] = BPb[(p0w + gid) * 36 + j8 + tidg + 4];
            afr[3] = BPb[(p0w + gid + 8) * 36 + j8 + tidg + 4];
#pragma unroll
            for (int nt = 0; nt < 8; nt++) {
                uint32_t bfr[2];
                bfr[0] = k2b[(nt * 8 + gid) * 36 + j8 + tidg];
                bfr[1] = k2b[(nt * 8 + gid) * 36 + j8 + tidg + 4];
                mma16bf(sfr[nt], afr, bfr);
            }
        }
        if (t0 + 64 <= P && p_count == 128) {
#pragma unroll
            for (int nt = 0; nt < 8; nt++)
#pragma unroll
                for (int r = 0; r < 4; r++) {
                    float e = __expf(sfr[nt][r] * 0.015625f);
                    lsum += e;
                    sfr[nt][r] = e - 1.f;
                }
        } else {
#pragma unroll
            for (int nt = 0; nt < 8; nt++)
#pragma unroll
                for (int r = 0; r < 4; r++) {
                    int p_loc = p0w + gid + ((r >> 1) << 3);
                    int t_loc = nt * 8 + 2 * tidg + (r & 1);
                    int gp = p_base + p_loc;
                    int gt = t0 + t_loc;
                    float e = (gp < P && gt < P) ? __expf(sfr[nt][r] * 0.015625f) : 0.f;
                    lsum += e;
                    sfr[nt][r] = e - 1.f;
                }
        }
#pragma unroll
        for (int kk = 0; kk < 4; kk++) {
            uint32_t afr[4];
            afr[0] = bf2(sfr[2 * kk][0], sfr[2 * kk][1]);
            afr[1] = bf2(sfr[2 * kk][2], sfr[2 * kk][3]);
            afr[2] = bf2(sfr[2 * kk + 1][0], sfr[2 * kk + 1][1]);
            afr[3] = bf2(sfr[2 * kk + 1][2], sfr[2 * kk + 1][3]);
            const int t8 = kk * 8;
#pragma unroll
            for (int nt = 0; nt < 8; nt++) {
                uint32_t bfr[2];
                bfr[0] = v2b[(nt * 8 + gid) * 36 + t8 + tidg];
                bfr[1] = v2b[(nt * 8 + gid) * 36 + t8 + tidg + 4];
                mma16bf(rfr[nt], afr, bfr);
            }
        }
        __syncthreads();
    }

    {
        uint16_t* RTh = reinterpret_cast<uint16_t*>(Cg);
#pragma unroll
        for (int nt = 0; nt < 8; nt++)
#pragma unroll
            for (int r = 0; r < 4; r++) {
                int p = p0w + gid + ((r >> 1) << 3);
                int c = nt * 8 + 2 * tidg + (r & 1);
                RTh[c * 136 + p] = bf16lo(rfr[nt][r]);
            }
    }
    {
        uint32_t* v1Tb = reinterpret_cast<uint32_t*>(U);
        float vsum = 0.f;
#pragma unroll
        for (int i = 0; i < 16; i++) {
            int pp = tq * 16 + i;
            int pA = 2 * pp, pB = 2 * pp + 1;
            float va = (pA < p_count)
                ? g_proj[(size_t)(p_base + pA) * NPROJ + 1536 + n * 64 + cld] : 0.f;
            float vb = (pB < p_count)
                ? g_proj[(size_t)(p_base + pB) * NPROJ + 1536 + n * 64 + cld] : 0.f;
            v1Tb[cld * 68 + pp] = bf2(va, vb);
            vsum += va + vb;
        }
        v1part[tq * 64 + cld] = vsum;
    }
    spart[tq * 64 + cld] = stot_loc;
#pragma unroll
    for (int off = 16; off > 0; off >>= 1)
        lsum += __shfl_xor_sync(0xffffffffu, lsum, off);
    if (pl == 0) red[wid] = lsum;
    __syncthreads();
    if (tid < 64) {
        stotc[tid] = spart[tid] + spart[64 + tid] + spart[128 + tid] + spart[192 + tid];
        v1sum[tid] = v1part[tid] + v1part[64 + tid] + v1part[128 + tid] + v1part[192 + tid];
    }
    if (tid == 0) {
        float total = 0.f;
#pragma unroll
        for (int w = 0; w < 8; w++) total += red[w];
        g_l[ph * (NH * T_SEQ) + n * T_SEQ + q] = total;
    }
    __syncthreads();

    {
        const uint32_t* v1Tb = reinterpret_cast<const uint32_t*>(U);
        const uint32_t* RTb = reinterpret_cast<const uint32_t*>(Cg);
        float* Gs = sm + OFF_BP;
        const int a0w = (wid & 3) * 16;
        const int c0w = (wid >> 2) * 32;
        float gacc[4][4] = {};
#pragma unroll
        for (int kk = 0; kk < 8; kk++) {
            const int k8 = kk * 8;
            uint32_t afr[4];
            afr[0] = v1Tb[(a0w + gid) * 68 + k8 + tidg];
            afr[1] = v1Tb[(a0w + gid + 8) * 68 + k8 + tidg];
            afr[2] = v1Tb[(a0w + gid) * 68 + k8 + tidg + 4];
            afr[3] = v1Tb[(a0w + gid + 8) * 68 + k8 + tidg + 4];
#pragma unroll
            for (int nt = 0; nt < 4; nt++) {
                uint32_t bfr[2];
                bfr[0] = RTb[(c0w + nt * 8 + gid) * 68 + k8 + tidg];
                bfr[1] = RTb[(c0w + nt * 8 + gid) * 68 + k8 + tidg + 4];
                mma16bf(gacc[nt], afr, bfr);
            }
        }
        __syncthreads();
#pragma unroll
        for (int nt = 0; nt < 4; nt++)
#pragma unroll
            for (int r = 0; r < 4; r++) {
                int a = a0w + gid + ((r >> 1) << 3);
                int c = c0w + nt * 8 + 2 * tidg + (r & 1);
                Gs[a * 68 + c] = gacc[nt][r] + v1sum[a] * stotc[c];
            }
    }
    __syncthreads();
    {
        const float* Gs = sm + OFF_BP;
        float* Gout = (ph ? g_Gb : g_Ga) + (size_t)(n * T_SEQ + q) * 4096;
#pragma unroll
        for (int kq = 0; kq < 4; kq++) {
            int f = tid + kq * 256;
            int row = f >> 4, c4 = (f & 15) * 4;
            float4 v = *reinterpret_cast<const float4*>(&Gs[row * 68 + c4]);
            *reinterpret_cast<float4*>(&Gout[row * 64 + c4]) = v;
        }
    }
}

// ---------------- K4 (tf32 mma, pipelined): z_raw += (Ga+Gb) @ W_Vq (K-split x8) ----------------
__global__ __launch_bounds__(256) void out_v_kernel() {
    __shared__ float As[64 * 36];   // [q][k] tf32
    __shared__ float Bs[64 * 36];   // [e][k] tf32
    const int n = blockIdx.y;
    const int bq = blockIdx.x * 64;
    const int ks = blockIdx.z;
    const int tid = threadIdx.x;
    const bool two = (bq >= 128);
    const int pl = tid & 31, wid = tid >> 5;
    const int gid = pl >> 2, tidg = pl & 3;
    const int m0 = (wid & 3) * 16;
    const int n0 = (wid >> 2) * 32;
    const int lrow = tid >> 3;
    const int liv = (tid & 7) * 4;
    float acc[4][4] = {};
    float4 rg[2], rw[2];
#pragma unroll
    for (int ps = 0; ps < 2; ps++) {
        int row = lrow + ps * 32;
        size_t idx = (size_t)(n * T_SEQ + bq + row) * 4096 + ks * 512 + liv;
        rg[ps] = *reinterpret_cast<const float4*>(&g_Ga[idx]);
        if (two) {
            float4 w = *reinterpret_cast<const float4*>(&g_Gb[idx]);
            rg[ps].x += w.x; rg[ps].y += w.y; rg[ps].z += w.z; rg[ps].w += w.w;
        }
        rw[ps] = *reinterpret_cast<const float4*>(
            &g_WvqT[(size_t)n * 262144 + (size_t)row * 4096 + ks * 512 + liv]);
    }
    for (int it = 0; it < 16; it++) {
#pragma unroll
        for (int ps = 0; ps < 2; ps++) {
            int row = lrow + ps * 32;
            *reinterpret_cast<float4*>(&As[row * 36 + liv]) =
                make_float4(f2tf_f(rg[ps].x), f2tf_f(rg[ps].y), f2tf_f(rg[ps].z), f2tf_f(rg[ps].w));
            *reinterpret_cast<float4*>(&Bs[row * 36 + liv]) =
                make_float4(f2tf_f(rw[ps].x), f2tf_f(rw[ps].y), f2tf_f(rw[ps].z), f2tf_f(rw[ps].w));
        }
        __syncthreads();
        if (it < 15) {
            int kn = ks * 512 + (it + 1) * 32;
#pragma unroll
            for (int ps = 0; ps < 2; ps++) {
                int row = lrow + ps * 32;
                size_t idx = (size_t)(n * T_SEQ + bq + row) * 4096 + kn + liv;
                rg[ps] = *reinterpret_cast<const float4*>(&g_Ga[idx]);
                if (two) {
                    float4 w = *reinterpret_cast<const float4*>(&g_Gb[idx]);
                    rg[ps].x += w.x; rg[ps].y += w.y; rg[ps].z += w.z; rg[ps].w += w.w;
                }
                rw[ps] = *reinterpret_cast<const float4*>(
                    &g_WvqT[(size_t)n * 262144 + (size_t)row * 4096 + kn + liv]);
            }
        }
#pragma unroll
        for (int kk = 0; kk < 4; kk++) {
            const int k8 = kk * 8;
            uint32_t afr[4];
            afr[0] = __float_as_uint(As[(m0 + gid) * 36 + k8 + tidg]);
            afr[1] = __float_as_uint(As[(m0 + gid + 8) * 36 + k8 + tidg]);
            afr[2] = __float_as_uint(As[(m0 + gid) * 36 + k8 + tidg + 4]);
            afr[3] = __float_as_uint(As[(m0 + gid + 8) * 36 + k8 + tidg + 4]);
#pragma unroll
            for (int nt = 0; nt < 4; nt++) {
                uint32_t bfr[2];
                bfr[0] = __float_as_uint(Bs[(n0 + nt * 8 + gid) * 36 + k8 + tidg]);
                bfr[1] = __float_as_uint(Bs[(n0 + nt * 8 + gid) * 36 + k8 + tidg + 4]);
                mma8(acc[nt], afr, bfr);
            }
        }
        __syncthreads();
    }
#pragma unroll
    for (int nt = 0; nt < 4; nt++)
#pragma unroll
        for (int r = 0; r < 4; r++) {
            int m = bq + m0 + gid + ((r >> 1) << 3);
            int e = n0 + nt * 8 + 2 * tidg + (r & 1);
            atomicAdd(&g_z[(size_t)m * DMODEL + n * 64 + e], acc[nt][r]);
        }
}

// ---------------- K5 (FFMA2, K-split x4): out += (z_raw/l) @ W_out (bias pre-seeded) ----------------
__global__ __launch_bounds__(256) void gemm_out_kernel(
    const float* __restrict__ Wout, float* __restrict__ C) {
    __shared__ float AsT[32 * 68];
    __shared__ float Bs[32 * 68];
    const int tid = threadIdx.x;
    const int bm = blockIdx.y * 64;
    const int bn = blockIdx.x * 64;
    const int ks = blockIdx.z;
    const int r0 = (tid & 15) * 4;
    const int c0 = (tid >> 4) * 4;
    const int arow = tid >> 3, acol = (tid & 7) * 4;
    const int brow = tid >> 4, bcol = (tid & 15) * 4;
    unsigned long long acc2[4][2] = {};
    for (int k0 = ks * 128; k0 < ks * 128 + 128; k0 += 32) {
#pragma unroll
        for (int rr = 0; rr < 2; rr++) {
            int r = bm + arow + rr * 32;
            int gk = k0 + acol;
            int li = (gk >> 6) * T_SEQ + r;
            float invl = 1.f / (g_l[li] + g_l[NH * T_SEQ + li]);
            float4 v = *reinterpret_cast<const float4*>(&g_z[(size_t)r * DMODEL + gk]);
            AsT[(acol + 0) * 68 + arow + rr * 32] = v.x * invl;
            AsT[(acol + 1) * 68 + arow + rr * 32] = v.y * invl;
            AsT[(acol + 2) * 68 + arow + rr * 32] = v.z * invl;
            AsT[(acol + 3) * 68 + arow + rr * 32] = v.w * invl;
        }
#pragma unroll
        for (int rr = 0; rr < 2; rr++) {
            float4 v = *reinterpret_cast<const float4*>(&Wout[(size_t)(k0 + brow + rr * 16) * DMODEL + bn + bcol]);
            *reinterpret_cast<float4*>(&Bs[(brow + rr * 16) * 68 + bcol]) = v;
        }
        __syncthreads();
#pragma unroll
        for (int kk = 0; kk < 32; kk++) {
            float4 a = *reinterpret_cast<const float4*>(&AsT[kk * 68 + r0]);
            ulonglong2 b2 = *reinterpret_cast<const ulonglong2*>(&Bs[kk * 68 + c0]);
            unsigned long long as[4] = {splat2(a.x), splat2(a.y), splat2(a.z), splat2(a.w)};
#pragma unroll
            for (int i = 0; i < 4; i++) {
                acc2[i][0] = fma2(as[i], b2.x, acc2[i][0]);
                acc2[i][1] = fma2(as[i], b2.y, acc2[i][1]);
            }
        }
        __syncthreads();
    }
#pragma unroll
    for (int i = 0; i < 4; i++) {
        float2 p0 = unpack2(acc2[i][0]);
        float2 p1 = unpack2(acc2[i][1]);
        float* cp = &C[(size_t)(bm + r0 + i) * DMODEL + bn + c0];
        atomicAdd(cp + 0, p0.x);
        atomicAdd(cp + 1, p0.y);
        atomicAdd(cp + 2, p1.x);
        atomicAdd(cp + 3, p1.y);
    }
}

// ---------------- launch ----------------
extern "C" void kernel_launch(void* const* d_in, const int* in_sizes, int n_in,
                              void* d_out, int out_size) {
    const float* x       = (const float*)d_in[0];
    const float* Wkkqvv  = (const float*)d_in[1];
    const float* bkkqvv  = (const float*)d_in[2];
    const float* WKq     = (const float*)d_in[3];
    const float* WVq     = (const float*)d_in[4];
    const float* Wout    = (const float*)d_in[5];
    const float* bout    = (const float*)d_in[6];
    float* out = (float*)d_out;

    float* proj_ptr = nullptr;
    cudaGetSymbolAddress((void**)&proj_ptr, g_proj);
    float* wkt_ptr = nullptr;
    cudaGetSymbolAddress((void**)&wkt_ptr, g_WkT);
    float* wvqt_ptr = nullptr;
    cudaGetSymbolAddress((void**)&wvqt_ptr, g_WvqT);

    cudaFuncSetAttribute(attn_kernel, cudaFuncAttributeMaxDynamicSharedMemorySize, ATTN_SMEM_BYTES);

    zero_kernel<<<(NZERO + 255) / 256, 256>>>(out, bout);
    transpose_kernel<<<dim3(NPROJ / 32, DMODEL / 32, 1), 256>>>(Wkkqvv, wkt_ptr, DMODEL, NPROJ);
    transpose_kernel<<<dim3(DHD / 32, 4096 / 32, NH), 256>>>(WVq, wvqt_ptr, 4096, DHD);
    gemm_proj_kernel<<<dim3(NPROJ / 64, T_SEQ / 64), 256>>>(x, bkkqvv, proj_ptr);
    compute_M_kernel<<<dim3(64, NH), 256>>>(WKq);
    attn_kernel<<<NH * T_SEQ * 2, 256, ATTN_SMEM_BYTES>>>();
    out_v_kernel<<<dim3(4, NH, 8), 256>>>();
    gemm_out_kernel<<<dim3(DMODEL / 64, T_SEQ / 64, 4), 256>>>(Wout, out);
}